// round 1
// baseline (speedup 1.0000x reference)
#include <cuda_runtime.h>

// ---------------------------------------------------------------------------
// GINE 2-layer GNN, N=25000, E=400000, 64 -> 256 -> 256 -> 128 -> 128 -> 1
// Scratch (device globals; no runtime allocation):
// ---------------------------------------------------------------------------
#define MAXN 25000
__device__ float g_agg1[MAXN * 64];
__device__ float g_agg2[MAXN * 256];
__device__ float g_bufA[MAXN * 256];
__device__ float g_bufB[MAXN * 256];
__device__ float g_colsum[256];
__device__ float g_colsq[256];
__device__ float g_bnA[256];
__device__ float g_bnB[256];
__device__ int   g_idx64;

// ---------------------------------------------------------------------------
// Detect edge_index dtype (int64 vs int32) + zero BN stat accumulators.
// If data is int64 (values < 2^31), every odd 32-bit word of the first
// 1024 entries is 0. If int32, odd words are random node ids (~never all 0).
// ---------------------------------------------------------------------------
__global__ void detect_zero_kernel(const int* __restrict__ ei) {
    __shared__ int found;
    if (threadIdx.x == 0) found = 0;
    __syncthreads();
    for (int i = threadIdx.x; i < 1024; i += blockDim.x)
        if (ei[2 * i + 1] != 0) found = 1;
    __syncthreads();
    if (threadIdx.x == 0) g_idx64 = found ? 0 : 1;
    if (threadIdx.x < 256) {
        g_colsum[threadIdx.x] = 0.f;
        g_colsq[threadIdx.x]  = 0.f;
    }
}

__global__ void zero_kernel(float4* __restrict__ p, int n4) {
    int i = blockIdx.x * blockDim.x + threadIdx.x;
    if (i < n4) p[i] = make_float4(0.f, 0.f, 0.f, 0.f);
}

// ---------------------------------------------------------------------------
// Edge kernel 1: m = relu(x[src] + edge_attr@We1 + be1); red-add into agg1[dst]
// d_in = 64. 16 threads per edge (one float4 each), 16 edges per block.
// ---------------------------------------------------------------------------
__global__ void __launch_bounds__(256) edge1_kernel(
    const void* __restrict__ eiv, int E,
    const float* __restrict__ ea,
    const float* __restrict__ We, const float* __restrict__ be,
    const float* __restrict__ x, float* __restrict__ agg)
{
    __shared__ __align__(16) float sW[8 * 64];
    __shared__ float sB[64];
    __shared__ float sEA[16 * 8];
    __shared__ int sSrc[16], sDst[16];
    int tid = threadIdx.x;
    for (int i = tid; i < 512; i += 256) sW[i] = We[i];
    if (tid < 64) sB[tid] = be[tid];
    int e0 = blockIdx.x * 16;
    int f = g_idx64;
    if (tid < 16) {
        int e = e0 + tid; int s = -1, d = -1;
        if (e < E) {
            if (f) { const long long* p = (const long long*)eiv; s = (int)p[e]; d = (int)p[E + e]; }
            else   { const int* p = (const int*)eiv;             s = p[e];      d = p[E + e]; }
        }
        sSrc[tid] = s; sDst[tid] = d;
    }
    if (tid < 128) sEA[tid] = (e0 + (tid >> 3) < E) ? ea[(size_t)e0 * 8 + tid] : 0.f;
    __syncthreads();

    int eg  = tid >> 4;
    int t16 = tid & 15;
    int src = sSrc[eg], dst = sDst[eg];
    if (src < 0) return;
    const float* a = &sEA[eg * 8];
    int c0 = t16 * 4;
    float m0 = sB[c0], m1 = sB[c0 + 1], m2 = sB[c0 + 2], m3 = sB[c0 + 3];
#pragma unroll
    for (int k = 0; k < 8; k++) {
        float av = a[k];
        float4 wv = *(const float4*)&sW[k * 64 + c0];
        m0 += av * wv.x; m1 += av * wv.y; m2 += av * wv.z; m3 += av * wv.w;
    }
    float4 xv = *(const float4*)(x + (size_t)src * 64 + c0);
    m0 = fmaxf(m0 + xv.x, 0.f); m1 = fmaxf(m1 + xv.y, 0.f);
    m2 = fmaxf(m2 + xv.z, 0.f); m3 = fmaxf(m3 + xv.w, 0.f);
    float* dp = agg + (size_t)dst * 64 + c0;
    asm volatile("red.global.add.v4.f32 [%0], {%1,%2,%3,%4};"
                 :: "l"(dp), "f"(m0), "f"(m1), "f"(m2), "f"(m3) : "memory");
}

// ---------------------------------------------------------------------------
// Edge kernel 2: h = relu(bnA*t2[src]+bnB); m = relu(h + edge_attr@We2 + be2)
// red-add into agg2[dst]. d = 256. 64 threads/edge, 4 edges/block.
// ---------------------------------------------------------------------------
__global__ void __launch_bounds__(256) edge2_kernel(
    const void* __restrict__ eiv, int E,
    const float* __restrict__ ea,
    const float* __restrict__ We, const float* __restrict__ be,
    const float* __restrict__ t2, float* __restrict__ agg)
{
    __shared__ __align__(16) float sW[8 * 256];
    __shared__ float sB[256], sA_[256], sBB[256];
    __shared__ float sEA[4 * 8];
    __shared__ int sSrc[4], sDst[4];
    int tid = threadIdx.x;
    for (int i = tid; i < 2048; i += 256) sW[i] = We[i];
    sB[tid]  = be[tid];
    sA_[tid] = g_bnA[tid];
    sBB[tid] = g_bnB[tid];
    int e0 = blockIdx.x * 4;
    int f = g_idx64;
    if (tid < 4) {
        int e = e0 + tid; int s = -1, d = -1;
        if (e < E) {
            if (f) { const long long* p = (const long long*)eiv; s = (int)p[e]; d = (int)p[E + e]; }
            else   { const int* p = (const int*)eiv;             s = p[e];      d = p[E + e]; }
        }
        sSrc[tid] = s; sDst[tid] = d;
    }
    if (tid < 32) sEA[tid] = (e0 + (tid >> 3) < E) ? ea[(size_t)e0 * 8 + tid] : 0.f;
    __syncthreads();

    int eg  = tid >> 6;
    int t64 = tid & 63;
    int src = sSrc[eg], dst = sDst[eg];
    if (src < 0) return;
    const float* a = &sEA[eg * 8];
    int c0 = t64 * 4;
    float m0 = sB[c0], m1 = sB[c0 + 1], m2 = sB[c0 + 2], m3 = sB[c0 + 3];
#pragma unroll
    for (int k = 0; k < 8; k++) {
        float av = a[k];
        float4 wv = *(const float4*)&sW[k * 256 + c0];
        m0 += av * wv.x; m1 += av * wv.y; m2 += av * wv.z; m3 += av * wv.w;
    }
    float4 tv = *(const float4*)(t2 + (size_t)src * 256 + c0);
    float h0 = fmaxf(sA_[c0]     * tv.x + sBB[c0],     0.f);
    float h1 = fmaxf(sA_[c0 + 1] * tv.y + sBB[c0 + 1], 0.f);
    float h2 = fmaxf(sA_[c0 + 2] * tv.z + sBB[c0 + 2], 0.f);
    float h3 = fmaxf(sA_[c0 + 3] * tv.w + sBB[c0 + 3], 0.f);
    m0 = fmaxf(m0 + h0, 0.f); m1 = fmaxf(m1 + h1, 0.f);
    m2 = fmaxf(m2 + h2, 0.f); m3 = fmaxf(m3 + h3, 0.f);
    float* dp = agg + (size_t)dst * 256 + c0;
    asm volatile("red.global.add.v4.f32 [%0], {%1,%2,%3,%4};"
                 :: "l"(dp), "f"(m0), "f"(m1), "f"(m2), "f"(m3) : "memory");
}

// ---------------------------------------------------------------------------
// SIMT GEMM: out[N,NCOLS] = PRE(X)[N,K] @ W[K,NCOLS] + bias, with fused
// per-column sum/sumsq accumulation for BatchNorm statistics.
// PRE: 0 raw, 1 (1+eps)*x+X2, 2 relu(bnA*x+bnB), 3 (1+eps)*relu(bnA*x+bnB)+X2
// 256 threads, 8x8 register tile per thread. BM = 2048*8/NCOLS.
// ---------------------------------------------------------------------------
template <int K, int NCOLS, int PRE>
__global__ void __launch_bounds__(256) gemm_kernel(
    const float* __restrict__ X, const float* __restrict__ W,
    const float* __restrict__ bias, float* __restrict__ out,
    const float* __restrict__ X2, const float* __restrict__ eps_ptr, int N)
{
    constexpr int CG = NCOLS / 8;       // column groups (32 or 16)
    constexpr int BM = 2048 / CG;       // 64 (NCOLS=256) or 128 (NCOLS=128)
    constexpr int BK = 32;
    __shared__ __align__(16) float Xs[BK][BM];
    __shared__ __align__(16) float Ws[BK][NCOLS];
    __shared__ float ssum[NCOLS], ssq[NCOLS];

    int tid = threadIdx.x;
    int cg = tid % CG;
    int ng = tid / CG;
    int n0 = blockIdx.x * BM;

    float eps = 0.f;
    if constexpr (PRE == 1 || PRE == 3) eps = 1.0f + *eps_ptr;

    float acc[8][8];
#pragma unroll
    for (int i = 0; i < 8; i++)
#pragma unroll
        for (int j = 0; j < 8; j++) acc[i][j] = 0.f;

    for (int k0 = 0; k0 < K; k0 += BK) {
        // X tile -> Xs[k][node] (transposed for vectorized reads)
#pragma unroll
        for (int it = 0; it < BM * BK / 256; it++) {
            int flat = tid + it * 256;
            int kk = flat & 31;
            int nn = flat >> 5;
            int n = n0 + nn;
            float v = 0.f;
            if (n < N) {
                int gk = k0 + kk;
                float raw = X[(size_t)n * K + gk];
                if constexpr (PRE == 0) v = raw;
                else if constexpr (PRE == 1) v = eps * raw + X2[(size_t)n * K + gk];
                else if constexpr (PRE == 2) v = fmaxf(g_bnA[gk] * raw + g_bnB[gk], 0.f);
                else {
                    float h = fmaxf(g_bnA[gk] * raw + g_bnB[gk], 0.f);
                    v = eps * h + X2[(size_t)n * K + gk];
                }
            }
            Xs[kk][nn] = v;
        }
        // W tile (float4 coalesced)
#pragma unroll
        for (int it = 0; it < BK * NCOLS / 1024; it++) {
            int flat = tid + it * 256;                 // float4 index
            int kk = flat / (NCOLS / 4);
            int cc = flat % (NCOLS / 4);
            ((float4*)&Ws[kk][0])[cc] = ((const float4*)&W[(size_t)(k0 + kk) * NCOLS])[cc];
        }
        __syncthreads();
#pragma unroll 8
        for (int kk = 0; kk < BK; kk++) {
            float4 a0 = *(const float4*)&Xs[kk][ng * 8];
            float4 a1 = *(const float4*)&Xs[kk][ng * 8 + 4];
            float4 b0 = *(const float4*)&Ws[kk][cg * 8];
            float4 b1 = *(const float4*)&Ws[kk][cg * 8 + 4];
            float a[8] = {a0.x, a0.y, a0.z, a0.w, a1.x, a1.y, a1.z, a1.w};
            float b[8] = {b0.x, b0.y, b0.z, b0.w, b1.x, b1.y, b1.z, b1.w};
#pragma unroll
            for (int i = 0; i < 8; i++)
#pragma unroll
                for (int j = 0; j < 8; j++)
                    acc[i][j] += a[i] * b[j];
        }
        __syncthreads();
    }

    // Epilogue: +bias, store, BN stats (regs -> shared atomics -> global)
    float bb[8];
#pragma unroll
    for (int j = 0; j < 8; j++) bb[j] = bias[cg * 8 + j];
    for (int i = tid; i < NCOLS; i += 256) { ssum[i] = 0.f; ssq[i] = 0.f; }
    __syncthreads();

    float s_[8], q_[8];
#pragma unroll
    for (int j = 0; j < 8; j++) { s_[j] = 0.f; q_[j] = 0.f; }
#pragma unroll
    for (int i = 0; i < 8; i++) {
        int row = n0 + ng * 8 + i;
        if (row < N) {
            float v[8];
#pragma unroll
            for (int j = 0; j < 8; j++) {
                v[j] = acc[i][j] + bb[j];
                s_[j] += v[j];
                q_[j] += v[j] * v[j];
            }
            float4* op = (float4*)(out + (size_t)row * NCOLS + cg * 8);
            op[0] = make_float4(v[0], v[1], v[2], v[3]);
            op[1] = make_float4(v[4], v[5], v[6], v[7]);
        }
    }
#pragma unroll
    for (int j = 0; j < 8; j++) {
        atomicAdd(&ssum[cg * 8 + j], s_[j]);
        atomicAdd(&ssq[cg * 8 + j],  q_[j]);
    }
    __syncthreads();
    for (int i = tid; i < NCOLS; i += 256) {
        atomicAdd(&g_colsum[i], ssum[i]);
        atomicAdd(&g_colsq[i],  ssq[i]);
    }
}

// ---------------------------------------------------------------------------
// BN prep: stats -> per-column affine (A,B), then reset stats. 1 block.
// ---------------------------------------------------------------------------
__global__ void bnprep_kernel(const float* __restrict__ g,
                              const float* __restrict__ bt, int N)
{
    int j = threadIdx.x;
    float invN = 1.0f / (float)N;
    float mu = g_colsum[j] * invN;
    float var = fmaxf(g_colsq[j] * invN - mu * mu, 0.f);
    float A = g[j] * rsqrtf(var + 1e-5f);
    g_bnA[j] = A;
    g_bnB[j] = bt[j] - A * mu;
    g_colsum[j] = 0.f;
    g_colsq[j]  = 0.f;
}

// ---------------------------------------------------------------------------
// Output head: out[n] = sum_j relu(bnA*t[n,j]+bnB) * Wout[j] + bout
// One warp per node (128 features -> 4 per lane).
// ---------------------------------------------------------------------------
__global__ void __launch_bounds__(256) out_kernel(
    const float* __restrict__ T, const float* __restrict__ Wout,
    const float* __restrict__ bout, float* __restrict__ out, int N)
{
    int wid = threadIdx.x >> 5, lane = threadIdx.x & 31;
    int n = blockIdx.x * 8 + wid;
    if (n >= N) return;
    float4 t = ((const float4*)(T + (size_t)n * 128))[lane];
    float4 w = ((const float4*)Wout)[lane];
    int c = lane * 4;
    float s = fmaxf(g_bnA[c]     * t.x + g_bnB[c],     0.f) * w.x
            + fmaxf(g_bnA[c + 1] * t.y + g_bnB[c + 1], 0.f) * w.y
            + fmaxf(g_bnA[c + 2] * t.z + g_bnB[c + 2], 0.f) * w.z
            + fmaxf(g_bnA[c + 3] * t.w + g_bnB[c + 3], 0.f) * w.w;
#pragma unroll
    for (int o = 16; o > 0; o >>= 1)
        s += __shfl_xor_sync(0xffffffffu, s, o);
    if (lane == 0) out[n] = s + bout[0];
}

// ---------------------------------------------------------------------------
extern "C" void kernel_launch(void* const* d_in, const int* in_sizes, int n_in,
                              void* d_out, int out_size)
{
    const float* x    = (const float*)d_in[0];
    const void*  ei   = d_in[1];
    const float* ea   = (const float*)d_in[2];
    const float* eps1 = (const float*)d_in[3];
    const float* We1  = (const float*)d_in[4];
    const float* be1  = (const float*)d_in[5];
    const float* W11  = (const float*)d_in[6];
    const float* b11  = (const float*)d_in[7];
    const float* g11  = (const float*)d_in[8];
    const float* bt11 = (const float*)d_in[9];
    const float* W12  = (const float*)d_in[10];
    const float* b12  = (const float*)d_in[11];
    const float* g1   = (const float*)d_in[12];
    const float* bt1  = (const float*)d_in[13];
    const float* eps2 = (const float*)d_in[14];
    const float* We2  = (const float*)d_in[15];
    const float* be2  = (const float*)d_in[16];
    const float* W21  = (const float*)d_in[17];
    const float* b21  = (const float*)d_in[18];
    const float* g21  = (const float*)d_in[19];
    const float* bt21 = (const float*)d_in[20];
    const float* W22  = (const float*)d_in[21];
    const float* b22  = (const float*)d_in[22];
    const float* g2   = (const float*)d_in[23];
    const float* bt2  = (const float*)d_in[24];
    const float* Wout = (const float*)d_in[25];
    const float* bout = (const float*)d_in[26];

    int N = in_sizes[0] / 64;   // 25000
    int E = in_sizes[2] / 8;    // 400000

    float *agg1, *agg2, *bufA, *bufB;
    cudaGetSymbolAddress((void**)&agg1, g_agg1);
    cudaGetSymbolAddress((void**)&agg2, g_agg2);
    cudaGetSymbolAddress((void**)&bufA, g_bufA);
    cudaGetSymbolAddress((void**)&bufB, g_bufB);

    // --- conv1 ---
    detect_zero_kernel<<<1, 256>>>((const int*)ei);
    {
        int n4 = N * 64 / 4;
        zero_kernel<<<(n4 + 255) / 256, 256>>>((float4*)agg1, n4);
    }
    edge1_kernel<<<(E + 15) / 16, 256>>>(ei, E, ea, We1, be1, x, agg1);
    gemm_kernel<64, 256, 1><<<(N + 63) / 64, 256>>>(x, W11, b11, bufA, agg1, eps1, N);
    bnprep_kernel<<<1, 256>>>(g11, bt11, N);
    gemm_kernel<256, 256, 2><<<(N + 63) / 64, 256>>>(bufA, W12, b12, bufB, nullptr, nullptr, N);
    bnprep_kernel<<<1, 256>>>(g1, bt1, N);   // bnA/bnB for relu(bn(.)) consumed by conv2

    // --- conv2 ---
    {
        int n4 = N * 256 / 4;
        zero_kernel<<<(n4 + 255) / 256, 256>>>((float4*)agg2, n4);
    }
    edge2_kernel<<<(E + 3) / 4, 256>>>(ei, E, ea, We2, be2, bufB, agg2);
    gemm_kernel<256, 128, 3><<<(N + 127) / 128, 256>>>(bufB, W21, b21, bufA, agg2, eps2, N);
    bnprep_kernel<<<1, 128>>>(g21, bt21, N);
    gemm_kernel<128, 128, 2><<<(N + 127) / 128, 256>>>(bufA, W22, b22, bufB, nullptr, nullptr, N);
    bnprep_kernel<<<1, 128>>>(g2, bt2, N);

    // --- head ---
    out_kernel<<<(N + 7) / 8, 256>>>(bufB, Wout, bout, (float*)d_out, N);
}

// round 2
// speedup vs baseline: 1.5112x; 1.5112x over previous
#include <cuda_runtime.h>
#include <stdint.h>

// ---------------------------------------------------------------------------
// GINE 2-layer GNN, N=25000, E=400000, 64 -> 256 -> 256 -> 128 -> 128 -> 1
// R2: CSR-based register aggregation (no float atomics) + 3xTF32 tensor-core
// GEMMs with fused BN-stat epilogue.
// ---------------------------------------------------------------------------
#define MAXN 25000
#define MAXE 400000

__device__ float g_bufA[MAXN * 256];
__device__ float g_bufB[MAXN * 256];
__device__ float g_agg1[MAXN * 64];
__device__ float g_agg2[MAXN * 256];
__device__ float g_colsum[256];
__device__ float g_colsq[256];
__device__ float g_bnA[256];
__device__ float g_bnB[256];
__device__ int   g_idx64;
__device__ int   g_deg[MAXN];
__device__ int   g_rowptr[MAXN + 1];
__device__ int   g_fill[MAXN];
__device__ int2  g_eperm[MAXE];     // (src, edge_id) sorted by dst

// ---------------------------------------------------------------------------
// dtype detect (int64 vs int32 edge_index) + zero BN stat accumulators
// ---------------------------------------------------------------------------
__global__ void detect_zero_kernel(const int* __restrict__ ei) {
    __shared__ int found;
    if (threadIdx.x == 0) found = 0;
    __syncthreads();
    for (int i = threadIdx.x; i < 1024; i += blockDim.x)
        if (ei[2 * i + 1] != 0) found = 1;
    __syncthreads();
    if (threadIdx.x == 0) g_idx64 = found ? 0 : 1;
    if (threadIdx.x < 256) {
        g_colsum[threadIdx.x] = 0.f;
        g_colsq[threadIdx.x]  = 0.f;
    }
}

__device__ __forceinline__ void read_edge(const void* eiv, int E, int e, int f,
                                          int& s, int& d) {
    if (f) {
        const long long* p = (const long long*)eiv;
        s = (int)p[e]; d = (int)p[E + e];
    } else {
        const int* p = (const int*)eiv;
        s = p[e]; d = p[E + e];
    }
}

// ---------------------------------------------------------------------------
// CSR build: zero-deg -> histogram -> scan -> scatter
// ---------------------------------------------------------------------------
__global__ void zero_deg_kernel(int N) {
    int i = blockIdx.x * blockDim.x + threadIdx.x;
    if (i < N) g_deg[i] = 0;
}

__global__ void hist_kernel(const void* __restrict__ eiv, int E) {
    int e = blockIdx.x * blockDim.x + threadIdx.x;
    if (e >= E) return;
    int f = g_idx64, s, d;
    read_edge(eiv, E, e, f, s, d);
    atomicAdd(&g_deg[d], 1);
}

__global__ void scan_kernel(int N) {
    __shared__ int sh[1024];
    int tid = threadIdx.x;
    int carry = 0;
    for (int base = 0; base < N; base += 1024) {
        int i = base + tid;
        int v = (i < N) ? g_deg[i] : 0;
        sh[tid] = v;
        __syncthreads();
#pragma unroll
        for (int off = 1; off < 1024; off <<= 1) {
            int t = (tid >= off) ? sh[tid - off] : 0;
            __syncthreads();
            sh[tid] += t;
            __syncthreads();
        }
        int incl = sh[tid];
        if (i < N) {
            int start = carry + incl - v;
            g_rowptr[i] = start;
            g_fill[i]   = start;
        }
        int total = sh[1023];
        __syncthreads();
        carry += total;
    }
    if (tid == 0) g_rowptr[N] = carry;
}

__global__ void scatter_kernel(const void* __restrict__ eiv, int E) {
    int e = blockIdx.x * blockDim.x + threadIdx.x;
    if (e >= E) return;
    int f = g_idx64, s, d;
    read_edge(eiv, E, e, f, s, d);
    int pos = atomicAdd(&g_fill[d], 1);
    g_eperm[pos] = make_int2(s, e);
}

// ---------------------------------------------------------------------------
// agg1: per-node register aggregation, d=64. One warp per node, float2/lane.
// agg[n] = sum_{e: dst=n} relu(x[src_e] + ea[e]@We + be)
// ---------------------------------------------------------------------------
__global__ void __launch_bounds__(256) agg1_kernel(
    const float* __restrict__ ea,
    const float* __restrict__ We, const float* __restrict__ be,
    const float* __restrict__ x, float* __restrict__ agg, int N)
{
    __shared__ float sW[8 * 64];
    __shared__ float sBe[64];
    int tid = threadIdx.x, lane = tid & 31, wid = tid >> 5;
    for (int i = tid; i < 512; i += 256) sW[i] = We[i];
    if (tid < 64) sBe[tid] = be[tid];
    __syncthreads();

    int node = blockIdx.x * 8 + wid;
    if (node >= N) return;
    int beg = g_rowptr[node], end = g_rowptr[node + 1];
    int c0 = lane * 2;
    float acc0 = 0.f, acc1 = 0.f;
    for (int i = beg; i < end; i++) {
        int2 p = g_eperm[i];
        const float4* eap = (const float4*)(ea + (size_t)p.y * 8);
        float4 e0 = __ldg(eap), e1 = __ldg(eap + 1);
        float a[8] = {e0.x, e0.y, e0.z, e0.w, e1.x, e1.y, e1.z, e1.w};
        float b0 = sBe[c0], b1 = sBe[c0 + 1];
#pragma unroll
        for (int k = 0; k < 8; k++) {
            b0 += a[k] * sW[k * 64 + c0];
            b1 += a[k] * sW[k * 64 + c0 + 1];
        }
        float2 xv = *(const float2*)(x + (size_t)p.x * 64 + c0);
        acc0 += fmaxf(xv.x + b0, 0.f);
        acc1 += fmaxf(xv.y + b1, 0.f);
    }
    *(float2*)(agg + (size_t)node * 64 + c0) = make_float2(acc0, acc1);
}

// ---------------------------------------------------------------------------
// agg2: per-node register aggregation, d=256. 64 threads/node, float4/lane.
// agg[n] = sum relu(h1[src] + ea@We2 + be2)   (h1 pre-materialized)
// ---------------------------------------------------------------------------
__global__ void __launch_bounds__(256) agg2_kernel(
    const float* __restrict__ ea,
    const float* __restrict__ We, const float* __restrict__ be,
    const float* __restrict__ h1, float* __restrict__ agg, int N)
{
    __shared__ __align__(16) float sW[8 * 256];
    __shared__ float sBe[256];
    int tid = threadIdx.x;
    for (int i = tid; i < 2048; i += 256) sW[i] = We[i];
    sBe[tid] = be[tid];
    __syncthreads();

    int node = blockIdx.x * 4 + (tid >> 6);
    if (node >= N) return;
    int t64 = tid & 63;
    int c0 = t64 * 4;
    int beg = g_rowptr[node], end = g_rowptr[node + 1];
    float acc0 = 0.f, acc1 = 0.f, acc2 = 0.f, acc3 = 0.f;
    for (int i = beg; i < end; i++) {
        int2 p = g_eperm[i];
        const float4* eap = (const float4*)(ea + (size_t)p.y * 8);
        float4 e0 = __ldg(eap), e1 = __ldg(eap + 1);
        float a[8] = {e0.x, e0.y, e0.z, e0.w, e1.x, e1.y, e1.z, e1.w};
        float b0 = sBe[c0], b1 = sBe[c0 + 1], b2 = sBe[c0 + 2], b3 = sBe[c0 + 3];
#pragma unroll
        for (int k = 0; k < 8; k++) {
            float4 wv = *(const float4*)&sW[k * 256 + c0];
            b0 += a[k] * wv.x; b1 += a[k] * wv.y;
            b2 += a[k] * wv.z; b3 += a[k] * wv.w;
        }
        float4 hv = *(const float4*)(h1 + (size_t)p.x * 256 + c0);
        acc0 += fmaxf(hv.x + b0, 0.f);
        acc1 += fmaxf(hv.y + b1, 0.f);
        acc2 += fmaxf(hv.z + b2, 0.f);
        acc3 += fmaxf(hv.w + b3, 0.f);
    }
    *(float4*)(agg + (size_t)node * 256 + c0) = make_float4(acc0, acc1, acc2, acc3);
}

// ---------------------------------------------------------------------------
// 3xTF32 tensor-core GEMM with fused PRE transform, bias, BN stats.
// out[N,NCOLS] = PRE(X)[N,K] @ W[K,NCOLS] + bias
// PRE: 0 raw; 1 (1+eps)*X + X2; 2 relu(bnA*X + bnB)
// Block 256 thr (8 warps: 2 along M x 4 along N), BM=64 BN=128 BK=16,
// warp tile 32x32, m16n8k8 tf32 mma, hi/lo split (3 mma per logical mma).
// ---------------------------------------------------------------------------
__device__ __forceinline__ uint32_t f2tf32(float f) {
    uint32_t r;
    asm("cvt.rna.tf32.f32 %0, %1;" : "=r"(r) : "f"(f));
    return r;
}

#define MMA_TF32(d, a, b)                                                     \
    asm volatile(                                                             \
        "mma.sync.aligned.m16n8k8.row.col.f32.tf32.tf32.f32 "                 \
        "{%0,%1,%2,%3},{%4,%5,%6,%7},{%8,%9},{%0,%1,%2,%3};"                  \
        : "+f"(d[0]), "+f"(d[1]), "+f"(d[2]), "+f"(d[3])                      \
        : "r"(a[0]), "r"(a[1]), "r"(a[2]), "r"(a[3]), "r"(b[0]), "r"(b[1]))

template <int K, int NCOLS, int PRE>
__global__ void __launch_bounds__(256) gemm_mma(
    const float* __restrict__ X, const float* __restrict__ W,
    const float* __restrict__ bias, float* __restrict__ out,
    const float* __restrict__ X2, const float* __restrict__ eps_ptr, int N)
{
    constexpr int BM = 64, BN = 128, BK = 16;
    constexpr int KT = K / BK;
    __shared__ float As[2][BK][BM + 4];
    __shared__ float Bs[2][BK][BN + 4];
    __shared__ float ssum[BN], ssq[BN];

    int tid = threadIdx.x, lane = tid & 31, wid = tid >> 5;
    int wm = wid & 1, wn = wid >> 1;
    int n0  = blockIdx.x * BM;
    int nb0 = blockIdx.y * BN;

    for (int i = tid; i < BN; i += 256) { ssum[i] = 0.f; ssq[i] = 0.f; }

    float eps = 0.f;
    if constexpr (PRE == 1) eps = 1.0f + *eps_ptr;

    float acc[2][4][4];
#pragma unroll
    for (int mt = 0; mt < 2; mt++)
#pragma unroll
        for (int nt = 0; nt < 4; nt++)
#pragma unroll
            for (int r = 0; r < 4; r++) acc[mt][nt][r] = 0.f;

    // ---- tile loaders (into registers) ----
    int a_row = tid >> 2;          // 0..63
    int a_kq  = (tid & 3) * 4;     // 0,4,8,12
    auto loadA = [&](int kt, float4& av) {
        int row = n0 + a_row;
        av = make_float4(0.f, 0.f, 0.f, 0.f);
        if (row < N) {
            int gk = kt * BK + a_kq;
            av = *(const float4*)(X + (size_t)row * K + gk);
            if constexpr (PRE == 1) {
                float4 xv = *(const float4*)(X2 + (size_t)row * K + gk);
                av.x = eps * av.x + xv.x; av.y = eps * av.y + xv.y;
                av.z = eps * av.z + xv.z; av.w = eps * av.w + xv.w;
            } else if constexpr (PRE == 2) {
                av.x = fmaxf(g_bnA[gk]     * av.x + g_bnB[gk],     0.f);
                av.y = fmaxf(g_bnA[gk + 1] * av.y + g_bnB[gk + 1], 0.f);
                av.z = fmaxf(g_bnA[gk + 2] * av.z + g_bnB[gk + 2], 0.f);
                av.w = fmaxf(g_bnA[gk + 3] * av.w + g_bnB[gk + 3], 0.f);
            }
        }
    };
    auto storeA = [&](int s, const float4& av) {
        As[s][a_kq][a_row]     = av.x;
        As[s][a_kq + 1][a_row] = av.y;
        As[s][a_kq + 2][a_row] = av.z;
        As[s][a_kq + 3][a_row] = av.w;
    };
    auto loadB = [&](int kt, float4* bv) {
#pragma unroll
        for (int r = 0; r < 2; r++) {
            int i = tid + r * 256;
            int krow = i >> 5, nq = i & 31;
            bv[r] = *(const float4*)(W + (size_t)(kt * BK + krow) * NCOLS + nb0 + nq * 4);
        }
    };
    auto storeB = [&](int s, const float4* bv) {
#pragma unroll
        for (int r = 0; r < 2; r++) {
            int i = tid + r * 256;
            int krow = i >> 5, nq = i & 31;
            *(float4*)&Bs[s][krow][nq * 4] = bv[r];
        }
    };

    {
        float4 av; float4 bv[2];
        loadA(0, av); loadB(0, bv);
        storeA(0, av); storeB(0, bv);
    }
    __syncthreads();

    for (int kt = 0; kt < KT; kt++) {
        float4 nav; float4 nbv[2];
        if (kt + 1 < KT) { loadA(kt + 1, nav); loadB(kt + 1, nbv); }
        int s = kt & 1;
#pragma unroll
        for (int ks = 0; ks < 2; ks++) {
            int kb = ks * 8;
            uint32_t ahi[2][4], alo[2][4];
#pragma unroll
            for (int mt = 0; mt < 2; mt++) {
#pragma unroll
                for (int r = 0; r < 4; r++) {
                    int kk = kb + (lane & 3) + ((r & 2) ? 4 : 0);
                    int mm = wm * 32 + mt * 16 + (lane >> 2) + ((r & 1) ? 8 : 0);
                    float f = As[s][kk][mm];
                    ahi[mt][r] = f2tf32(f);
                    alo[mt][r] = f2tf32(f - __uint_as_float(ahi[mt][r]));
                }
            }
            uint32_t bhi[4][2], blo[4][2];
#pragma unroll
            for (int nt = 0; nt < 4; nt++) {
#pragma unroll
                for (int r = 0; r < 2; r++) {
                    int kk = kb + (lane & 3) + r * 4;
                    int nn = wn * 32 + nt * 8 + (lane >> 2);
                    float f = Bs[s][kk][nn];
                    bhi[nt][r] = f2tf32(f);
                    blo[nt][r] = f2tf32(f - __uint_as_float(bhi[nt][r]));
                }
            }
#pragma unroll
            for (int mt = 0; mt < 2; mt++)
#pragma unroll
                for (int nt = 0; nt < 4; nt++) {
                    MMA_TF32(acc[mt][nt], ahi[mt], bhi[nt]);
                    MMA_TF32(acc[mt][nt], alo[mt], bhi[nt]);
                    MMA_TF32(acc[mt][nt], ahi[mt], blo[nt]);
                }
        }
        __syncthreads();
        if (kt + 1 < KT) { storeA(s ^ 1, nav); storeB(s ^ 1, nbv); }
        __syncthreads();
    }

    // ---- epilogue: bias, store, BN stats ----
#pragma unroll
    for (int nt = 0; nt < 4; nt++) {
        int cb = wn * 32 + nt * 8 + 2 * (lane & 3);
        float b0 = bias[nb0 + cb], b1 = bias[nb0 + cb + 1];
        float s0 = 0.f, s1 = 0.f, q0 = 0.f, q1 = 0.f;
#pragma unroll
        for (int mt = 0; mt < 2; mt++) {
            int row0 = n0 + wm * 32 + mt * 16 + (lane >> 2);
            float v0 = acc[mt][nt][0] + b0, v1 = acc[mt][nt][1] + b1;
            float v2 = acc[mt][nt][2] + b0, v3 = acc[mt][nt][3] + b1;
            if (row0 < N) {
                *(float2*)(out + (size_t)row0 * NCOLS + nb0 + cb) = make_float2(v0, v1);
                s0 += v0; s1 += v1; q0 += v0 * v0; q1 += v1 * v1;
            }
            if (row0 + 8 < N) {
                *(float2*)(out + (size_t)(row0 + 8) * NCOLS + nb0 + cb) = make_float2(v2, v3);
                s0 += v2; s1 += v3; q0 += v2 * v2; q1 += v3 * v3;
            }
        }
#pragma unroll
        for (int off = 4; off < 32; off <<= 1) {
            s0 += __shfl_xor_sync(0xffffffffu, s0, off);
            s1 += __shfl_xor_sync(0xffffffffu, s1, off);
            q0 += __shfl_xor_sync(0xffffffffu, q0, off);
            q1 += __shfl_xor_sync(0xffffffffu, q1, off);
        }
        if (lane < 4) {
            atomicAdd(&ssum[cb], s0); atomicAdd(&ssum[cb + 1], s1);
            atomicAdd(&ssq[cb],  q0); atomicAdd(&ssq[cb + 1],  q1);
        }
    }
    __syncthreads();
    for (int i = tid; i < BN; i += 256) {
        atomicAdd(&g_colsum[nb0 + i], ssum[i]);
        atomicAdd(&g_colsq[nb0 + i],  ssq[i]);
    }
}

// ---------------------------------------------------------------------------
// BN prep: stats -> affine (A,B); reset stats. 1 block.
// ---------------------------------------------------------------------------
__global__ void bnprep_kernel(const float* __restrict__ g,
                              const float* __restrict__ bt, int N)
{
    int j = threadIdx.x;
    float invN = 1.0f / (float)N;
    float mu = g_colsum[j] * invN;
    float var = fmaxf(g_colsq[j] * invN - mu * mu, 0.f);
    float A = g[j] * rsqrtf(var + 1e-5f);
    g_bnA[j] = A;
    g_bnB[j] = bt[j] - A * mu;
    g_colsum[j] = 0.f;
    g_colsq[j]  = 0.f;
}

// ---------------------------------------------------------------------------
// h = relu(bnA*in + bnB), 256-wide rows (materialize h1 for conv2)
// ---------------------------------------------------------------------------
__global__ void bnrelu_kernel(const float4* __restrict__ in,
                              float4* __restrict__ outp, int n4)
{
    int i = blockIdx.x * blockDim.x + threadIdx.x;
    if (i >= n4) return;
    int c0 = (i & 63) * 4;
    float4 v = in[i];
    v.x = fmaxf(g_bnA[c0]     * v.x + g_bnB[c0],     0.f);
    v.y = fmaxf(g_bnA[c0 + 1] * v.y + g_bnB[c0 + 1], 0.f);
    v.z = fmaxf(g_bnA[c0 + 2] * v.z + g_bnB[c0 + 2], 0.f);
    v.w = fmaxf(g_bnA[c0 + 3] * v.w + g_bnB[c0 + 3], 0.f);
    outp[i] = v;
}

// ---------------------------------------------------------------------------
// Output head: out[n] = sum_j relu(bnA*t[n,j]+bnB) * Wout[j] + bout
// ---------------------------------------------------------------------------
__global__ void __launch_bounds__(256) out_kernel(
    const float* __restrict__ T, const float* __restrict__ Wout,
    const float* __restrict__ bout, float* __restrict__ out, int N)
{
    int wid = threadIdx.x >> 5, lane = threadIdx.x & 31;
    int n = blockIdx.x * 8 + wid;
    if (n >= N) return;
    float4 t = ((const float4*)(T + (size_t)n * 128))[lane];
    float4 w = ((const float4*)Wout)[lane];
    int c = lane * 4;
    float s = fmaxf(g_bnA[c]     * t.x + g_bnB[c],     0.f) * w.x
            + fmaxf(g_bnA[c + 1] * t.y + g_bnB[c + 1], 0.f) * w.y
            + fmaxf(g_bnA[c + 2] * t.z + g_bnB[c + 2], 0.f) * w.z
            + fmaxf(g_bnA[c + 3] * t.w + g_bnB[c + 3], 0.f) * w.w;
#pragma unroll
    for (int o = 16; o > 0; o >>= 1)
        s += __shfl_xor_sync(0xffffffffu, s, o);
    if (lane == 0) out[n] = s + bout[0];
}

// ---------------------------------------------------------------------------
extern "C" void kernel_launch(void* const* d_in, const int* in_sizes, int n_in,
                              void* d_out, int out_size)
{
    const float* x    = (const float*)d_in[0];
    const void*  ei   = d_in[1];
    const float* ea   = (const float*)d_in[2];
    const float* eps1 = (const float*)d_in[3];
    const float* We1  = (const float*)d_in[4];
    const float* be1  = (const float*)d_in[5];
    const float* W11  = (const float*)d_in[6];
    const float* b11  = (const float*)d_in[7];
    const float* g11  = (const float*)d_in[8];
    const float* bt11 = (const float*)d_in[9];
    const float* W12  = (const float*)d_in[10];
    const float* b12  = (const float*)d_in[11];
    const float* g1   = (const float*)d_in[12];
    const float* bt1  = (const float*)d_in[13];
    const float* eps2 = (const float*)d_in[14];
    const float* We2  = (const float*)d_in[15];
    const float* be2  = (const float*)d_in[16];
    const float* W21  = (const float*)d_in[17];
    const float* b21  = (const float*)d_in[18];
    const float* g21  = (const float*)d_in[19];
    const float* bt21 = (const float*)d_in[20];
    const float* W22  = (const float*)d_in[21];
    const float* b22  = (const float*)d_in[22];
    const float* g2   = (const float*)d_in[23];
    const float* bt2  = (const float*)d_in[24];
    const float* Wout = (const float*)d_in[25];
    const float* bout = (const float*)d_in[26];

    int N = in_sizes[0] / 64;   // 25000
    int E = in_sizes[2] / 8;    // 400000

    float *agg1, *agg2, *bufA, *bufB;
    cudaGetSymbolAddress((void**)&agg1, g_agg1);
    cudaGetSymbolAddress((void**)&agg2, g_agg2);
    cudaGetSymbolAddress((void**)&bufA, g_bufA);
    cudaGetSymbolAddress((void**)&bufB, g_bufB);

    // --- CSR build (graph static per call) ---
    detect_zero_kernel<<<1, 256>>>((const int*)ei);
    zero_deg_kernel<<<(N + 255) / 256, 256>>>(N);
    hist_kernel<<<(E + 255) / 256, 256>>>(ei, E);
    scan_kernel<<<1, 1024>>>(N);
    scatter_kernel<<<(E + 255) / 256, 256>>>(ei, E);

    int gx = (N + 63) / 64;   // 391

    // --- conv1 ---
    agg1_kernel<<<(N + 7) / 8, 256>>>(ea, We1, be1, x, agg1, N);
    gemm_mma<64, 256, 1><<<dim3(gx, 2), 256>>>(x, W11, b11, bufA, agg1, eps1, N);
    bnprep_kernel<<<1, 256>>>(g11, bt11, N);
    gemm_mma<256, 256, 2><<<dim3(gx, 2), 256>>>(bufA, W12, b12, bufB, nullptr, nullptr, N);
    bnprep_kernel<<<1, 256>>>(g1, bt1, N);
    // materialize h1 = relu(bn(bufB)) -> bufA
    bnrelu_kernel<<<(N * 64 + 255) / 256, 256>>>((const float4*)bufB, (float4*)bufA, N * 64);

    // --- conv2 ---
    agg2_kernel<<<(N + 3) / 4, 256>>>(ea, We2, be2, bufA, agg2, N);
    gemm_mma<256, 128, 1><<<dim3(gx, 1), 256>>>(bufA, W21, b21, bufB, agg2, eps2, N);
    bnprep_kernel<<<1, 128>>>(g21, bt21, N);
    gemm_mma<128, 128, 2><<<dim3(gx, 1), 256>>>(bufB, W22, b22, bufA, nullptr, nullptr, N);
    bnprep_kernel<<<1, 128>>>(g2, bt2, N);

    // --- head ---
    out_kernel<<<(N + 7) / 8, 256>>>(bufA, Wout, bout, (float*)d_out, N);
}

// round 3
// speedup vs baseline: 1.7874x; 1.1828x over previous
#include <cuda_runtime.h>
#include <stdint.h>

// ---------------------------------------------------------------------------
// GINE 2-layer GNN, N=25000, E=400000, 64 -> 256 -> 256 -> 128 -> 128 -> 1
// R3: parallel scan, pre-split tf32 weights (no B-side cvt in GEMM),
// 2-edge-unrolled CSR aggregation.
// ---------------------------------------------------------------------------
#define MAXN 25000
#define MAXE 400000

__device__ float g_bufA[MAXN * 256];
__device__ float g_bufB[MAXN * 256];
__device__ float g_agg1[MAXN * 64];
__device__ float g_agg2[MAXN * 256];
__device__ float g_colsum[256];
__device__ float g_colsq[256];
__device__ float g_bnA[256];
__device__ float g_bnB[256];
__device__ int   g_idx64;
__device__ int   g_deg[MAXN];
__device__ int   g_rowptr[MAXN + 1];
__device__ int   g_fill[MAXN];
__device__ int   g_blocksum[32];
__device__ int2  g_eperm[MAXE];          // (src, edge_id) grouped by dst
__device__ uint32_t g_Whi[131072];       // tf32 hi parts of W11|W12|W21|W22
__device__ uint32_t g_Wlo[131072];       // tf32 lo (residual) parts

__device__ __forceinline__ uint32_t f2tf32(float f) {
    uint32_t r;
    asm("cvt.rna.tf32.f32 %0, %1;" : "=r"(r) : "f"(f));
    return r;
}

// ---------------------------------------------------------------------------
// dtype detect (int64 vs int32 edge_index) + zero BN stat accumulators
// ---------------------------------------------------------------------------
__global__ void detect_zero_kernel(const int* __restrict__ ei) {
    __shared__ int found;
    if (threadIdx.x == 0) found = 0;
    __syncthreads();
    for (int i = threadIdx.x; i < 1024; i += blockDim.x)
        if (ei[2 * i + 1] != 0) found = 1;
    __syncthreads();
    if (threadIdx.x == 0) g_idx64 = found ? 0 : 1;
    if (threadIdx.x < 256) {
        g_colsum[threadIdx.x] = 0.f;
        g_colsq[threadIdx.x]  = 0.f;
    }
}

__device__ __forceinline__ void read_edge(const void* eiv, int E, int e, int f,
                                          int& s, int& d) {
    if (f) {
        const long long* p = (const long long*)eiv;
        s = (int)p[e]; d = (int)p[E + e];
    } else {
        const int* p = (const int*)eiv;
        s = p[e]; d = p[E + e];
    }
}

// ---------------------------------------------------------------------------
// Weight split: W -> (tf32 hi, tf32 residual).  Layout: W11|W12|W21|W22
// ---------------------------------------------------------------------------
__global__ void wsplit_kernel(const float* __restrict__ W11,
                              const float* __restrict__ W12,
                              const float* __restrict__ W21,
                              const float* __restrict__ W22) {
    int i = blockIdx.x * blockDim.x + threadIdx.x;   // < 131072
    float f;
    if (i < 16384)       f = W11[i];
    else if (i < 81920)  f = W12[i - 16384];
    else if (i < 114688) f = W21[i - 81920];
    else                 f = W22[i - 114688];
    uint32_t hi = f2tf32(f);
    g_Whi[i] = hi;
    g_Wlo[i] = f2tf32(f - __uint_as_float(hi));
}

// ---------------------------------------------------------------------------
// CSR build: zero-deg -> histogram -> parallel scan -> scatter
// ---------------------------------------------------------------------------
__global__ void zero_deg_kernel(int N) {
    int i = blockIdx.x * blockDim.x + threadIdx.x;
    if (i < N) g_deg[i] = 0;
}

__global__ void hist_kernel(const void* __restrict__ eiv, int E) {
    int e = blockIdx.x * blockDim.x + threadIdx.x;
    if (e >= E) return;
    int f = g_idx64, s, d;
    read_edge(eiv, E, e, f, s, d);
    atomicAdd(&g_deg[d], 1);
}

// per-block sums (grid = ceil(N/1024))
__global__ void blocksum_kernel(int N) {
    __shared__ int sh[1024];
    int i = blockIdx.x * 1024 + threadIdx.x;
    sh[threadIdx.x] = (i < N) ? g_deg[i] : 0;
    __syncthreads();
#pragma unroll
    for (int off = 512; off > 0; off >>= 1) {
        if (threadIdx.x < off) sh[threadIdx.x] += sh[threadIdx.x + off];
        __syncthreads();
    }
    if (threadIdx.x == 0) g_blocksum[blockIdx.x] = sh[0];
}

// local scan + block prefix (grid = ceil(N/1024))
__global__ void scan2_kernel(int N) {
    __shared__ int sh[1024];
    __shared__ int off_s;
    int b = blockIdx.x;
    int i = b * 1024 + threadIdx.x;
    int v = (i < N) ? g_deg[i] : 0;
    sh[threadIdx.x] = v;
    if (threadIdx.x == 0) {
        int o = 0;
        for (int j = 0; j < b; j++) o += g_blocksum[j];
        off_s = o;
    }
    __syncthreads();
#pragma unroll
    for (int off = 1; off < 1024; off <<= 1) {
        int t = (threadIdx.x >= off) ? sh[threadIdx.x - off] : 0;
        __syncthreads();
        sh[threadIdx.x] += t;
        __syncthreads();
    }
    int start = off_s + sh[threadIdx.x] - v;
    if (i < N) {
        g_rowptr[i] = start;
        g_fill[i]   = start;
    }
    if (i == N - 1) g_rowptr[N] = start + v;
}

__global__ void scatter_kernel(const void* __restrict__ eiv, int E) {
    int e = blockIdx.x * blockDim.x + threadIdx.x;
    if (e >= E) return;
    int f = g_idx64, s, d;
    read_edge(eiv, E, e, f, s, d);
    int pos = atomicAdd(&g_fill[d], 1);
    g_eperm[pos] = make_int2(s, e);
}

// ---------------------------------------------------------------------------
// agg1: per-node register aggregation, d=64. One warp per node, float2/lane.
// agg[n] = sum_{e: dst=n} relu(x[src_e] + ea[e]@We + be).  2-edge unroll.
// ---------------------------------------------------------------------------
__global__ void __launch_bounds__(256) agg1_kernel(
    const float* __restrict__ ea,
    const float* __restrict__ We, const float* __restrict__ be,
    const float* __restrict__ x, float* __restrict__ agg, int N)
{
    __shared__ float sW[8 * 64];
    __shared__ float sBe[64];
    int tid = threadIdx.x, lane = tid & 31, wid = tid >> 5;
    for (int i = tid; i < 512; i += 256) sW[i] = We[i];
    if (tid < 64) sBe[tid] = be[tid];
    __syncthreads();

    int node = blockIdx.x * 8 + wid;
    if (node >= N) return;
    int beg = g_rowptr[node], end = g_rowptr[node + 1];
    int c0 = lane * 2;
    float bse0 = sBe[c0], bse1 = sBe[c0 + 1];
    float acc0 = 0.f, acc1 = 0.f;

    int i = beg;
    for (; i + 1 < end; i += 2) {
        int2 pa = g_eperm[i], pb = g_eperm[i + 1];
        const float4* eap = (const float4*)(ea + (size_t)pa.y * 8);
        const float4* ebp = (const float4*)(ea + (size_t)pb.y * 8);
        float4 a0 = __ldg(eap), a1 = __ldg(eap + 1);
        float4 b0 = __ldg(ebp), b1 = __ldg(ebp + 1);
        float2 xa = *(const float2*)(x + (size_t)pa.x * 64 + c0);
        float2 xb = *(const float2*)(x + (size_t)pb.x * 64 + c0);
        float aa[8] = {a0.x, a0.y, a0.z, a0.w, a1.x, a1.y, a1.z, a1.w};
        float bb[8] = {b0.x, b0.y, b0.z, b0.w, b1.x, b1.y, b1.z, b1.w};
        float ma0 = bse0, ma1 = bse1, mb0 = bse0, mb1 = bse1;
#pragma unroll
        for (int k = 0; k < 8; k++) {
            float w0 = sW[k * 64 + c0], w1 = sW[k * 64 + c0 + 1];
            ma0 += aa[k] * w0; ma1 += aa[k] * w1;
            mb0 += bb[k] * w0; mb1 += bb[k] * w1;
        }
        acc0 += fmaxf(xa.x + ma0, 0.f) + fmaxf(xb.x + mb0, 0.f);
        acc1 += fmaxf(xa.y + ma1, 0.f) + fmaxf(xb.y + mb1, 0.f);
    }
    if (i < end) {
        int2 pa = g_eperm[i];
        const float4* eap = (const float4*)(ea + (size_t)pa.y * 8);
        float4 a0 = __ldg(eap), a1 = __ldg(eap + 1);
        float2 xa = *(const float2*)(x + (size_t)pa.x * 64 + c0);
        float aa[8] = {a0.x, a0.y, a0.z, a0.w, a1.x, a1.y, a1.z, a1.w};
        float ma0 = bse0, ma1 = bse1;
#pragma unroll
        for (int k = 0; k < 8; k++) {
            ma0 += aa[k] * sW[k * 64 + c0];
            ma1 += aa[k] * sW[k * 64 + c0 + 1];
        }
        acc0 += fmaxf(xa.x + ma0, 0.f);
        acc1 += fmaxf(xa.y + ma1, 0.f);
    }
    *(float2*)(agg + (size_t)node * 64 + c0) = make_float2(acc0, acc1);
}

// ---------------------------------------------------------------------------
// agg2: per-node register aggregation, d=256. 64 threads/node, float4/lane.
// agg[n] = sum relu(h1[src] + ea@We2 + be2).  2-edge unroll.
// ---------------------------------------------------------------------------
__global__ void __launch_bounds__(256) agg2_kernel(
    const float* __restrict__ ea,
    const float* __restrict__ We, const float* __restrict__ be,
    const float* __restrict__ h1, float* __restrict__ agg, int N)
{
    __shared__ __align__(16) float sW[8 * 256];
    __shared__ float sBe[256];
    int tid = threadIdx.x;
    for (int i = tid; i < 2048; i += 256) sW[i] = We[i];
    sBe[tid] = be[tid];
    __syncthreads();

    int node = blockIdx.x * 4 + (tid >> 6);
    if (node >= N) return;
    int t64 = tid & 63;
    int c0 = t64 * 4;
    int beg = g_rowptr[node], end = g_rowptr[node + 1];
    float bs0 = sBe[c0], bs1 = sBe[c0 + 1], bs2 = sBe[c0 + 2], bs3 = sBe[c0 + 3];
    float acc0 = 0.f, acc1 = 0.f, acc2 = 0.f, acc3 = 0.f;

    int i = beg;
    for (; i + 1 < end; i += 2) {
        int2 pa = g_eperm[i], pb = g_eperm[i + 1];
        const float4* eap = (const float4*)(ea + (size_t)pa.y * 8);
        const float4* ebp = (const float4*)(ea + (size_t)pb.y * 8);
        float4 a0 = __ldg(eap), a1 = __ldg(eap + 1);
        float4 b0 = __ldg(ebp), b1 = __ldg(ebp + 1);
        float4 ha = *(const float4*)(h1 + (size_t)pa.x * 256 + c0);
        float4 hb = *(const float4*)(h1 + (size_t)pb.x * 256 + c0);
        float aa[8] = {a0.x, a0.y, a0.z, a0.w, a1.x, a1.y, a1.z, a1.w};
        float ab[8] = {b0.x, b0.y, b0.z, b0.w, b1.x, b1.y, b1.z, b1.w};
        float ma0 = bs0, ma1 = bs1, ma2 = bs2, ma3 = bs3;
        float mb0 = bs0, mb1 = bs1, mb2 = bs2, mb3 = bs3;
#pragma unroll
        for (int k = 0; k < 8; k++) {
            float4 wv = *(const float4*)&sW[k * 256 + c0];
            ma0 += aa[k] * wv.x; ma1 += aa[k] * wv.y;
            ma2 += aa[k] * wv.z; ma3 += aa[k] * wv.w;
            mb0 += ab[k] * wv.x; mb1 += ab[k] * wv.y;
            mb2 += ab[k] * wv.z; mb3 += ab[k] * wv.w;
        }
        acc0 += fmaxf(ha.x + ma0, 0.f) + fmaxf(hb.x + mb0, 0.f);
        acc1 += fmaxf(ha.y + ma1, 0.f) + fmaxf(hb.y + mb1, 0.f);
        acc2 += fmaxf(ha.z + ma2, 0.f) + fmaxf(hb.z + mb2, 0.f);
        acc3 += fmaxf(ha.w + ma3, 0.f) + fmaxf(hb.w + mb3, 0.f);
    }
    if (i < end) {
        int2 pa = g_eperm[i];
        const float4* eap = (const float4*)(ea + (size_t)pa.y * 8);
        float4 a0 = __ldg(eap), a1 = __ldg(eap + 1);
        float4 ha = *(const float4*)(h1 + (size_t)pa.x * 256 + c0);
        float aa[8] = {a0.x, a0.y, a0.z, a0.w, a1.x, a1.y, a1.z, a1.w};
        float ma0 = bs0, ma1 = bs1, ma2 = bs2, ma3 = bs3;
#pragma unroll
        for (int k = 0; k < 8; k++) {
            float4 wv = *(const float4*)&sW[k * 256 + c0];
            ma0 += aa[k] * wv.x; ma1 += aa[k] * wv.y;
            ma2 += aa[k] * wv.z; ma3 += aa[k] * wv.w;
        }
        acc0 += fmaxf(ha.x + ma0, 0.f);
        acc1 += fmaxf(ha.y + ma1, 0.f);
        acc2 += fmaxf(ha.z + ma2, 0.f);
        acc3 += fmaxf(ha.w + ma3, 0.f);
    }
    *(float4*)(agg + (size_t)node * 256 + c0) = make_float4(acc0, acc1, acc2, acc3);
}

// ---------------------------------------------------------------------------
// 3xTF32 tensor-core GEMM, B pre-split (Whi/Wlo), fused PRE/bias/BN-stats.
// out[N,NCOLS] = PRE(X)[N,K] @ W[K,NCOLS] + bias
// PRE: 1 (1+eps)*X + X2; 2 relu(bnA*X + bnB)
// ---------------------------------------------------------------------------
#define MMA_TF32(d, a, b)                                                     \
    asm volatile(                                                             \
        "mma.sync.aligned.m16n8k8.row.col.f32.tf32.tf32.f32 "                 \
        "{%0,%1,%2,%3},{%4,%5,%6,%7},{%8,%9},{%0,%1,%2,%3};"                  \
        : "+f"(d[0]), "+f"(d[1]), "+f"(d[2]), "+f"(d[3])                      \
        : "r"(a[0]), "r"(a[1]), "r"(a[2]), "r"(a[3]), "r"(b[0]), "r"(b[1]))

template <int K, int NCOLS, int PRE>
__global__ void __launch_bounds__(256) gemm_mma(
    const float* __restrict__ X,
    const uint32_t* __restrict__ Whi, const uint32_t* __restrict__ Wlo,
    const float* __restrict__ bias, float* __restrict__ out,
    const float* __restrict__ X2, const float* __restrict__ eps_ptr, int N)
{
    constexpr int BM = 64, BN = 128, BK = 16;
    constexpr int KT = K / BK;
    __shared__ float    As[2][BK][BM + 4];
    __shared__ uint32_t Bh[2][BK][BN + 4];
    __shared__ uint32_t Bl[2][BK][BN + 4];
    __shared__ float ssum[BN], ssq[BN];

    int tid = threadIdx.x, lane = tid & 31, wid = tid >> 5;
    int wm = wid & 1, wn = wid >> 1;
    int n0  = blockIdx.x * BM;
    int nb0 = blockIdx.y * BN;

    for (int i = tid; i < BN; i += 256) { ssum[i] = 0.f; ssq[i] = 0.f; }

    float eps = 0.f;
    if constexpr (PRE == 1) eps = 1.0f + *eps_ptr;

    float acc[2][4][4];
#pragma unroll
    for (int mt = 0; mt < 2; mt++)
#pragma unroll
        for (int nt = 0; nt < 4; nt++)
#pragma unroll
            for (int r = 0; r < 4; r++) acc[mt][nt][r] = 0.f;

    int a_row = tid >> 2;
    int a_kq  = (tid & 3) * 4;
    auto loadA = [&](int kt, float4& av) {
        int row = n0 + a_row;
        av = make_float4(0.f, 0.f, 0.f, 0.f);
        if (row < N) {
            int gk = kt * BK + a_kq;
            av = *(const float4*)(X + (size_t)row * K + gk);
            if constexpr (PRE == 1) {
                float4 xv = *(const float4*)(X2 + (size_t)row * K + gk);
                av.x = eps * av.x + xv.x; av.y = eps * av.y + xv.y;
                av.z = eps * av.z + xv.z; av.w = eps * av.w + xv.w;
            } else if constexpr (PRE == 2) {
                av.x = fmaxf(g_bnA[gk]     * av.x + g_bnB[gk],     0.f);
                av.y = fmaxf(g_bnA[gk + 1] * av.y + g_bnB[gk + 1], 0.f);
                av.z = fmaxf(g_bnA[gk + 2] * av.z + g_bnB[gk + 2], 0.f);
                av.w = fmaxf(g_bnA[gk + 3] * av.w + g_bnB[gk + 3], 0.f);
            }
        }
    };
    auto storeA = [&](int s, const float4& av) {
        As[s][a_kq][a_row]     = av.x;
        As[s][a_kq + 1][a_row] = av.y;
        As[s][a_kq + 2][a_row] = av.z;
        As[s][a_kq + 3][a_row] = av.w;
    };
    auto loadB = [&](int kt, uint4* bh, uint4* bl) {
#pragma unroll
        for (int r = 0; r < 2; r++) {
            int i = tid + r * 256;
            int krow = i >> 5, nq = i & 31;
            size_t off = (size_t)(kt * BK + krow) * NCOLS + nb0 + nq * 4;
            bh[r] = *(const uint4*)(Whi + off);
            bl[r] = *(const uint4*)(Wlo + off);
        }
    };
    auto storeB = [&](int s, const uint4* bh, const uint4* bl) {
#pragma unroll
        for (int r = 0; r < 2; r++) {
            int i = tid + r * 256;
            int krow = i >> 5, nq = i & 31;
            *(uint4*)&Bh[s][krow][nq * 4] = bh[r];
            *(uint4*)&Bl[s][krow][nq * 4] = bl[r];
        }
    };

    {
        float4 av; uint4 bh[2], bl[2];
        loadA(0, av); loadB(0, bh, bl);
        storeA(0, av); storeB(0, bh, bl);
    }
    __syncthreads();

    for (int kt = 0; kt < KT; kt++) {
        float4 nav; uint4 nbh[2], nbl[2];
        if (kt + 1 < KT) { loadA(kt + 1, nav); loadB(kt + 1, nbh, nbl); }
        int s = kt & 1;
#pragma unroll
        for (int ks = 0; ks < 2; ks++) {
            int kb = ks * 8;
            uint32_t ahi[2][4], alo[2][4];
#pragma unroll
            for (int mt = 0; mt < 2; mt++) {
#pragma unroll
                for (int r = 0; r < 4; r++) {
                    int kk = kb + (lane & 3) + ((r & 2) ? 4 : 0);
                    int mm = wm * 32 + mt * 16 + (lane >> 2) + ((r & 1) ? 8 : 0);
                    float f = As[s][kk][mm];
                    ahi[mt][r] = f2tf32(f);
                    alo[mt][r] = f2tf32(f - __uint_as_float(ahi[mt][r]));
                }
            }
            uint32_t bhi[4][2], blo[4][2];
#pragma unroll
            for (int nt = 0; nt < 4; nt++) {
#pragma unroll
                for (int r = 0; r < 2; r++) {
                    int kk = kb + (lane & 3) + r * 4;
                    int nn = wn * 32 + nt * 8 + (lane >> 2);
                    bhi[nt][r] = Bh[s][kk][nn];
                    blo[nt][r] = Bl[s][kk][nn];
                }
            }
#pragma unroll
            for (int mt = 0; mt < 2; mt++)
#pragma unroll
                for (int nt = 0; nt < 4; nt++) {
                    MMA_TF32(acc[mt][nt], ahi[mt], bhi[nt]);
                    MMA_TF32(acc[mt][nt], alo[mt], bhi[nt]);
                    MMA_TF32(acc[mt][nt], ahi[mt], blo[nt]);
                }
        }
        if (kt + 1 < KT) {
            storeA(s ^ 1, nav); storeB(s ^ 1, nbh, nbl);
            __syncthreads();
        }
    }

    // epilogue: bias, store, BN stats
#pragma unroll
    for (int nt = 0; nt < 4; nt++) {
        int cb = wn * 32 + nt * 8 + 2 * (lane & 3);
        float b0 = bias[nb0 + cb], b1 = bias[nb0 + cb + 1];
        float s0 = 0.f, s1 = 0.f, q0 = 0.f, q1 = 0.f;
#pragma unroll
        for (int mt = 0; mt < 2; mt++) {
            int row0 = n0 + wm * 32 + mt * 16 + (lane >> 2);
            float v0 = acc[mt][nt][0] + b0, v1 = acc[mt][nt][1] + b1;
            float v2 = acc[mt][nt][2] + b0, v3 = acc[mt][nt][3] + b1;
            if (row0 < N) {
                *(float2*)(out + (size_t)row0 * NCOLS + nb0 + cb) = make_float2(v0, v1);
                s0 += v0; s1 += v1; q0 += v0 * v0; q1 += v1 * v1;
            }
            if (row0 + 8 < N) {
                *(float2*)(out + (size_t)(row0 + 8) * NCOLS + nb0 + cb) = make_float2(v2, v3);
                s0 += v2; s1 += v3; q0 += v2 * v2; q1 += v3 * v3;
            }
        }
#pragma unroll
        for (int off = 4; off < 32; off <<= 1) {
            s0 += __shfl_xor_sync(0xffffffffu, s0, off);
            s1 += __shfl_xor_sync(0xffffffffu, s1, off);
            q0 += __shfl_xor_sync(0xffffffffu, q0, off);
            q1 += __shfl_xor_sync(0xffffffffu, q1, off);
        }
        if (lane < 4) {
            atomicAdd(&ssum[cb], s0); atomicAdd(&ssum[cb + 1], s1);
            atomicAdd(&ssq[cb],  q0); atomicAdd(&ssq[cb + 1],  q1);
        }
    }
    __syncthreads();
    for (int i = tid; i < BN; i += 256) {
        atomicAdd(&g_colsum[nb0 + i], ssum[i]);
        atomicAdd(&g_colsq[nb0 + i],  ssq[i]);
    }
}

// ---------------------------------------------------------------------------
__global__ void bnprep_kernel(const float* __restrict__ g,
                              const float* __restrict__ bt, int N)
{
    int j = threadIdx.x;
    float invN = 1.0f / (float)N;
    float mu = g_colsum[j] * invN;
    float var = fmaxf(g_colsq[j] * invN - mu * mu, 0.f);
    float A = g[j] * rsqrtf(var + 1e-5f);
    g_bnA[j] = A;
    g_bnB[j] = bt[j] - A * mu;
    g_colsum[j] = 0.f;
    g_colsq[j]  = 0.f;
}

__global__ void bnrelu_kernel(const float4* __restrict__ in,
                              float4* __restrict__ outp, int n4)
{
    int i = blockIdx.x * blockDim.x + threadIdx.x;
    if (i >= n4) return;
    int c0 = (i & 63) * 4;
    float4 v = in[i];
    v.x = fmaxf(g_bnA[c0]     * v.x + g_bnB[c0],     0.f);
    v.y = fmaxf(g_bnA[c0 + 1] * v.y + g_bnB[c0 + 1], 0.f);
    v.z = fmaxf(g_bnA[c0 + 2] * v.z + g_bnB[c0 + 2], 0.f);
    v.w = fmaxf(g_bnA[c0 + 3] * v.w + g_bnB[c0 + 3], 0.f);
    outp[i] = v;
}

__global__ void __launch_bounds__(256) out_kernel(
    const float* __restrict__ T, const float* __restrict__ Wout,
    const float* __restrict__ bout, float* __restrict__ out, int N)
{
    int wid = threadIdx.x >> 5, lane = threadIdx.x & 31;
    int n = blockIdx.x * 8 + wid;
    if (n >= N) return;
    float4 t = ((const float4*)(T + (size_t)n * 128))[lane];
    float4 w = ((const float4*)Wout)[lane];
    int c = lane * 4;
    float s = fmaxf(g_bnA[c]     * t.x + g_bnB[c],     0.f) * w.x
            + fmaxf(g_bnA[c + 1] * t.y + g_bnB[c + 1], 0.f) * w.y
            + fmaxf(g_bnA[c + 2] * t.z + g_bnB[c + 2], 0.f) * w.z
            + fmaxf(g_bnA[c + 3] * t.w + g_bnB[c + 3], 0.f) * w.w;
#pragma unroll
    for (int o = 16; o > 0; o >>= 1)
        s += __shfl_xor_sync(0xffffffffu, s, o);
    if (lane == 0) out[n] = s + bout[0];
}

// ---------------------------------------------------------------------------
extern "C" void kernel_launch(void* const* d_in, const int* in_sizes, int n_in,
                              void* d_out, int out_size)
{
    const float* x    = (const float*)d_in[0];
    const void*  ei   = d_in[1];
    const float* ea   = (const float*)d_in[2];
    const float* eps1 = (const float*)d_in[3];
    const float* We1  = (const float*)d_in[4];
    const float* be1  = (const float*)d_in[5];
    const float* W11  = (const float*)d_in[6];
    const float* b11  = (const float*)d_in[7];
    const float* g11  = (const float*)d_in[8];
    const float* bt11 = (const float*)d_in[9];
    const float* W12  = (const float*)d_in[10];
    const float* b12  = (const float*)d_in[11];
    const float* g1   = (const float*)d_in[12];
    const float* bt1  = (const float*)d_in[13];
    const float* eps2 = (const float*)d_in[14];
    const float* We2  = (const float*)d_in[15];
    const float* be2  = (const float*)d_in[16];
    const float* W21  = (const float*)d_in[17];
    const float* b21  = (const float*)d_in[18];
    const float* g21  = (const float*)d_in[19];
    const float* bt21 = (const float*)d_in[20];
    const float* W22  = (const float*)d_in[21];
    const float* b22  = (const float*)d_in[22];
    const float* g2   = (const float*)d_in[23];
    const float* bt2  = (const float*)d_in[24];
    const float* Wout = (const float*)d_in[25];
    const float* bout = (const float*)d_in[26];

    int N = in_sizes[0] / 64;   // 25000
    int E = in_sizes[2] / 8;    // 400000

    float *agg1, *agg2, *bufA, *bufB;
    uint32_t *whi, *wlo;
    cudaGetSymbolAddress((void**)&agg1, g_agg1);
    cudaGetSymbolAddress((void**)&agg2, g_agg2);
    cudaGetSymbolAddress((void**)&bufA, g_bufA);
    cudaGetSymbolAddress((void**)&bufB, g_bufB);
    cudaGetSymbolAddress((void**)&whi, g_Whi);
    cudaGetSymbolAddress((void**)&wlo, g_Wlo);

    int NB = (N + 1023) / 1024;

    // --- setup: dtype detect, weight split, CSR build ---
    detect_zero_kernel<<<1, 256>>>((const int*)ei);
    wsplit_kernel<<<512, 256>>>(W11, W12, W21, W22);
    zero_deg_kernel<<<(N + 255) / 256, 256>>>(N);
    hist_kernel<<<(E + 255) / 256, 256>>>(ei, E);
    blocksum_kernel<<<NB, 1024>>>(N);
    scan2_kernel<<<NB, 1024>>>(N);
    scatter_kernel<<<(E + 255) / 256, 256>>>(ei, E);

    int gx = (N + 63) / 64;   // 391

    // --- conv1 ---
    agg1_kernel<<<(N + 7) / 8, 256>>>(ea, We1, be1, x, agg1, N);
    gemm_mma<64, 256, 1><<<dim3(gx, 2), 256>>>(x, whi, wlo, b11, bufA, agg1, eps1, N);
    bnprep_kernel<<<1, 256>>>(g11, bt11, N);
    gemm_mma<256, 256, 2><<<dim3(gx, 2), 256>>>(bufA, whi + 16384, wlo + 16384,
                                                b12, bufB, nullptr, nullptr, N);
    bnprep_kernel<<<1, 256>>>(g1, bt1, N);
    bnrelu_kernel<<<(N * 64 + 255) / 256, 256>>>((const float4*)bufB, (float4*)bufA, N * 64);

    // --- conv2 ---
    agg2_kernel<<<(N + 3) / 4, 256>>>(ea, We2, be2, bufA, agg2, N);
    gemm_mma<256, 128, 1><<<dim3(gx, 1), 256>>>(bufA, whi + 81920, wlo + 81920,
                                                b21, bufB, agg2, eps2, N);
    bnprep_kernel<<<1, 128>>>(g21, bt21, N);
    gemm_mma<128, 128, 2><<<dim3(gx, 1), 256>>>(bufB, whi + 114688, wlo + 114688,
                                                b22, bufA, nullptr, nullptr, N);
    bnprep_kernel<<<1, 128>>>(g2, bt2, N);

    // --- head ---
    out_kernel<<<(N + 7) / 8, 256>>>(bufA, Wout, bout, (float*)d_out, N);
}

// round 4
// speedup vs baseline: 1.8267x; 1.0220x over previous
#include <cuda_runtime.h>
#include <stdint.h>

// ---------------------------------------------------------------------------
// GINE 2-layer GNN, N=25000, E=400000, 64 -> 256 -> 256 -> 128 -> 128 -> 1
// R4: register-resident edge weights in aggregation (kills smem-crossbar
// bottleneck), bnprep launches removed (inline BN affine from per-layer
// stats), warp-shuffle scans, vectorized CSR build.
// ---------------------------------------------------------------------------
#define MAXN 25000
#define MAXE 400000

__device__ float g_bufA[MAXN * 256];
__device__ float g_bufB[MAXN * 256];
__device__ float g_agg1[MAXN * 64];
__device__ float g_agg2[MAXN * 256];
__device__ float g_colsum[4][256];
__device__ float g_colsq[4][256];
__device__ int   g_idx64;
__device__ int   g_deg[MAXN];
__device__ int   g_rowptr[MAXN + 1];
__device__ int   g_fill[MAXN];
__device__ int   g_blocksum[32];
__device__ int2  g_eperm[MAXE];          // (src, edge_id) grouped by dst
__device__ uint32_t g_Whi[131072];       // tf32 hi parts of W11|W12|W21|W22
__device__ uint32_t g_Wlo[131072];       // tf32 lo (residual) parts

__device__ __forceinline__ uint32_t f2tf32(float f) {
    uint32_t r;
    asm("cvt.rna.tf32.f32 %0, %1;" : "=r"(r) : "f"(f));
    return r;
}

// ---------------------------------------------------------------------------
// setup: zero degrees + zero BN stats + detect edge_index dtype (block 0)
// ---------------------------------------------------------------------------
__global__ void setup_kernel(const int* __restrict__ ei, int N) {
    int i = blockIdx.x * blockDim.x + threadIdx.x;
    if (i < N) g_deg[i] = 0;
    if (i < 1024) {
        ((float*)g_colsum)[i] = 0.f;
        ((float*)g_colsq)[i]  = 0.f;
    }
    if (blockIdx.x == 0) {
        __shared__ int found;
        if (threadIdx.x == 0) found = 0;
        __syncthreads();
        for (int j = threadIdx.x; j < 1024; j += blockDim.x)
            if (ei[2 * j + 1] != 0) found = 1;
        __syncthreads();
        if (threadIdx.x == 0) g_idx64 = found ? 0 : 1;
    }
}

// ---------------------------------------------------------------------------
// CSR build: histogram (4 edges/thread) -> warp-shuffle scan -> scatter
// ---------------------------------------------------------------------------
__global__ void hist_kernel(const void* __restrict__ eiv, int E) {
    int base = (blockIdx.x * blockDim.x + threadIdx.x) * 4;
    if (base >= E) return;
    int f = g_idx64;
    int cnt = min(4, E - base);
    int d[4];
    bool al = ((E & 3) == 0);
    if (f) {
        const long long* p = (const long long*)eiv;
        if (cnt == 4 && al) {
            longlong2 d01 = *(const longlong2*)(p + E + base);
            longlong2 d23 = *(const longlong2*)(p + E + base + 2);
            d[0] = (int)d01.x; d[1] = (int)d01.y; d[2] = (int)d23.x; d[3] = (int)d23.y;
        } else {
            for (int j = 0; j < cnt; j++) d[j] = (int)p[E + base + j];
        }
    } else {
        const int* p = (const int*)eiv;
        if (cnt == 4 && al) {
            int4 dv = *(const int4*)(p + E + base);
            d[0] = dv.x; d[1] = dv.y; d[2] = dv.z; d[3] = dv.w;
        } else {
            for (int j = 0; j < cnt; j++) d[j] = p[E + base + j];
        }
    }
    for (int j = 0; j < cnt; j++) atomicAdd(&g_deg[d[j]], 1);
}

__global__ void blocksum_kernel(int N) {
    __shared__ int ws[32];
    int i = blockIdx.x * 1024 + threadIdx.x;
    int lane = threadIdx.x & 31, wid = threadIdx.x >> 5;
    int v = (i < N) ? g_deg[i] : 0;
#pragma unroll
    for (int o = 16; o > 0; o >>= 1) v += __shfl_xor_sync(0xffffffffu, v, o);
    if (lane == 0) ws[wid] = v;
    __syncthreads();
    if (wid == 0) {
        int t = ws[lane];
#pragma unroll
        for (int o = 16; o > 0; o >>= 1) t += __shfl_xor_sync(0xffffffffu, t, o);
        if (lane == 0) g_blocksum[blockIdx.x] = t;
    }
}

__global__ void scan2_kernel(int N) {
    __shared__ int woff[32];
    __shared__ int boff;
    int tid = threadIdx.x, lane = tid & 31, wid = tid >> 5;
    int b = blockIdx.x;
    int i = b * 1024 + tid;
    int v = (i < N) ? g_deg[i] : 0;
    int incl = v;
#pragma unroll
    for (int o = 1; o < 32; o <<= 1) {
        int t = __shfl_up_sync(0xffffffffu, incl, o);
        if (lane >= o) incl += t;
    }
    if (lane == 31) woff[wid] = incl;
    __syncthreads();
    if (wid == 0) {
        int s = woff[lane];
        int si = s;
#pragma unroll
        for (int o = 1; o < 32; o <<= 1) {
            int t = __shfl_up_sync(0xffffffffu, si, o);
            if (lane >= o) si += t;
        }
        woff[lane] = si - s;   // exclusive warp offsets
        int bs = (lane < b) ? g_blocksum[lane] : 0;
#pragma unroll
        for (int o = 16; o > 0; o >>= 1) bs += __shfl_xor_sync(0xffffffffu, bs, o);
        if (lane == 0) boff = bs;
    }
    __syncthreads();
    int start = boff + woff[wid] + incl - v;
    if (i < N) {
        g_rowptr[i] = start;
        g_fill[i]   = start;
    }
    if (i == N - 1) g_rowptr[N] = start + v;
}

__global__ void scatter_kernel(const void* __restrict__ eiv, int E) {
    int base = (blockIdx.x * blockDim.x + threadIdx.x) * 4;
    if (base >= E) return;
    int f = g_idx64;
    int cnt = min(4, E - base);
    int s[4], d[4];
    bool al = ((E & 3) == 0);
    if (f) {
        const long long* p = (const long long*)eiv;
        if (cnt == 4 && al) {
            longlong2 s01 = *(const longlong2*)(p + base);
            longlong2 s23 = *(const longlong2*)(p + base + 2);
            longlong2 d01 = *(const longlong2*)(p + E + base);
            longlong2 d23 = *(const longlong2*)(p + E + base + 2);
            s[0] = (int)s01.x; s[1] = (int)s01.y; s[2] = (int)s23.x; s[3] = (int)s23.y;
            d[0] = (int)d01.x; d[1] = (int)d01.y; d[2] = (int)d23.x; d[3] = (int)d23.y;
        } else {
            for (int j = 0; j < cnt; j++) { s[j] = (int)p[base + j]; d[j] = (int)p[E + base + j]; }
        }
    } else {
        const int* p = (const int*)eiv;
        if (cnt == 4 && al) {
            int4 sv = *(const int4*)(p + base);
            int4 dv = *(const int4*)(p + E + base);
            s[0] = sv.x; s[1] = sv.y; s[2] = sv.z; s[3] = sv.w;
            d[0] = dv.x; d[1] = dv.y; d[2] = dv.z; d[3] = dv.w;
        } else {
            for (int j = 0; j < cnt; j++) { s[j] = p[base + j]; d[j] = p[E + base + j]; }
        }
    }
    for (int j = 0; j < cnt; j++) {
        int pos = atomicAdd(&g_fill[d[j]], 1);
        g_eperm[pos] = make_int2(s[j], base + j);
    }
}

// ---------------------------------------------------------------------------
// agg1: warp per node, d=64, 2 cols/lane, W in REGISTERS (16 regs).
// agg[n] = sum_{e: dst=n} relu(x[src_e] + ea[e]@We + be)
// ---------------------------------------------------------------------------
__global__ void __launch_bounds__(256) agg1_kernel(
    const float* __restrict__ ea,
    const float* __restrict__ We, const float* __restrict__ be,
    const float* __restrict__ x, float* __restrict__ agg, int N)
{
    int tid = threadIdx.x, lane = tid & 31, wid = tid >> 5;
    int node = blockIdx.x * 8 + wid;
    if (node >= N) return;
    int c0 = lane * 2;
    float w0[8], w1[8];
#pragma unroll
    for (int k = 0; k < 8; k++) {
        float2 wv = *(const float2*)(We + k * 64 + c0);
        w0[k] = wv.x; w1[k] = wv.y;
    }
    float2 bv = *(const float2*)(be + c0);
    int beg = g_rowptr[node], end = g_rowptr[node + 1];
    float acc0 = 0.f, acc1 = 0.f;

    for (int i = beg; i < end; i += 2) {
        int2 pl = make_int2(0, 0);
        if (lane < 2 && i + lane < end) pl = g_eperm[i + lane];
        int s0 = __shfl_sync(0xffffffffu, pl.x, 0);
        int e0 = __shfl_sync(0xffffffffu, pl.y, 0);
        int s1 = __shfl_sync(0xffffffffu, pl.x, 1);
        int e1 = __shfl_sync(0xffffffffu, pl.y, 1);
        bool has1 = (i + 1 < end);
        int e1s = has1 ? e1 : e0, s1s = has1 ? s1 : s0;

        float4 a0 = __ldg((const float4*)(ea + (size_t)e0 * 8));
        float4 a1 = __ldg((const float4*)(ea + (size_t)e0 * 8) + 1);
        float4 b0 = __ldg((const float4*)(ea + (size_t)e1s * 8));
        float4 b1 = __ldg((const float4*)(ea + (size_t)e1s * 8) + 1);
        float2 xa = *(const float2*)(x + (size_t)s0 * 64 + c0);
        float2 xb = *(const float2*)(x + (size_t)s1s * 64 + c0);

        float aa[8] = {a0.x, a0.y, a0.z, a0.w, a1.x, a1.y, a1.z, a1.w};
        float ab[8] = {b0.x, b0.y, b0.z, b0.w, b1.x, b1.y, b1.z, b1.w};
        float ma0 = bv.x, ma1 = bv.y, mb0 = bv.x, mb1 = bv.y;
#pragma unroll
        for (int k = 0; k < 8; k++) {
            ma0 += aa[k] * w0[k]; ma1 += aa[k] * w1[k];
            mb0 += ab[k] * w0[k]; mb1 += ab[k] * w1[k];
        }
        acc0 += fmaxf(xa.x + ma0, 0.f);
        acc1 += fmaxf(xa.y + ma1, 0.f);
        if (has1) {
            acc0 += fmaxf(xb.x + mb0, 0.f);
            acc1 += fmaxf(xb.y + mb1, 0.f);
        }
    }
    *(float2*)(agg + (size_t)node * 64 + c0) = make_float2(acc0, acc1);
}

// ---------------------------------------------------------------------------
// agg2: 64 threads per node, d=256, 4 cols/lane, W in REGISTERS (32 regs).
// agg[n] = sum relu(h1[src] + ea@We2 + be2)
// ---------------------------------------------------------------------------
__global__ void __launch_bounds__(256) agg2_kernel(
    const float* __restrict__ ea,
    const float* __restrict__ We, const float* __restrict__ be,
    const float* __restrict__ h1, float* __restrict__ agg, int N)
{
    int tid = threadIdx.x, lane = tid & 31;
    int node = blockIdx.x * 4 + (tid >> 6);
    if (node >= N) return;
    int c0 = (tid & 63) * 4;
    float w0[8], w1[8], w2[8], w3[8];
#pragma unroll
    for (int k = 0; k < 8; k++) {
        float4 wv = *(const float4*)(We + k * 256 + c0);
        w0[k] = wv.x; w1[k] = wv.y; w2[k] = wv.z; w3[k] = wv.w;
    }
    float4 bv = *(const float4*)(be + c0);
    int beg = g_rowptr[node], end = g_rowptr[node + 1];
    float ac0 = 0.f, ac1 = 0.f, ac2 = 0.f, ac3 = 0.f;

    for (int i = beg; i < end; i += 2) {
        int2 pl = make_int2(0, 0);
        if (lane < 2 && i + lane < end) pl = g_eperm[i + lane];
        int s0 = __shfl_sync(0xffffffffu, pl.x, 0);
        int e0 = __shfl_sync(0xffffffffu, pl.y, 0);
        int s1 = __shfl_sync(0xffffffffu, pl.x, 1);
        int e1 = __shfl_sync(0xffffffffu, pl.y, 1);
        bool has1 = (i + 1 < end);
        int e1s = has1 ? e1 : e0, s1s = has1 ? s1 : s0;

        float4 a0 = __ldg((const float4*)(ea + (size_t)e0 * 8));
        float4 a1 = __ldg((const float4*)(ea + (size_t)e0 * 8) + 1);
        float4 b0 = __ldg((const float4*)(ea + (size_t)e1s * 8));
        float4 b1 = __ldg((const float4*)(ea + (size_t)e1s * 8) + 1);
        float4 ha = *(const float4*)(h1 + (size_t)s0 * 256 + c0);
        float4 hb = *(const float4*)(h1 + (size_t)s1s * 256 + c0);

        float aa[8] = {a0.x, a0.y, a0.z, a0.w, a1.x, a1.y, a1.z, a1.w};
        float ab[8] = {b0.x, b0.y, b0.z, b0.w, b1.x, b1.y, b1.z, b1.w};
        float ma0 = bv.x, ma1 = bv.y, ma2 = bv.z, ma3 = bv.w;
        float mb0 = bv.x, mb1 = bv.y, mb2 = bv.z, mb3 = bv.w;
#pragma unroll
        for (int k = 0; k < 8; k++) {
            ma0 += aa[k] * w0[k]; ma1 += aa[k] * w1[k];
            ma2 += aa[k] * w2[k]; ma3 += aa[k] * w3[k];
            mb0 += ab[k] * w0[k]; mb1 += ab[k] * w1[k];
            mb2 += ab[k] * w2[k]; mb3 += ab[k] * w3[k];
        }
        ac0 += fmaxf(ha.x + ma0, 0.f);
        ac1 += fmaxf(ha.y + ma1, 0.f);
        ac2 += fmaxf(ha.z + ma2, 0.f);
        ac3 += fmaxf(ha.w + ma3, 0.f);
        if (has1) {
            ac0 += fmaxf(hb.x + mb0, 0.f);
            ac1 += fmaxf(hb.y + mb1, 0.f);
            ac2 += fmaxf(hb.z + mb2, 0.f);
            ac3 += fmaxf(hb.w + mb3, 0.f);
        }
    }
    *(float4*)(agg + (size_t)node * 256 + c0) = make_float4(ac0, ac1, ac2, ac3);
}

// ---------------------------------------------------------------------------
// 3xTF32 tensor-core GEMM, B pre-split, fused PRE / bias / BN-stat epilogue.
// PRE: 1 (1+eps)*X + X2; 2 relu(A*X+B) with affine computed inline from
// layer-LIN stats. Stats accumulated into layer LOUT.
// ---------------------------------------------------------------------------
#define MMA_TF32(d, a, b)                                                     \
    asm volatile(                                                             \
        "mma.sync.aligned.m16n8k8.row.col.f32.tf32.tf32.f32 "                 \
        "{%0,%1,%2,%3},{%4,%5,%6,%7},{%8,%9},{%0,%1,%2,%3};"                  \
        : "+f"(d[0]), "+f"(d[1]), "+f"(d[2]), "+f"(d[3])                      \
        : "r"(a[0]), "r"(a[1]), "r"(a[2]), "r"(a[3]), "r"(b[0]), "r"(b[1]))

template <int K, int NCOLS, int PRE, int LIN, int LOUT>
__global__ void __launch_bounds__(256) gemm_mma(
    const float* __restrict__ X,
    const uint32_t* __restrict__ Whi, const uint32_t* __restrict__ Wlo,
    const float* __restrict__ bias, float* __restrict__ out,
    const float* __restrict__ X2, const float* __restrict__ eps_ptr,
    const float* __restrict__ gin, const float* __restrict__ btin,
    int N, float invN)
{
    constexpr int BM = 64, BN = 128, BK = 16;
    constexpr int KT = K / BK;
    __shared__ float    As[2][BK][BM + 4];
    __shared__ uint32_t Bh[2][BK][BN + 4];
    __shared__ uint32_t Bl[2][BK][BN + 4];
    __shared__ float ssum[BN], ssq[BN];
    __shared__ float sAf[256], sBf[256];

    int tid = threadIdx.x, lane = tid & 31, wid = tid >> 5;
    int wm = wid & 1, wn = wid >> 1;
    int n0  = blockIdx.x * BM;
    int nb0 = blockIdx.y * BN;

    for (int i = tid; i < BN; i += 256) { ssum[i] = 0.f; ssq[i] = 0.f; }
    if constexpr (PRE == 2) {
        for (int j = tid; j < K; j += 256) {
            float mu = g_colsum[LIN][j] * invN;
            float var = fmaxf(g_colsq[LIN][j] * invN - mu * mu, 0.f);
            float A = gin[j] * rsqrtf(var + 1e-5f);
            sAf[j] = A;
            sBf[j] = btin[j] - A * mu;
        }
    }
    __syncthreads();

    float eps = 0.f;
    if constexpr (PRE == 1) eps = 1.0f + *eps_ptr;

    float acc[2][4][4];
#pragma unroll
    for (int mt = 0; mt < 2; mt++)
#pragma unroll
        for (int nt = 0; nt < 4; nt++)
#pragma unroll
            for (int r = 0; r < 4; r++) acc[mt][nt][r] = 0.f;

    int a_row = tid >> 2;
    int a_kq  = (tid & 3) * 4;
    auto loadA = [&](int kt, float4& av) {
        int row = n0 + a_row;
        av = make_float4(0.f, 0.f, 0.f, 0.f);
        if (row < N) {
            int gk = kt * BK + a_kq;
            av = *(const float4*)(X + (size_t)row * K + gk);
            if constexpr (PRE == 1) {
                float4 xv = *(const float4*)(X2 + (size_t)row * K + gk);
                av.x = eps * av.x + xv.x; av.y = eps * av.y + xv.y;
                av.z = eps * av.z + xv.z; av.w = eps * av.w + xv.w;
            } else if constexpr (PRE == 2) {
                av.x = fmaxf(sAf[gk]     * av.x + sBf[gk],     0.f);
                av.y = fmaxf(sAf[gk + 1] * av.y + sBf[gk + 1], 0.f);
                av.z = fmaxf(sAf[gk + 2] * av.z + sBf[gk + 2], 0.f);
                av.w = fmaxf(sAf[gk + 3] * av.w + sBf[gk + 3], 0.f);
            }
        }
    };
    auto storeA = [&](int s, const float4& av) {
        As[s][a_kq][a_row]     = av.x;
        As[s][a_kq + 1][a_row] = av.y;
        As[s][a_kq + 2][a_row] = av.z;
        As[s][a_kq + 3][a_row] = av.w;
    };
    auto loadB = [&](int kt, uint4* bh, uint4* bl) {
#pragma unroll
        for (int r = 0; r < 2; r++) {
            int i = tid + r * 256;
            int krow = i >> 5, nq = i & 31;
            size_t off = (size_t)(kt * BK + krow) * NCOLS + nb0 + nq * 4;
            bh[r] = *(const uint4*)(Whi + off);
            bl[r] = *(const uint4*)(Wlo + off);
        }
    };
    auto storeB = [&](int s, const uint4* bh, const uint4* bl) {
#pragma unroll
        for (int r = 0; r < 2; r++) {
            int i = tid + r * 256;
            int krow = i >> 5, nq = i & 31;
            *(uint4*)&Bh[s][krow][nq * 4] = bh[r];
            *(uint4*)&Bl[s][krow][nq * 4] = bl[r];
        }
    };

    {
        float4 av; uint4 bh[2], bl[2];
        loadA(0, av); loadB(0, bh, bl);
        storeA(0, av); storeB(0, bh, bl);
    }
    __syncthreads();

    for (int kt = 0; kt < KT; kt++) {
        float4 nav; uint4 nbh[2], nbl[2];
        if (kt + 1 < KT) { loadA(kt + 1, nav); loadB(kt + 1, nbh, nbl); }
        int s = kt & 1;
#pragma unroll
        for (int ks = 0; ks < 2; ks++) {
            int kb = ks * 8;
            uint32_t ahi[2][4], alo[2][4];
#pragma unroll
            for (int mt = 0; mt < 2; mt++) {
#pragma unroll
                for (int r = 0; r < 4; r++) {
                    int kk = kb + (lane & 3) + ((r & 2) ? 4 : 0);
                    int mm = wm * 32 + mt * 16 + (lane >> 2) + ((r & 1) ? 8 : 0);
                    float f = As[s][kk][mm];
                    ahi[mt][r] = f2tf32(f);
                    alo[mt][r] = f2tf32(f - __uint_as_float(ahi[mt][r]));
                }
            }
            uint32_t bhi[4][2], blo[4][2];
#pragma unroll
            for (int nt = 0; nt < 4; nt++) {
#pragma unroll
                for (int r = 0; r < 2; r++) {
                    int kk = kb + (lane & 3) + r * 4;
                    int nn = wn * 32 + nt * 8 + (lane >> 2);
                    bhi[nt][r] = Bh[s][kk][nn];
                    blo[nt][r] = Bl[s][kk][nn];
                }
            }
#pragma unroll
            for (int mt = 0; mt < 2; mt++)
#pragma unroll
                for (int nt = 0; nt < 4; nt++) {
                    MMA_TF32(acc[mt][nt], ahi[mt], bhi[nt]);
                    MMA_TF32(acc[mt][nt], alo[mt], bhi[nt]);
                    MMA_TF32(acc[mt][nt], ahi[mt], blo[nt]);
                }
        }
        if (kt + 1 < KT) {
            storeA(s ^ 1, nav); storeB(s ^ 1, nbh, nbl);
            __syncthreads();
        }
    }

    // epilogue: bias, store, BN stats
#pragma unroll
    for (int nt = 0; nt < 4; nt++) {
        int cb = wn * 32 + nt * 8 + 2 * (lane & 3);
        float b0 = bias[nb0 + cb], b1 = bias[nb0 + cb + 1];
        float s0 = 0.f, s1 = 0.f, q0 = 0.f, q1 = 0.f;
#pragma unroll
        for (int mt = 0; mt < 2; mt++) {
            int row0 = n0 + wm * 32 + mt * 16 + (lane >> 2);
            float v0 = acc[mt][nt][0] + b0, v1 = acc[mt][nt][1] + b1;
            float v2 = acc[mt][nt][2] + b0, v3 = acc[mt][nt][3] + b1;
            if (row0 < N) {
                *(float2*)(out + (size_t)row0 * NCOLS + nb0 + cb) = make_float2(v0, v1);
                s0 += v0; s1 += v1; q0 += v0 * v0; q1 += v1 * v1;
            }
            if (row0 + 8 < N) {
                *(float2*)(out + (size_t)(row0 + 8) * NCOLS + nb0 + cb) = make_float2(v2, v3);
                s0 += v2; s1 += v3; q0 += v2 * v2; q1 += v3 * v3;
            }
        }
#pragma unroll
        for (int off = 4; off < 32; off <<= 1) {
            s0 += __shfl_xor_sync(0xffffffffu, s0, off);
            s1 += __shfl_xor_sync(0xffffffffu, s1, off);
            q0 += __shfl_xor_sync(0xffffffffu, q0, off);
            q1 += __shfl_xor_sync(0xffffffffu, q1, off);
        }
        if (lane < 4) {
            atomicAdd(&ssum[cb], s0); atomicAdd(&ssum[cb + 1], s1);
            atomicAdd(&ssq[cb],  q0); atomicAdd(&ssq[cb + 1],  q1);
        }
    }
    __syncthreads();
    for (int i = tid; i < BN; i += 256) {
        atomicAdd(&g_colsum[LOUT][nb0 + i], ssum[i]);
        atomicAdd(&g_colsq[LOUT][nb0 + i],  ssq[i]);
    }
}

// ---------------------------------------------------------------------------
// h = relu(bn(in)) with inline affine from layer-1 stats (256 cols)
// ---------------------------------------------------------------------------
__global__ void bnrelu_kernel(const float4* __restrict__ in,
                              float4* __restrict__ outp, int n4,
                              const float* __restrict__ g,
                              const float* __restrict__ bt, float invN)
{
    __shared__ float sA[256], sB[256];
    int tid = threadIdx.x;
    {
        float mu = g_colsum[1][tid] * invN;
        float var = fmaxf(g_colsq[1][tid] * invN - mu * mu, 0.f);
        float A = g[tid] * rsqrtf(var + 1e-5f);
        sA[tid] = A;
        sB[tid] = bt[tid] - A * mu;
    }
    __syncthreads();
    int i = blockIdx.x * 256 + tid;
    if (i >= n4) return;
    int c0 = (i & 63) * 4;
    float4 v = in[i];
    v.x = fmaxf(sA[c0]     * v.x + sB[c0],     0.f);
    v.y = fmaxf(sA[c0 + 1] * v.y + sB[c0 + 1], 0.f);
    v.z = fmaxf(sA[c0 + 2] * v.z + sB[c0 + 2], 0.f);
    v.w = fmaxf(sA[c0 + 3] * v.w + sB[c0 + 3], 0.f);
    outp[i] = v;
}

// ---------------------------------------------------------------------------
// Output head: out[n] = sum_j relu(bn3(t[n,j])) * Wout[j] + bout
// ---------------------------------------------------------------------------
__global__ void __launch_bounds__(256) out_kernel(
    const float* __restrict__ T, const float* __restrict__ Wout,
    const float* __restrict__ bout, float* __restrict__ out, int N,
    const float* __restrict__ g, const float* __restrict__ bt, float invN)
{
    __shared__ float sA[128], sB[128];
    int tid = threadIdx.x;
    if (tid < 128) {
        float mu = g_colsum[3][tid] * invN;
        float var = fmaxf(g_colsq[3][tid] * invN - mu * mu, 0.f);
        float A = g[tid] * rsqrtf(var + 1e-5f);
        sA[tid] = A;
        sB[tid] = bt[tid] - A * mu;
    }
    __syncthreads();
    int wid = tid >> 5, lane = tid & 31;
    int n = blockIdx.x * 8 + wid;
    if (n >= N) return;
    float4 t = ((const float4*)(T + (size_t)n * 128))[lane];
    float4 w = ((const float4*)Wout)[lane];
    int c = lane * 4;
    float s = fmaxf(sA[c]     * t.x + sB[c],     0.f) * w.x
            + fmaxf(sA[c + 1] * t.y + sB[c + 1], 0.f) * w.y
            + fmaxf(sA[c + 2] * t.z + sB[c + 2], 0.f) * w.z
            + fmaxf(sA[c + 3] * t.w + sB[c + 3], 0.f) * w.w;
#pragma unroll
    for (int o = 16; o > 0; o >>= 1)
        s += __shfl_xor_sync(0xffffffffu, s, o);
    if (lane == 0) out[n] = s + bout[0];
}

// ---------------------------------------------------------------------------
// Weight split: W -> (tf32 hi, tf32 residual).  Layout: W11|W12|W21|W22
// ---------------------------------------------------------------------------
__global__ void wsplit_kernel(const float* __restrict__ W11,
                              const float* __restrict__ W12,
                              const float* __restrict__ W21,
                              const float* __restrict__ W22) {
    int i = blockIdx.x * blockDim.x + threadIdx.x;
    float f;
    if (i < 16384)       f = W11[i];
    else if (i < 81920)  f = W12[i - 16384];
    else if (i < 114688) f = W21[i - 81920];
    else                 f = W22[i - 114688];
    uint32_t hi = f2tf32(f);
    g_Whi[i] = hi;
    g_Wlo[i] = f2tf32(f - __uint_as_float(hi));
}

// ---------------------------------------------------------------------------
extern "C" void kernel_launch(void* const* d_in, const int* in_sizes, int n_in,
                              void* d_out, int out_size)
{
    const float* x    = (const float*)d_in[0];
    const void*  ei   = d_in[1];
    const float* ea   = (const float*)d_in[2];
    const float* eps1 = (const float*)d_in[3];
    const float* We1  = (const float*)d_in[4];
    const float* be1  = (const float*)d_in[5];
    const float* W11  = (const float*)d_in[6];
    const float* b11  = (const float*)d_in[7];
    const float* g11  = (const float*)d_in[8];
    const float* bt11 = (const float*)d_in[9];
    const float* W12  = (const float*)d_in[10];
    const float* b12  = (const float*)d_in[11];
    const float* g1   = (const float*)d_in[12];
    const float* bt1  = (const float*)d_in[13];
    const float* eps2 = (const float*)d_in[14];
    const float* We2  = (const float*)d_in[15];
    const float* be2  = (const float*)d_in[16];
    const float* W21  = (const float*)d_in[17];
    const float* b21  = (const float*)d_in[18];
    const float* g21  = (const float*)d_in[19];
    const float* bt21 = (const float*)d_in[20];
    const float* W22  = (const float*)d_in[21];
    const float* b22  = (const float*)d_in[22];
    const float* g2   = (const float*)d_in[23];
    const float* bt2  = (const float*)d_in[24];
    const float* Wout = (const float*)d_in[25];
    const float* bout = (const float*)d_in[26];

    int N = in_sizes[0] / 64;   // 25000
    int E = in_sizes[2] / 8;    // 400000
    float invN = 1.0f / (float)N;

    float *agg1, *agg2, *bufA, *bufB;
    uint32_t *whi, *wlo;
    cudaGetSymbolAddress((void**)&agg1, g_agg1);
    cudaGetSymbolAddress((void**)&agg2, g_agg2);
    cudaGetSymbolAddress((void**)&bufA, g_bufA);
    cudaGetSymbolAddress((void**)&bufB, g_bufB);
    cudaGetSymbolAddress((void**)&whi, g_Whi);
    cudaGetSymbolAddress((void**)&wlo, g_Wlo);

    int NB = (N + 1023) / 1024;
    int EB = (E + 1023) / 1024;
    int gx = (N + 63) / 64;

    // --- CSR build (launches 0-4) ---
    setup_kernel<<<(N + 255) / 256, 256>>>((const int*)ei, N);
    hist_kernel<<<EB, 256>>>(ei, E);
    blocksum_kernel<<<NB, 1024>>>(N);
    scan2_kernel<<<NB, 1024>>>(N);
    scatter_kernel<<<EB, 256>>>(ei, E);

    // --- conv1 (agg1 is launch #5 -> ncu -s 5 captures it) ---
    agg1_kernel<<<(N + 7) / 8, 256>>>(ea, We1, be1, x, agg1, N);
    wsplit_kernel<<<512, 256>>>(W11, W12, W21, W22);
    gemm_mma<64, 256, 1, 0, 0><<<dim3(gx, 2), 256>>>(
        x, whi, wlo, b11, bufA, agg1, eps1, nullptr, nullptr, N, invN);
    gemm_mma<256, 256, 2, 0, 1><<<dim3(gx, 2), 256>>>(
        bufA, whi + 16384, wlo + 16384, b12, bufB, nullptr, nullptr, g11, bt11, N, invN);
    bnrelu_kernel<<<(N * 64 + 255) / 256, 256>>>(
        (const float4*)bufB, (float4*)bufA, N * 64, g1, bt1, invN);

    // --- conv2 ---
    agg2_kernel<<<(N + 3) / 4, 256>>>(ea, We2, be2, bufA, agg2, N);
    gemm_mma<256, 128, 1, 0, 2><<<dim3(gx, 1), 256>>>(
        bufA, whi + 81920, wlo + 81920, b21, bufB, agg2, eps2, nullptr, nullptr, N, invN);
    gemm_mma<128, 128, 2, 2, 3><<<dim3(gx, 1), 256>>>(
        bufB, whi + 114688, wlo + 114688, b22, bufA, nullptr, nullptr, g21, bt21, N, invN);

    // --- head ---
    out_kernel<<<(N + 7) / 8, 256>>>(bufA, Wout, bout, (float*)d_out, N, g2, bt2, invN);
}

// round 5
// speedup vs baseline: 2.1245x; 1.1631x over previous
#include <cuda_runtime.h>
#include <stdint.h>

// ---------------------------------------------------------------------------
// GINE 2-layer GNN, N=25000, E=400000, 64 -> 256 -> 256 -> 128 -> 128 -> 1
// R5: GEMM core switched to 3xBF16 (Ootomo split) with m16n8k16 mma —
// half the MMA instructions of 3xTF32/m16n8k8, B pre-split+packed bf16x2,
// conflict-free smem fragment loads, bit-mask residual computation.
// ---------------------------------------------------------------------------
#define MAXN 25000
#define MAXE 400000

__device__ float g_bufA[MAXN * 256];
__device__ float g_bufB[MAXN * 256];
__device__ float g_agg1[MAXN * 64];
__device__ float g_agg2[MAXN * 256];
__device__ float g_colsum[4][256];
__device__ float g_colsq[4][256];
__device__ int   g_idx64;
__device__ int   g_deg[MAXN];
__device__ int   g_rowptr[MAXN + 1];
__device__ int   g_fill[MAXN];
__device__ int   g_blocksum[32];
__device__ int2  g_eperm[MAXE];          // (src, edge_id) grouped by dst
// bf16x2-packed (along K) weight halves: W11|W12|W21|W22 (u32 pair-rows x N)
__device__ uint32_t g_Whi[65536];
__device__ uint32_t g_Wlo[65536];

__device__ __forceinline__ uint32_t packbf(float fhi, float flo) {
    uint32_t r;
    asm("cvt.rn.bf16x2.f32 %0, %1, %2;" : "=r"(r) : "f"(fhi), "f"(flo));
    return r;
}

// ---------------------------------------------------------------------------
// setup: zero degrees + zero BN stats + detect edge_index dtype (block 0)
// ---------------------------------------------------------------------------
__global__ void setup_kernel(const int* __restrict__ ei, int N) {
    int i = blockIdx.x * blockDim.x + threadIdx.x;
    if (i < N) g_deg[i] = 0;
    if (i < 1024) {
        ((float*)g_colsum)[i] = 0.f;
        ((float*)g_colsq)[i]  = 0.f;
    }
    if (blockIdx.x == 0) {
        __shared__ int found;
        if (threadIdx.x == 0) found = 0;
        __syncthreads();
        for (int j = threadIdx.x; j < 1024; j += blockDim.x)
            if (ei[2 * j + 1] != 0) found = 1;
        __syncthreads();
        if (threadIdx.x == 0) g_idx64 = found ? 0 : 1;
    }
}

// ---------------------------------------------------------------------------
// Weight split into bf16 hi/lo, packed bf16x2 along K.
// u32 layout per matrix: [K/2][N]. Offsets: W11 0, W12 8192, W21 40960, W22 57344.
// ---------------------------------------------------------------------------
__global__ void wsplit_kernel(const float* __restrict__ W11,
                              const float* __restrict__ W12,
                              const float* __restrict__ W21,
                              const float* __restrict__ W22) {
    int i = blockIdx.x * blockDim.x + threadIdx.x;   // < 65536
    const float* W; int Ncols, il;
    if (i < 8192)        { W = W11; Ncols = 256; il = i; }
    else if (i < 40960)  { W = W12; Ncols = 256; il = i - 8192; }
    else if (i < 57344)  { W = W21; Ncols = 128; il = i - 40960; }
    else                 { W = W22; Ncols = 128; il = i - 57344; }
    int pr = il / Ncols, n = il % Ncols;
    float f0 = W[(2 * pr) * Ncols + n];       // k even  -> low half
    float f1 = W[(2 * pr + 1) * Ncols + n];   // k odd   -> high half
    uint32_t hi = packbf(f1, f0);
    float lo0 = f0 - __uint_as_float(hi << 16);
    float lo1 = f1 - __uint_as_float(hi & 0xffff0000u);
    g_Whi[i] = hi;
    g_Wlo[i] = packbf(lo1, lo0);
}

// ---------------------------------------------------------------------------
// CSR build: histogram (4 edges/thread) -> warp-shuffle scan -> scatter
// ---------------------------------------------------------------------------
__global__ void hist_kernel(const void* __restrict__ eiv, int E) {
    int base = (blockIdx.x * blockDim.x + threadIdx.x) * 4;
    if (base >= E) return;
    int f = g_idx64;
    int cnt = min(4, E - base);
    int d[4];
    bool al = ((E & 3) == 0);
    if (f) {
        const long long* p = (const long long*)eiv;
        if (cnt == 4 && al) {
            longlong2 d01 = *(const longlong2*)(p + E + base);
            longlong2 d23 = *(const longlong2*)(p + E + base + 2);
            d[0] = (int)d01.x; d[1] = (int)d01.y; d[2] = (int)d23.x; d[3] = (int)d23.y;
        } else {
            for (int j = 0; j < cnt; j++) d[j] = (int)p[E + base + j];
        }
    } else {
        const int* p = (const int*)eiv;
        if (cnt == 4 && al) {
            int4 dv = *(const int4*)(p + E + base);
            d[0] = dv.x; d[1] = dv.y; d[2] = dv.z; d[3] = dv.w;
        } else {
            for (int j = 0; j < cnt; j++) d[j] = p[E + base + j];
        }
    }
    for (int j = 0; j < cnt; j++) atomicAdd(&g_deg[d[j]], 1);
}

__global__ void blocksum_kernel(int N) {
    __shared__ int ws[32];
    int i = blockIdx.x * 1024 + threadIdx.x;
    int lane = threadIdx.x & 31, wid = threadIdx.x >> 5;
    int v = (i < N) ? g_deg[i] : 0;
#pragma unroll
    for (int o = 16; o > 0; o >>= 1) v += __shfl_xor_sync(0xffffffffu, v, o);
    if (lane == 0) ws[wid] = v;
    __syncthreads();
    if (wid == 0) {
        int t = ws[lane];
#pragma unroll
        for (int o = 16; o > 0; o >>= 1) t += __shfl_xor_sync(0xffffffffu, t, o);
        if (lane == 0) g_blocksum[blockIdx.x] = t;
    }
}

__global__ void scan2_kernel(int N) {
    __shared__ int woff[32];
    __shared__ int boff;
    int tid = threadIdx.x, lane = tid & 31, wid = tid >> 5;
    int b = blockIdx.x;
    int i = b * 1024 + tid;
    int v = (i < N) ? g_deg[i] : 0;
    int incl = v;
#pragma unroll
    for (int o = 1; o < 32; o <<= 1) {
        int t = __shfl_up_sync(0xffffffffu, incl, o);
        if (lane >= o) incl += t;
    }
    if (lane == 31) woff[wid] = incl;
    __syncthreads();
    if (wid == 0) {
        int s = woff[lane];
        int si = s;
#pragma unroll
        for (int o = 1; o < 32; o <<= 1) {
            int t = __shfl_up_sync(0xffffffffu, si, o);
            if (lane >= o) si += t;
        }
        woff[lane] = si - s;
        int bs = (lane < b) ? g_blocksum[lane] : 0;
#pragma unroll
        for (int o = 16; o > 0; o >>= 1) bs += __shfl_xor_sync(0xffffffffu, bs, o);
        if (lane == 0) boff = bs;
    }
    __syncthreads();
    int start = boff + woff[wid] + incl - v;
    if (i < N) {
        g_rowptr[i] = start;
        g_fill[i]   = start;
    }
    if (i == N - 1) g_rowptr[N] = start + v;
}

__global__ void scatter_kernel(const void* __restrict__ eiv, int E) {
    int base = (blockIdx.x * blockDim.x + threadIdx.x) * 4;
    if (base >= E) return;
    int f = g_idx64;
    int cnt = min(4, E - base);
    int s[4], d[4];
    bool al = ((E & 3) == 0);
    if (f) {
        const long long* p = (const long long*)eiv;
        if (cnt == 4 && al) {
            longlong2 s01 = *(const longlong2*)(p + base);
            longlong2 s23 = *(const longlong2*)(p + base + 2);
            longlong2 d01 = *(const longlong2*)(p + E + base);
            longlong2 d23 = *(const longlong2*)(p + E + base + 2);
            s[0] = (int)s01.x; s[1] = (int)s01.y; s[2] = (int)s23.x; s[3] = (int)s23.y;
            d[0] = (int)d01.x; d[1] = (int)d01.y; d[2] = (int)d23.x; d[3] = (int)d23.y;
        } else {
            for (int j = 0; j < cnt; j++) { s[j] = (int)p[base + j]; d[j] = (int)p[E + base + j]; }
        }
    } else {
        const int* p = (const int*)eiv;
        if (cnt == 4 && al) {
            int4 sv = *(const int4*)(p + base);
            int4 dv = *(const int4*)(p + E + base);
            s[0] = sv.x; s[1] = sv.y; s[2] = sv.z; s[3] = sv.w;
            d[0] = dv.x; d[1] = dv.y; d[2] = dv.z; d[3] = dv.w;
        } else {
            for (int j = 0; j < cnt; j++) { s[j] = p[base + j]; d[j] = p[E + base + j]; }
        }
    }
    for (int j = 0; j < cnt; j++) {
        int pos = atomicAdd(&g_fill[d[j]], 1);
        g_eperm[pos] = make_int2(s[j], base + j);
    }
}

// ---------------------------------------------------------------------------
// agg1: warp per node, d=64, 2 cols/lane, W in registers.
// ---------------------------------------------------------------------------
__global__ void __launch_bounds__(256) agg1_kernel(
    const float* __restrict__ ea,
    const float* __restrict__ We, const float* __restrict__ be,
    const float* __restrict__ x, float* __restrict__ agg, int N)
{
    int tid = threadIdx.x, lane = tid & 31, wid = tid >> 5;
    int node = blockIdx.x * 8 + wid;
    if (node >= N) return;
    int c0 = lane * 2;
    float w0[8], w1[8];
#pragma unroll
    for (int k = 0; k < 8; k++) {
        float2 wv = *(const float2*)(We + k * 64 + c0);
        w0[k] = wv.x; w1[k] = wv.y;
    }
    float2 bv = *(const float2*)(be + c0);
    int beg = g_rowptr[node], end = g_rowptr[node + 1];
    float acc0 = 0.f, acc1 = 0.f;

    for (int i = beg; i < end; i += 2) {
        int2 pl = make_int2(0, 0);
        if (lane < 2 && i + lane < end) pl = g_eperm[i + lane];
        int s0 = __shfl_sync(0xffffffffu, pl.x, 0);
        int e0 = __shfl_sync(0xffffffffu, pl.y, 0);
        int s1 = __shfl_sync(0xffffffffu, pl.x, 1);
        int e1 = __shfl_sync(0xffffffffu, pl.y, 1);
        bool has1 = (i + 1 < end);
        int e1s = has1 ? e1 : e0, s1s = has1 ? s1 : s0;

        float4 a0 = __ldg((const float4*)(ea + (size_t)e0 * 8));
        float4 a1 = __ldg((const float4*)(ea + (size_t)e0 * 8) + 1);
        float4 b0 = __ldg((const float4*)(ea + (size_t)e1s * 8));
        float4 b1 = __ldg((const float4*)(ea + (size_t)e1s * 8) + 1);
        float2 xa = *(const float2*)(x + (size_t)s0 * 64 + c0);
        float2 xb = *(const float2*)(x + (size_t)s1s * 64 + c0);

        float aa[8] = {a0.x, a0.y, a0.z, a0.w, a1.x, a1.y, a1.z, a1.w};
        float ab[8] = {b0.x, b0.y, b0.z, b0.w, b1.x, b1.y, b1.z, b1.w};
        float ma0 = bv.x, ma1 = bv.y, mb0 = bv.x, mb1 = bv.y;
#pragma unroll
        for (int k = 0; k < 8; k++) {
            ma0 += aa[k] * w0[k]; ma1 += aa[k] * w1[k];
            mb0 += ab[k] * w0[k]; mb1 += ab[k] * w1[k];
        }
        acc0 += fmaxf(xa.x + ma0, 0.f);
        acc1 += fmaxf(xa.y + ma1, 0.f);
        if (has1) {
            acc0 += fmaxf(xb.x + mb0, 0.f);
            acc1 += fmaxf(xb.y + mb1, 0.f);
        }
    }
    *(float2*)(agg + (size_t)node * 64 + c0) = make_float2(acc0, acc1);
}

// ---------------------------------------------------------------------------
// agg2: 64 threads per node, d=256, 4 cols/lane, W in registers.
// ---------------------------------------------------------------------------
__global__ void __launch_bounds__(256) agg2_kernel(
    const float* __restrict__ ea,
    const float* __restrict__ We, const float* __restrict__ be,
    const float* __restrict__ h1, float* __restrict__ agg, int N)
{
    int tid = threadIdx.x, lane = tid & 31;
    int node = blockIdx.x * 4 + (tid >> 6);
    if (node >= N) return;
    int c0 = (tid & 63) * 4;
    float w0[8], w1[8], w2[8], w3[8];
#pragma unroll
    for (int k = 0; k < 8; k++) {
        float4 wv = *(const float4*)(We + k * 256 + c0);
        w0[k] = wv.x; w1[k] = wv.y; w2[k] = wv.z; w3[k] = wv.w;
    }
    float4 bv = *(const float4*)(be + c0);
    int beg = g_rowptr[node], end = g_rowptr[node + 1];
    float ac0 = 0.f, ac1 = 0.f, ac2 = 0.f, ac3 = 0.f;

    for (int i = beg; i < end; i += 2) {
        int2 pl = make_int2(0, 0);
        if (lane < 2 && i + lane < end) pl = g_eperm[i + lane];
        int s0 = __shfl_sync(0xffffffffu, pl.x, 0);
        int e0 = __shfl_sync(0xffffffffu, pl.y, 0);
        int s1 = __shfl_sync(0xffffffffu, pl.x, 1);
        int e1 = __shfl_sync(0xffffffffu, pl.y, 1);
        bool has1 = (i + 1 < end);
        int e1s = has1 ? e1 : e0, s1s = has1 ? s1 : s0;

        float4 a0 = __ldg((const float4*)(ea + (size_t)e0 * 8));
        float4 a1 = __ldg((const float4*)(ea + (size_t)e0 * 8) + 1);
        float4 b0 = __ldg((const float4*)(ea + (size_t)e1s * 8));
        float4 b1 = __ldg((const float4*)(ea + (size_t)e1s * 8) + 1);
        float4 ha = *(const float4*)(h1 + (size_t)s0 * 256 + c0);
        float4 hb = *(const float4*)(h1 + (size_t)s1s * 256 + c0);

        float aa[8] = {a0.x, a0.y, a0.z, a0.w, a1.x, a1.y, a1.z, a1.w};
        float ab[8] = {b0.x, b0.y, b0.z, b0.w, b1.x, b1.y, b1.z, b1.w};
        float ma0 = bv.x, ma1 = bv.y, ma2 = bv.z, ma3 = bv.w;
        float mb0 = bv.x, mb1 = bv.y, mb2 = bv.z, mb3 = bv.w;
#pragma unroll
        for (int k = 0; k < 8; k++) {
            ma0 += aa[k] * w0[k]; ma1 += aa[k] * w1[k];
            ma2 += aa[k] * w2[k]; ma3 += aa[k] * w3[k];
            mb0 += ab[k] * w0[k]; mb1 += ab[k] * w1[k];
            mb2 += ab[k] * w2[k]; mb3 += ab[k] * w3[k];
        }
        ac0 += fmaxf(ha.x + ma0, 0.f);
        ac1 += fmaxf(ha.y + ma1, 0.f);
        ac2 += fmaxf(ha.z + ma2, 0.f);
        ac3 += fmaxf(ha.w + ma3, 0.f);
        if (has1) {
            ac0 += fmaxf(hb.x + mb0, 0.f);
            ac1 += fmaxf(hb.y + mb1, 0.f);
            ac2 += fmaxf(hb.z + mb2, 0.f);
            ac3 += fmaxf(hb.w + mb3, 0.f);
        }
    }
    *(float4*)(agg + (size_t)node * 256 + c0) = make_float4(ac0, ac1, ac2, ac3);
}

// ---------------------------------------------------------------------------
// 3xBF16 tensor-core GEMM (m16n8k16), B pre-split bf16x2-packed.
// out[N,NCOLS] = PRE(X)[N,K] @ W[K,NCOLS] + bias, fused BN-stat epilogue.
// PRE: 1 (1+eps)*X + X2; 2 relu(A*X+B) from layer-LIN stats. Stats -> LOUT.
// Block 256 (8 warps: 2M x 4N), BM=64 BN=128 BK=16, warp tile 32x32.
// ---------------------------------------------------------------------------
#define MMA_BF16(d, a, b)                                                     \
    asm volatile(                                                             \
        "mma.sync.aligned.m16n8k16.row.col.f32.bf16.bf16.f32 "                \
        "{%0,%1,%2,%3},{%4,%5,%6,%7},{%8,%9},{%0,%1,%2,%3};"                  \
        : "+f"(d[0]), "+f"(d[1]), "+f"(d[2]), "+f"(d[3])                      \
        : "r"(a[0]), "r"(a[1]), "r"(a[2]), "r"(a[3]), "r"(b[0]), "r"(b[1]))

template <int K, int NCOLS, int PRE, int LIN, int LOUT>
__global__ void __launch_bounds__(256) gemm_mma(
    const float* __restrict__ X,
    const uint32_t* __restrict__ Wh2, const uint32_t* __restrict__ Wl2,
    const float* __restrict__ bias, float* __restrict__ out,
    const float* __restrict__ X2, const float* __restrict__ eps_ptr,
    const float* __restrict__ gin, const float* __restrict__ btin,
    int N, float invN)
{
    constexpr int BM = 64, BN = 128, BK = 16;
    constexpr int KT = K / BK;
    constexpr int AP = 20;    // A row pad (floats): 80B rows, 16B-aligned
    constexpr int BP = 136;   // B row pad (u32): conflict-free fragments
    __shared__ __align__(16) float    As[2][BM][AP];
    __shared__ __align__(16) uint32_t Bh[2][8][BP];
    __shared__ __align__(16) uint32_t Bl[2][8][BP];
    __shared__ float ssum[BN], ssq[BN];
    __shared__ float sAf[256], sBf[256];

    int tid = threadIdx.x, lane = tid & 31, wid = tid >> 5;
    int wm = wid & 1, wn = wid >> 1;
    int n0  = blockIdx.x * BM;
    int nb0 = blockIdx.y * BN;

    for (int i = tid; i < BN; i += 256) { ssum[i] = 0.f; ssq[i] = 0.f; }
    if constexpr (PRE == 2) {
        for (int j = tid; j < K; j += 256) {
            float mu = g_colsum[LIN][j] * invN;
            float var = fmaxf(g_colsq[LIN][j] * invN - mu * mu, 0.f);
            float A = gin[j] * rsqrtf(var + 1e-5f);
            sAf[j] = A;
            sBf[j] = btin[j] - A * mu;
        }
    }
    __syncthreads();

    float eps = 0.f;
    if constexpr (PRE == 1) eps = 1.0f + *eps_ptr;

    float acc[2][4][4];
#pragma unroll
    for (int mt = 0; mt < 2; mt++)
#pragma unroll
        for (int nt = 0; nt < 4; nt++)
#pragma unroll
            for (int r = 0; r < 4; r++) acc[mt][nt][r] = 0.f;

    int a_row = tid >> 2;           // 0..63
    int a_kq  = (tid & 3) * 4;      // 0,4,8,12
    auto loadA = [&](int kt, float4& av) {
        int row = n0 + a_row;
        av = make_float4(0.f, 0.f, 0.f, 0.f);
        if (row < N) {
            int gk = kt * BK + a_kq;
            av = *(const float4*)(X + (size_t)row * K + gk);
            if constexpr (PRE == 1) {
                float4 xv = *(const float4*)(X2 + (size_t)row * K + gk);
                av.x = eps * av.x + xv.x; av.y = eps * av.y + xv.y;
                av.z = eps * av.z + xv.z; av.w = eps * av.w + xv.w;
            } else if constexpr (PRE == 2) {
                av.x = fmaxf(sAf[gk]     * av.x + sBf[gk],     0.f);
                av.y = fmaxf(sAf[gk + 1] * av.y + sBf[gk + 1], 0.f);
                av.z = fmaxf(sAf[gk + 2] * av.z + sBf[gk + 2], 0.f);
                av.w = fmaxf(sAf[gk + 3] * av.w + sBf[gk + 3], 0.f);
            }
        }
    };
    auto storeA = [&](int s, const float4& av) {
        *(float4*)&As[s][a_row][a_kq] = av;
    };
    // B tile: pair-rows kt*8 .. kt*8+7, 128 u32 each. 1 uint4/thread per part.
    int b_kr = tid >> 5, b_nq = tid & 31;
    auto loadB = [&](int kt, uint4& bh, uint4& bl) {
        size_t off = (size_t)(kt * 8 + b_kr) * NCOLS + nb0 + b_nq * 4;
        bh = *(const uint4*)(Wh2 + off);
        bl = *(const uint4*)(Wl2 + off);
    };
    auto storeB = [&](int s, const uint4& bh, const uint4& bl) {
        *(uint4*)&Bh[s][b_kr][b_nq * 4] = bh;
        *(uint4*)&Bl[s][b_kr][b_nq * 4] = bl;
    };

    {
        float4 av; uint4 bh, bl;
        loadA(0, av); loadB(0, bh, bl);
        storeA(0, av); storeB(0, bh, bl);
    }
    __syncthreads();

    int t2 = (lane & 3) * 2;
    int mrow = (lane >> 2);

    for (int kt = 0; kt < KT; kt++) {
        float4 nav; uint4 nbh, nbl;
        if (kt + 1 < KT) { loadA(kt + 1, nav); loadB(kt + 1, nbh, nbl); }
        int s = kt & 1;

        // A fragments (hi + residual lo via bit-mask)
        uint32_t ahi[2][4], alo[2][4];
#pragma unroll
        for (int mt = 0; mt < 2; mt++) {
            int m0 = wm * 32 + mt * 16 + mrow;
            float2 f00 = *(const float2*)&As[s][m0][t2];
            float2 f10 = *(const float2*)&As[s][m0 + 8][t2];
            float2 f01 = *(const float2*)&As[s][m0][t2 + 8];
            float2 f11 = *(const float2*)&As[s][m0 + 8][t2 + 8];
            uint32_t h0 = packbf(f00.y, f00.x);
            uint32_t h1 = packbf(f10.y, f10.x);
            uint32_t h2 = packbf(f01.y, f01.x);
            uint32_t h3 = packbf(f11.y, f11.x);
            ahi[mt][0] = h0; ahi[mt][1] = h1; ahi[mt][2] = h2; ahi[mt][3] = h3;
            alo[mt][0] = packbf(f00.y - __uint_as_float(h0 & 0xffff0000u),
                                f00.x - __uint_as_float(h0 << 16));
            alo[mt][1] = packbf(f10.y - __uint_as_float(h1 & 0xffff0000u),
                                f10.x - __uint_as_float(h1 << 16));
            alo[mt][2] = packbf(f01.y - __uint_as_float(h2 & 0xffff0000u),
                                f01.x - __uint_as_float(h2 << 16));
            alo[mt][3] = packbf(f11.y - __uint_as_float(h3 & 0xffff0000u),
                                f11.x - __uint_as_float(h3 << 16));
        }
        // B fragments (direct LDS)
        uint32_t bhi[4][2], blo[4][2];
#pragma unroll
        for (int nt = 0; nt < 4; nt++) {
            int n = wn * 32 + nt * 8 + (lane >> 2);
            int tg = lane & 3;
            bhi[nt][0] = Bh[s][tg][n];     bhi[nt][1] = Bh[s][tg + 4][n];
            blo[nt][0] = Bl[s][tg][n];     blo[nt][1] = Bl[s][tg + 4][n];
        }
#pragma unroll
        for (int mt = 0; mt < 2; mt++)
#pragma unroll
            for (int nt = 0; nt < 4; nt++) {
                MMA_BF16(acc[mt][nt], ahi[mt], bhi[nt]);
                MMA_BF16(acc[mt][nt], alo[mt], bhi[nt]);
                MMA_BF16(acc[mt][nt], ahi[mt], blo[nt]);
            }
        if (kt + 1 < KT) {
            __syncthreads();
            storeA(s ^ 1, nav); storeB(s ^ 1, nbh, nbl);
            __syncthreads();
        }
    }

    // epilogue: bias, store, BN stats
#pragma unroll
    for (int nt = 0; nt < 4; nt++) {
        int cb = wn * 32 + nt * 8 + 2 * (lane & 3);
        float b0 = bias[nb0 + cb], b1 = bias[nb0 + cb + 1];
        float s0 = 0.f, s1 = 0.f, q0 = 0.f, q1 = 0.f;
#pragma unroll
        for (int mt = 0; mt < 2; mt++) {
            int row0 = n0 + wm * 32 + mt * 16 + (lane >> 2);
            float v0 = acc[mt][nt][0] + b0, v1 = acc[mt][nt][1] + b1;
            float v2 = acc[mt][nt][2] + b0, v3 = acc[mt][nt][3] + b1;
            if (row0 < N) {
                *(float2*)(out + (size_t)row0 * NCOLS + nb0 + cb) = make_float2(v0, v1);
                s0 += v0; s1 += v1; q0 += v0 * v0; q1 += v1 * v1;
            }
            if (row0 + 8 < N) {
                *(float2*)(out + (size_t)(row0 + 8) * NCOLS + nb0 + cb) = make_float2(v2, v3);
                s0 += v2; s1 += v3; q0 += v2 * v2; q1 += v3 * v3;
            }
        }
#pragma unroll
        for (int off = 4; off < 32; off <<= 1) {
            s0 += __shfl_xor_sync(0xffffffffu, s0, off);
            s1 += __shfl_xor_sync(0xffffffffu, s1, off);
            q0 += __shfl_xor_sync(0xffffffffu, q0, off);
            q1 += __shfl_xor_sync(0xffffffffu, q1, off);
        }
        if (lane < 4) {
            atomicAdd(&ssum[cb], s0); atomicAdd(&ssum[cb + 1], s1);
            atomicAdd(&ssq[cb],  q0); atomicAdd(&ssq[cb + 1],  q1);
        }
    }
    __syncthreads();
    for (int i = tid; i < BN; i += 256) {
        atomicAdd(&g_colsum[LOUT][nb0 + i], ssum[i]);
        atomicAdd(&g_colsq[LOUT][nb0 + i],  ssq[i]);
    }
}

// ---------------------------------------------------------------------------
// h = relu(bn(in)) with inline affine from layer-1 stats (256 cols)
// ---------------------------------------------------------------------------
__global__ void bnrelu_kernel(const float4* __restrict__ in,
                              float4* __restrict__ outp, int n4,
                              const float* __restrict__ g,
                              const float* __restrict__ bt, float invN)
{
    __shared__ float sA[256], sB[256];
    int tid = threadIdx.x;
    {
        float mu = g_colsum[1][tid] * invN;
        float var = fmaxf(g_colsq[1][tid] * invN - mu * mu, 0.f);
        float A = g[tid] * rsqrtf(var + 1e-5f);
        sA[tid] = A;
        sB[tid] = bt[tid] - A * mu;
    }
    __syncthreads();
    int i = blockIdx.x * 256 + tid;
    if (i >= n4) return;
    int c0 = (i & 63) * 4;
    float4 v = in[i];
    v.x = fmaxf(sA[c0]     * v.x + sB[c0],     0.f);
    v.y = fmaxf(sA[c0 + 1] * v.y + sB[c0 + 1], 0.f);
    v.z = fmaxf(sA[c0 + 2] * v.z + sB[c0 + 2], 0.f);
    v.w = fmaxf(sA[c0 + 3] * v.w + sB[c0 + 3], 0.f);
    outp[i] = v;
}

// ---------------------------------------------------------------------------
// Output head: out[n] = sum_j relu(bn3(t[n,j])) * Wout[j] + bout
// ---------------------------------------------------------------------------
__global__ void __launch_bounds__(256) out_kernel(
    const float* __restrict__ T, const float* __restrict__ Wout,
    const float* __restrict__ bout, float* __restrict__ out, int N,
    const float* __restrict__ g, const float* __restrict__ bt, float invN)
{
    __shared__ float sA[128], sB[128];
    int tid = threadIdx.x;
    if (tid < 128) {
        float mu = g_colsum[3][tid] * invN;
        float var = fmaxf(g_colsq[3][tid] * invN - mu * mu, 0.f);
        float A = g[tid] * rsqrtf(var + 1e-5f);
        sA[tid] = A;
        sB[tid] = bt[tid] - A * mu;
    }
    __syncthreads();
    int wid = tid >> 5, lane = tid & 31;
    int n = blockIdx.x * 8 + wid;
    if (n >= N) return;
    float4 t = ((const float4*)(T + (size_t)n * 128))[lane];
    float4 w = ((const float4*)Wout)[lane];
    int c = lane * 4;
    float s = fmaxf(sA[c]     * t.x + sB[c],     0.f) * w.x
            + fmaxf(sA[c + 1] * t.y + sB[c + 1], 0.f) * w.y
            + fmaxf(sA[c + 2] * t.z + sB[c + 2], 0.f) * w.z
            + fmaxf(sA[c + 3] * t.w + sB[c + 3], 0.f) * w.w;
#pragma unroll
    for (int o = 16; o > 0; o >>= 1)
        s += __shfl_xor_sync(0xffffffffu, s, o);
    if (lane == 0) out[n] = s + bout[0];
}

// ---------------------------------------------------------------------------
extern "C" void kernel_launch(void* const* d_in, const int* in_sizes, int n_in,
                              void* d_out, int out_size)
{
    const float* x    = (const float*)d_in[0];
    const void*  ei   = d_in[1];
    const float* ea   = (const float*)d_in[2];
    const float* eps1 = (const float*)d_in[3];
    const float* We1  = (const float*)d_in[4];
    const float* be1  = (const float*)d_in[5];
    const float* W11  = (const float*)d_in[6];
    const float* b11  = (const float*)d_in[7];
    const float* g11  = (const float*)d_in[8];
    const float* bt11 = (const float*)d_in[9];
    const float* W12  = (const float*)d_in[10];
    const float* b12  = (const float*)d_in[11];
    const float* g1   = (const float*)d_in[12];
    const float* bt1  = (const float*)d_in[13];
    const float* eps2 = (const float*)d_in[14];
    const float* We2  = (const float*)d_in[15];
    const float* be2  = (const float*)d_in[16];
    const float* W21  = (const float*)d_in[17];
    const float* b21  = (const float*)d_in[18];
    const float* g21  = (const float*)d_in[19];
    const float* bt21 = (const float*)d_in[20];
    const float* W22  = (const float*)d_in[21];
    const float* b22  = (const float*)d_in[22];
    const float* g2   = (const float*)d_in[23];
    const float* bt2  = (const float*)d_in[24];
    const float* Wout = (const float*)d_in[25];
    const float* bout = (const float*)d_in[26];

    int N = in_sizes[0] / 64;   // 25000
    int E = in_sizes[2] / 8;    // 400000
    float invN = 1.0f / (float)N;

    float *agg1, *agg2, *bufA, *bufB;
    uint32_t *whi, *wlo;
    cudaGetSymbolAddress((void**)&agg1, g_agg1);
    cudaGetSymbolAddress((void**)&agg2, g_agg2);
    cudaGetSymbolAddress((void**)&bufA, g_bufA);
    cudaGetSymbolAddress((void**)&bufB, g_bufB);
    cudaGetSymbolAddress((void**)&whi, g_Whi);
    cudaGetSymbolAddress((void**)&wlo, g_Wlo);

    int NB = (N + 1023) / 1024;
    int EB = (E + 1023) / 1024;
    int gx = (N + 63) / 64;

    // --- setup + CSR build ---
    setup_kernel<<<(N + 255) / 256, 256>>>((const int*)ei, N);
    hist_kernel<<<EB, 256>>>(ei, E);
    wsplit_kernel<<<256, 256>>>(W11, W12, W21, W22);
    blocksum_kernel<<<NB, 1024>>>(N);
    scan2_kernel<<<NB, 1024>>>(N);
    scatter_kernel<<<EB, 256>>>(ei, E);

    // --- conv1 ---
    agg1_kernel<<<(N + 7) / 8, 256>>>(ea, We1, be1, x, agg1, N);
    gemm_mma<64, 256, 1, 0, 0><<<dim3(gx, 2), 256>>>(
        x, whi, wlo, b11, bufA, agg1, eps1, nullptr, nullptr, N, invN);
    gemm_mma<256, 256, 2, 0, 1><<<dim3(gx, 2), 256>>>(
        bufA, whi + 8192, wlo + 8192, b12, bufB, nullptr, nullptr, g11, bt11, N, invN);
    bnrelu_kernel<<<(N * 64 + 255) / 256, 256>>>(
        (const float4*)bufB, (float4*)bufA, N * 64, g1, bt1, invN);

    // --- conv2 ---
    agg2_kernel<<<(N + 3) / 4, 256>>>(ea, We2, be2, bufA, agg2, N);
    gemm_mma<256, 128, 1, 0, 2><<<dim3(gx, 1), 256>>>(
        bufA, whi + 40960, wlo + 40960, b21, bufB, agg2, eps2, nullptr, nullptr, N, invN);
    gemm_mma<128, 128, 2, 2, 3><<<dim3(gx, 1), 256>>>(
        bufB, whi + 57344, wlo + 57344, b22, bufA, nullptr, nullptr, g21, bt21, N, invN);

    // --- head ---
    out_kernel<<<(N + 7) / 8, 256>>>(bufA, Wout, bout, (float*)d_out, N, g2, bt2, invN);
}

// round 6
// speedup vs baseline: 2.3152x; 1.0897x over previous
#include <cuda_runtime.h>
#include <stdint.h>

// ---------------------------------------------------------------------------
// GINE 2-layer GNN, N=25000, E=400000, 64 -> 256 -> 256 -> 128 -> 128 -> 1
// R6: GEMM mainloop overhaul — A pre-split (hi/lo bf16x2) into smem by the
// tile loader, BK=32, cp.async B tiles, conflict-free fragment LDS.
// ---------------------------------------------------------------------------
#define MAXN 25000
#define MAXE 400000

__device__ float g_bufA[MAXN * 256];
__device__ float g_bufB[MAXN * 256];
__device__ float g_agg1[MAXN * 64];
__device__ float g_agg2[MAXN * 256];
__device__ float g_colsum[4][256];
__device__ float g_colsq[4][256];
__device__ int   g_idx64;
__device__ int   g_deg[MAXN];
__device__ int   g_rowptr[MAXN + 1];
__device__ int   g_fill[MAXN];
__device__ int   g_blocksum[32];
__device__ int2  g_eperm[MAXE];          // (src, edge_id) grouped by dst
// bf16x2-packed (along K) weight halves: W11|W12|W21|W22 ([K/2][N] u32 each)
__device__ uint32_t g_Whi[65536];
__device__ uint32_t g_Wlo[65536];

__device__ __forceinline__ uint32_t packbf(float fhi, float flo) {
    uint32_t r;
    asm("cvt.rn.bf16x2.f32 %0, %1, %2;" : "=r"(r) : "f"(fhi), "f"(flo));
    return r;
}
__device__ __forceinline__ void cp16(uint32_t saddr, const void* g) {
    asm volatile("cp.async.cg.shared.global [%0], [%1], 16;" :: "r"(saddr), "l"(g));
}
__device__ __forceinline__ void cp_commit() {
    asm volatile("cp.async.commit_group;" ::: "memory");
}
__device__ __forceinline__ void cp_wait0() {
    asm volatile("cp.async.wait_group 0;" ::: "memory");
}

// ---------------------------------------------------------------------------
// setup: zero degrees + zero BN stats + detect edge_index dtype (block 0)
// ---------------------------------------------------------------------------
__global__ void setup_kernel(const int* __restrict__ ei, int N) {
    int i = blockIdx.x * blockDim.x + threadIdx.x;
    if (i < N) g_deg[i] = 0;
    if (i < 1024) {
        ((float*)g_colsum)[i] = 0.f;
        ((float*)g_colsq)[i]  = 0.f;
    }
    if (blockIdx.x == 0) {
        __shared__ int found;
        if (threadIdx.x == 0) found = 0;
        __syncthreads();
        for (int j = threadIdx.x; j < 1024; j += blockDim.x)
            if (ei[2 * j + 1] != 0) found = 1;
        __syncthreads();
        if (threadIdx.x == 0) g_idx64 = found ? 0 : 1;
    }
}

// ---------------------------------------------------------------------------
// Weight split into bf16 hi/lo, packed bf16x2 along K.
// Offsets (u32): W11 0, W12 8192, W21 40960, W22 57344.
// ---------------------------------------------------------------------------
__global__ void wsplit_kernel(const float* __restrict__ W11,
                              const float* __restrict__ W12,
                              const float* __restrict__ W21,
                              const float* __restrict__ W22) {
    int i = blockIdx.x * blockDim.x + threadIdx.x;   // < 65536
    const float* W; int Ncols, il;
    if (i < 8192)        { W = W11; Ncols = 256; il = i; }
    else if (i < 40960)  { W = W12; Ncols = 256; il = i - 8192; }
    else if (i < 57344)  { W = W21; Ncols = 128; il = i - 40960; }
    else                 { W = W22; Ncols = 128; il = i - 57344; }
    int pr = il / Ncols, n = il % Ncols;
    float f0 = W[(2 * pr) * Ncols + n];       // k even  -> low half
    float f1 = W[(2 * pr + 1) * Ncols + n];   // k odd   -> high half
    uint32_t hi = packbf(f1, f0);
    float lo0 = f0 - __uint_as_float(hi << 16);
    float lo1 = f1 - __uint_as_float(hi & 0xffff0000u);
    g_Whi[i] = hi;
    g_Wlo[i] = packbf(lo1, lo0);
}

// ---------------------------------------------------------------------------
// CSR build: histogram (4 edges/thread) -> warp-shuffle scan -> scatter
// ---------------------------------------------------------------------------
__global__ void hist_kernel(const void* __restrict__ eiv, int E) {
    int base = (blockIdx.x * blockDim.x + threadIdx.x) * 4;
    if (base >= E) return;
    int f = g_idx64;
    int cnt = min(4, E - base);
    int d[4];
    bool al = ((E & 3) == 0);
    if (f) {
        const long long* p = (const long long*)eiv;
        if (cnt == 4 && al) {
            longlong2 d01 = *(const longlong2*)(p + E + base);
            longlong2 d23 = *(const longlong2*)(p + E + base + 2);
            d[0] = (int)d01.x; d[1] = (int)d01.y; d[2] = (int)d23.x; d[3] = (int)d23.y;
        } else {
            for (int j = 0; j < cnt; j++) d[j] = (int)p[E + base + j];
        }
    } else {
        const int* p = (const int*)eiv;
        if (cnt == 4 && al) {
            int4 dv = *(const int4*)(p + E + base);
            d[0] = dv.x; d[1] = dv.y; d[2] = dv.z; d[3] = dv.w;
        } else {
            for (int j = 0; j < cnt; j++) d[j] = p[E + base + j];
        }
    }
    for (int j = 0; j < cnt; j++) atomicAdd(&g_deg[d[j]], 1);
}

__global__ void blocksum_kernel(int N) {
    __shared__ int ws[32];
    int i = blockIdx.x * 1024 + threadIdx.x;
    int lane = threadIdx.x & 31, wid = threadIdx.x >> 5;
    int v = (i < N) ? g_deg[i] : 0;
#pragma unroll
    for (int o = 16; o > 0; o >>= 1) v += __shfl_xor_sync(0xffffffffu, v, o);
    if (lane == 0) ws[wid] = v;
    __syncthreads();
    if (wid == 0) {
        int t = ws[lane];
#pragma unroll
        for (int o = 16; o > 0; o >>= 1) t += __shfl_xor_sync(0xffffffffu, t, o);
        if (lane == 0) g_blocksum[blockIdx.x] = t;
    }
}

__global__ void scan2_kernel(int N) {
    __shared__ int woff[32];
    __shared__ int boff;
    int tid = threadIdx.x, lane = tid & 31, wid = tid >> 5;
    int b = blockIdx.x;
    int i = b * 1024 + tid;
    int v = (i < N) ? g_deg[i] : 0;
    int incl = v;
#pragma unroll
    for (int o = 1; o < 32; o <<= 1) {
        int t = __shfl_up_sync(0xffffffffu, incl, o);
        if (lane >= o) incl += t;
    }
    if (lane == 31) woff[wid] = incl;
    __syncthreads();
    if (wid == 0) {
        int s = woff[lane];
        int si = s;
#pragma unroll
        for (int o = 1; o < 32; o <<= 1) {
            int t = __shfl_up_sync(0xffffffffu, si, o);
            if (lane >= o) si += t;
        }
        woff[lane] = si - s;
        int bs = (lane < b) ? g_blocksum[lane] : 0;
#pragma unroll
        for (int o = 16; o > 0; o >>= 1) bs += __shfl_xor_sync(0xffffffffu, bs, o);
        if (lane == 0) boff = bs;
    }
    __syncthreads();
    int start = boff + woff[wid] + incl - v;
    if (i < N) {
        g_rowptr[i] = start;
        g_fill[i]   = start;
    }
    if (i == N - 1) g_rowptr[N] = start + v;
}

__global__ void scatter_kernel(const void* __restrict__ eiv, int E) {
    int base = (blockIdx.x * blockDim.x + threadIdx.x) * 4;
    if (base >= E) return;
    int f = g_idx64;
    int cnt = min(4, E - base);
    int s[4], d[4];
    bool al = ((E & 3) == 0);
    if (f) {
        const long long* p = (const long long*)eiv;
        if (cnt == 4 && al) {
            longlong2 s01 = *(const longlong2*)(p + base);
            longlong2 s23 = *(const longlong2*)(p + base + 2);
            longlong2 d01 = *(const longlong2*)(p + E + base);
            longlong2 d23 = *(const longlong2*)(p + E + base + 2);
            s[0] = (int)s01.x; s[1] = (int)s01.y; s[2] = (int)s23.x; s[3] = (int)s23.y;
            d[0] = (int)d01.x; d[1] = (int)d01.y; d[2] = (int)d23.x; d[3] = (int)d23.y;
        } else {
            for (int j = 0; j < cnt; j++) { s[j] = (int)p[base + j]; d[j] = (int)p[E + base + j]; }
        }
    } else {
        const int* p = (const int*)eiv;
        if (cnt == 4 && al) {
            int4 sv = *(const int4*)(p + base);
            int4 dv = *(const int4*)(p + E + base);
            s[0] = sv.x; s[1] = sv.y; s[2] = sv.z; s[3] = sv.w;
            d[0] = dv.x; d[1] = dv.y; d[2] = dv.z; d[3] = dv.w;
        } else {
            for (int j = 0; j < cnt; j++) { s[j] = p[base + j]; d[j] = p[E + base + j]; }
        }
    }
    for (int j = 0; j < cnt; j++) {
        int pos = atomicAdd(&g_fill[d[j]], 1);
        g_eperm[pos] = make_int2(s[j], base + j);
    }
}

// ---------------------------------------------------------------------------
// agg1: warp per node, d=64, 2 cols/lane, W in registers.
// ---------------------------------------------------------------------------
__global__ void __launch_bounds__(256) agg1_kernel(
    const float* __restrict__ ea,
    const float* __restrict__ We, const float* __restrict__ be,
    const float* __restrict__ x, float* __restrict__ agg, int N)
{
    int tid = threadIdx.x, lane = tid & 31, wid = tid >> 5;
    int node = blockIdx.x * 8 + wid;
    if (node >= N) return;
    int c0 = lane * 2;
    float w0[8], w1[8];
#pragma unroll
    for (int k = 0; k < 8; k++) {
        float2 wv = *(const float2*)(We + k * 64 + c0);
        w0[k] = wv.x; w1[k] = wv.y;
    }
    float2 bv = *(const float2*)(be + c0);
    int beg = g_rowptr[node], end = g_rowptr[node + 1];
    float acc0 = 0.f, acc1 = 0.f;

    for (int i = beg; i < end; i += 2) {
        int2 pl = make_int2(0, 0);
        if (lane < 2 && i + lane < end) pl = g_eperm[i + lane];
        int s0 = __shfl_sync(0xffffffffu, pl.x, 0);
        int e0 = __shfl_sync(0xffffffffu, pl.y, 0);
        int s1 = __shfl_sync(0xffffffffu, pl.x, 1);
        int e1 = __shfl_sync(0xffffffffu, pl.y, 1);
        bool has1 = (i + 1 < end);
        int e1s = has1 ? e1 : e0, s1s = has1 ? s1 : s0;

        float4 a0 = __ldg((const float4*)(ea + (size_t)e0 * 8));
        float4 a1 = __ldg((const float4*)(ea + (size_t)e0 * 8) + 1);
        float4 b0 = __ldg((const float4*)(ea + (size_t)e1s * 8));
        float4 b1 = __ldg((const float4*)(ea + (size_t)e1s * 8) + 1);
        float2 xa = *(const float2*)(x + (size_t)s0 * 64 + c0);
        float2 xb = *(const float2*)(x + (size_t)s1s * 64 + c0);

        float aa[8] = {a0.x, a0.y, a0.z, a0.w, a1.x, a1.y, a1.z, a1.w};
        float ab[8] = {b0.x, b0.y, b0.z, b0.w, b1.x, b1.y, b1.z, b1.w};
        float ma0 = bv.x, ma1 = bv.y, mb0 = bv.x, mb1 = bv.y;
#pragma unroll
        for (int k = 0; k < 8; k++) {
            ma0 += aa[k] * w0[k]; ma1 += aa[k] * w1[k];
            mb0 += ab[k] * w0[k]; mb1 += ab[k] * w1[k];
        }
        acc0 += fmaxf(xa.x + ma0, 0.f);
        acc1 += fmaxf(xa.y + ma1, 0.f);
        if (has1) {
            acc0 += fmaxf(xb.x + mb0, 0.f);
            acc1 += fmaxf(xb.y + mb1, 0.f);
        }
    }
    *(float2*)(agg + (size_t)node * 64 + c0) = make_float2(acc0, acc1);
}

// ---------------------------------------------------------------------------
// agg2: 64 threads per node, d=256, 4 cols/lane, W in registers.
// ---------------------------------------------------------------------------
__global__ void __launch_bounds__(256) agg2_kernel(
    const float* __restrict__ ea,
    const float* __restrict__ We, const float* __restrict__ be,
    const float* __restrict__ h1, float* __restrict__ agg, int N)
{
    int tid = threadIdx.x, lane = tid & 31;
    int node = blockIdx.x * 4 + (tid >> 6);
    if (node >= N) return;
    int c0 = (tid & 63) * 4;
    float w0[8], w1[8], w2[8], w3[8];
#pragma unroll
    for (int k = 0; k < 8; k++) {
        float4 wv = *(const float4*)(We + k * 256 + c0);
        w0[k] = wv.x; w1[k] = wv.y; w2[k] = wv.z; w3[k] = wv.w;
    }
    float4 bv = *(const float4*)(be + c0);
    int beg = g_rowptr[node], end = g_rowptr[node + 1];
    float ac0 = 0.f, ac1 = 0.f, ac2 = 0.f, ac3 = 0.f;

    for (int i = beg; i < end; i += 2) {
        int2 pl = make_int2(0, 0);
        if (lane < 2 && i + lane < end) pl = g_eperm[i + lane];
        int s0 = __shfl_sync(0xffffffffu, pl.x, 0);
        int e0 = __shfl_sync(0xffffffffu, pl.y, 0);
        int s1 = __shfl_sync(0xffffffffu, pl.x, 1);
        int e1 = __shfl_sync(0xffffffffu, pl.y, 1);
        bool has1 = (i + 1 < end);
        int e1s = has1 ? e1 : e0, s1s = has1 ? s1 : s0;

        float4 a0 = __ldg((const float4*)(ea + (size_t)e0 * 8));
        float4 a1 = __ldg((const float4*)(ea + (size_t)e0 * 8) + 1);
        float4 b0 = __ldg((const float4*)(ea + (size_t)e1s * 8));
        float4 b1 = __ldg((const float4*)(ea + (size_t)e1s * 8) + 1);
        float4 ha = *(const float4*)(h1 + (size_t)s0 * 256 + c0);
        float4 hb = *(const float4*)(h1 + (size_t)s1s * 256 + c0);

        float aa[8] = {a0.x, a0.y, a0.z, a0.w, a1.x, a1.y, a1.z, a1.w};
        float ab[8] = {b0.x, b0.y, b0.z, b0.w, b1.x, b1.y, b1.z, b1.w};
        float ma0 = bv.x, ma1 = bv.y, ma2 = bv.z, ma3 = bv.w;
        float mb0 = bv.x, mb1 = bv.y, mb2 = bv.z, mb3 = bv.w;
#pragma unroll
        for (int k = 0; k < 8; k++) {
            ma0 += aa[k] * w0[k]; ma1 += aa[k] * w1[k];
            ma2 += aa[k] * w2[k]; ma3 += aa[k] * w3[k];
            mb0 += ab[k] * w0[k]; mb1 += ab[k] * w1[k];
            mb2 += ab[k] * w2[k]; mb3 += ab[k] * w3[k];
        }
        ac0 += fmaxf(ha.x + ma0, 0.f);
        ac1 += fmaxf(ha.y + ma1, 0.f);
        ac2 += fmaxf(ha.z + ma2, 0.f);
        ac3 += fmaxf(ha.w + ma3, 0.f);
        if (has1) {
            ac0 += fmaxf(hb.x + mb0, 0.f);
            ac1 += fmaxf(hb.y + mb1, 0.f);
            ac2 += fmaxf(hb.z + mb2, 0.f);
            ac3 += fmaxf(hb.w + mb3, 0.f);
        }
    }
    *(float4*)(agg + (size_t)node * 256 + c0) = make_float4(ac0, ac1, ac2, ac3);
}

// ---------------------------------------------------------------------------
// 3xBF16 tensor-core GEMM (m16n8k16), BK=32, A pre-split into smem by the
// loader, B via cp.async (pre-split in global). Fused PRE / bias / BN stats.
// PRE: 1 (1+eps)*X + X2; 2 relu(A*X+B) from layer-LIN stats. Stats -> LOUT.
// Dynamic smem (58368 B). Block 256 (8 warps: 2M x 4N), BM=64 BN=128.
// ---------------------------------------------------------------------------
#define MMA_BF16(d, a, b)                                                     \
    asm volatile(                                                             \
        "mma.sync.aligned.m16n8k16.row.col.f32.bf16.bf16.f32 "                \
        "{%0,%1,%2,%3},{%4,%5,%6,%7},{%8,%9},{%0,%1,%2,%3};"                  \
        : "+f"(d[0]), "+f"(d[1]), "+f"(d[2]), "+f"(d[3])                      \
        : "r"(a[0]), "r"(a[1]), "r"(a[2]), "r"(a[3]), "r"(b[0]), "r"(b[1]))

// u32 offsets inside dynamic smem
#define OFF_AH 0
#define OFF_AL 2560      // 2 * 64 * 20
#define OFF_BH 5120
#define OFF_BL 9472      // + 2 * 16 * 136
#define OFF_SUM 13824
#define OFF_SQ  13952
#define OFF_AF  14080
#define OFF_BF  14336
#define GEMM_SMEM_BYTES (14592 * 4)

template <int K, int NCOLS, int PRE, int LIN, int LOUT>
__global__ void __launch_bounds__(256) gemm_mma(
    const float* __restrict__ X,
    const uint32_t* __restrict__ Wh2, const uint32_t* __restrict__ Wl2,
    const float* __restrict__ bias, float* __restrict__ out,
    const float* __restrict__ X2, const float* __restrict__ eps_ptr,
    const float* __restrict__ gin, const float* __restrict__ btin,
    int N, float invN)
{
    constexpr int BM = 64, BN = 128, BK = 32;
    constexpr int KT = K / BK;
    extern __shared__ uint32_t dsm[];
    uint32_t* Ah = dsm + OFF_AH;   // [2][64][20]
    uint32_t* Al = dsm + OFF_AL;
    uint32_t* Bh = dsm + OFF_BH;   // [2][16][136]
    uint32_t* Bl = dsm + OFF_BL;
    float* ssum = (float*)(dsm + OFF_SUM);
    float* ssq  = (float*)(dsm + OFF_SQ);
    float* sAf  = (float*)(dsm + OFF_AF);
    float* sBf  = (float*)(dsm + OFF_BF);
    uint32_t smem_base = (uint32_t)__cvta_generic_to_shared(dsm);

    int tid = threadIdx.x, lane = tid & 31, wid = tid >> 5;
    int wm = wid & 1, wn = wid >> 1;
    int n0  = blockIdx.x * BM;
    int nb0 = blockIdx.y * BN;

    for (int i = tid; i < BN; i += 256) { ssum[i] = 0.f; ssq[i] = 0.f; }
    if constexpr (PRE == 2) {
        for (int j = tid; j < K; j += 256) {
            float mu = g_colsum[LIN][j] * invN;
            float var = fmaxf(g_colsq[LIN][j] * invN - mu * mu, 0.f);
            float A = gin[j] * rsqrtf(var + 1e-5f);
            sAf[j] = A;
            sBf[j] = btin[j] - A * mu;
        }
    }
    __syncthreads();

    float eps = 0.f;
    if constexpr (PRE == 1) eps = 1.0f + *eps_ptr;

    float acc[2][4][4];
#pragma unroll
    for (int mt = 0; mt < 2; mt++)
#pragma unroll
        for (int nt = 0; nt < 4; nt++)
#pragma unroll
            for (int r = 0; r < 4; r++) acc[mt][nt][r] = 0.f;

    int a_row = tid >> 2;            // 0..63
    int a_kq  = (tid & 3) * 8;       // 0,8,16,24
    auto loadA = [&](int kt, float4* av) {
        int row = n0 + a_row;
        av[0] = make_float4(0.f, 0.f, 0.f, 0.f);
        av[1] = make_float4(0.f, 0.f, 0.f, 0.f);
        if (row < N) {
            int gk = kt * BK + a_kq;
#pragma unroll
            for (int q = 0; q < 2; q++) {
                int gkq = gk + q * 4;
                float4 v = *(const float4*)(X + (size_t)row * K + gkq);
                if constexpr (PRE == 1) {
                    float4 xv = *(const float4*)(X2 + (size_t)row * K + gkq);
                    v.x = eps * v.x + xv.x; v.y = eps * v.y + xv.y;
                    v.z = eps * v.z + xv.z; v.w = eps * v.w + xv.w;
                } else if constexpr (PRE == 2) {
                    v.x = fmaxf(sAf[gkq]     * v.x + sBf[gkq],     0.f);
                    v.y = fmaxf(sAf[gkq + 1] * v.y + sBf[gkq + 1], 0.f);
                    v.z = fmaxf(sAf[gkq + 2] * v.z + sBf[gkq + 2], 0.f);
                    v.w = fmaxf(sAf[gkq + 3] * v.w + sBf[gkq + 3], 0.f);
                }
                av[q] = v;
            }
        }
    };
    // split 8 floats -> 4 hi + 4 lo bf16x2, store as two STS.128
    auto storeA = [&](int s, const float4* av) {
        uint32_t h[4], l[4];
#pragma unroll
        for (int q = 0; q < 2; q++) {
            uint32_t h0 = packbf(av[q].y, av[q].x);
            uint32_t h1 = packbf(av[q].w, av[q].z);
            h[q * 2]     = h0;
            h[q * 2 + 1] = h1;
            l[q * 2]     = packbf(av[q].y - __uint_as_float(h0 & 0xffff0000u),
                                  av[q].x - __uint_as_float(h0 << 16));
            l[q * 2 + 1] = packbf(av[q].w - __uint_as_float(h1 & 0xffff0000u),
                                  av[q].z - __uint_as_float(h1 << 16));
        }
        int idx = s * 1280 + a_row * 20 + (tid & 3) * 4;
        *(uint4*)&Ah[idx] = make_uint4(h[0], h[1], h[2], h[3]);
        *(uint4*)&Al[idx] = make_uint4(l[0], l[1], l[2], l[3]);
    };
    // B tile via cp.async: 16 pair-rows x 128 u32, per thread 2x16B each part
    int b_row = tid >> 4, b_c = (tid & 15) * 8;
    auto loadBasync = [&](int kt, int s) {
        size_t goff = (size_t)(kt * 16 + b_row) * NCOLS + nb0 + b_c;
        uint32_t sh = smem_base + (OFF_BH + s * 2176 + b_row * 136 + b_c) * 4;
        uint32_t sl = smem_base + (OFF_BL + s * 2176 + b_row * 136 + b_c) * 4;
        cp16(sh,      Wh2 + goff);
        cp16(sh + 16, Wh2 + goff + 4);
        cp16(sl,      Wl2 + goff);
        cp16(sl + 16, Wl2 + goff + 4);
        cp_commit();
    };

    {
        float4 av[2];
        loadBasync(0, 0);
        loadA(0, av);
        storeA(0, av);
        cp_wait0();
        __syncthreads();
    }

    int tg = lane & 3, mrow = lane >> 2;

    for (int kt = 0; kt < KT; kt++) {
        int s = kt & 1;
        float4 nav[2];
        if (kt + 1 < KT) { loadBasync(kt + 1, s ^ 1); loadA(kt + 1, nav); }

#pragma unroll
        for (int ks = 0; ks < 2; ks++) {
            int k2 = ks * 8 + tg;
            uint32_t ahi[2][4], alo[2][4];
#pragma unroll
            for (int mt = 0; mt < 2; mt++) {
                int m = wm * 32 + mt * 16 + mrow;
                int i0 = s * 1280 + m * 20;
                ahi[mt][0] = Ah[i0 + k2];
                ahi[mt][1] = Ah[i0 + 160 + k2];        // m+8
                ahi[mt][2] = Ah[i0 + k2 + 4];
                ahi[mt][3] = Ah[i0 + 160 + k2 + 4];
                alo[mt][0] = Al[i0 + k2];
                alo[mt][1] = Al[i0 + 160 + k2];
                alo[mt][2] = Al[i0 + k2 + 4];
                alo[mt][3] = Al[i0 + 160 + k2 + 4];
            }
            uint32_t bhi[4][2], blo[4][2];
#pragma unroll
            for (int nt = 0; nt < 4; nt++) {
                int n = wn * 32 + nt * 8 + mrow;
                int i0 = s * 2176 + k2 * 136 + n;
                bhi[nt][0] = Bh[i0];
                bhi[nt][1] = Bh[i0 + 4 * 136];
                blo[nt][0] = Bl[i0];
                blo[nt][1] = Bl[i0 + 4 * 136];
            }
#pragma unroll
            for (int mt = 0; mt < 2; mt++)
#pragma unroll
                for (int nt = 0; nt < 4; nt++) {
                    MMA_BF16(acc[mt][nt], ahi[mt], bhi[nt]);
                    MMA_BF16(acc[mt][nt], alo[mt], bhi[nt]);
                    MMA_BF16(acc[mt][nt], ahi[mt], blo[nt]);
                }
        }
        if (kt + 1 < KT) {
            cp_wait0();
            __syncthreads();
            storeA(s ^ 1, nav);
            __syncthreads();
        }
    }

    // epilogue: bias, store, BN stats
#pragma unroll
    for (int nt = 0; nt < 4; nt++) {
        int cb = wn * 32 + nt * 8 + 2 * (lane & 3);
        float b0 = bias[nb0 + cb], b1 = bias[nb0 + cb + 1];
        float s0 = 0.f, s1 = 0.f, q0 = 0.f, q1 = 0.f;
#pragma unroll
        for (int mt = 0; mt < 2; mt++) {
            int row0 = n0 + wm * 32 + mt * 16 + (lane >> 2);
            float v0 = acc[mt][nt][0] + b0, v1 = acc[mt][nt][1] + b1;
            float v2 = acc[mt][nt][2] + b0, v3 = acc[mt][nt][3] + b1;
            if (row0 < N) {
                *(float2*)(out + (size_t)row0 * NCOLS + nb0 + cb) = make_float2(v0, v1);
                s0 += v0; s1 += v1; q0 += v0 * v0; q1 += v1 * v1;
            }
            if (row0 + 8 < N) {
                *(float2*)(out + (size_t)(row0 + 8) * NCOLS + nb0 + cb) = make_float2(v2, v3);
                s0 += v2; s1 += v3; q0 += v2 * v2; q1 += v3 * v3;
            }
        }
#pragma unroll
        for (int off = 4; off < 32; off <<= 1) {
            s0 += __shfl_xor_sync(0xffffffffu, s0, off);
            s1 += __shfl_xor_sync(0xffffffffu, s1, off);
            q0 += __shfl_xor_sync(0xffffffffu, q0, off);
            q1 += __shfl_xor_sync(0xffffffffu, q1, off);
        }
        if (lane < 4) {
            atomicAdd(&ssum[cb], s0); atomicAdd(&ssum[cb + 1], s1);
            atomicAdd(&ssq[cb],  q0); atomicAdd(&ssq[cb + 1],  q1);
        }
    }
    __syncthreads();
    for (int i = tid; i < BN; i += 256) {
        atomicAdd(&g_colsum[LOUT][nb0 + i], ssum[i]);
        atomicAdd(&g_colsq[LOUT][nb0 + i],  ssq[i]);
    }
}

// ---------------------------------------------------------------------------
// h = relu(bn(in)) with inline affine from layer-1 stats (256 cols)
// ---------------------------------------------------------------------------
__global__ void bnrelu_kernel(const float4* __restrict__ in,
                              float4* __restrict__ outp, int n4,
                              const float* __restrict__ g,
                              const float* __restrict__ bt, float invN)
{
    __shared__ float sA[256], sB[256];
    int tid = threadIdx.x;
    {
        float mu = g_colsum[1][tid] * invN;
        float var = fmaxf(g_colsq[1][tid] * invN - mu * mu, 0.f);
        float A = g[tid] * rsqrtf(var + 1e-5f);
        sA[tid] = A;
        sB[tid] = bt[tid] - A * mu;
    }
    __syncthreads();
    int i = blockIdx.x * 256 + tid;
    if (i >= n4) return;
    int c0 = (i & 63) * 4;
    float4 v = in[i];
    v.x = fmaxf(sA[c0]     * v.x + sB[c0],     0.f);
    v.y = fmaxf(sA[c0 + 1] * v.y + sB[c0 + 1], 0.f);
    v.z = fmaxf(sA[c0 + 2] * v.z + sB[c0 + 2], 0.f);
    v.w = fmaxf(sA[c0 + 3] * v.w + sB[c0 + 3], 0.f);
    outp[i] = v;
}

// ---------------------------------------------------------------------------
// Output head: out[n] = sum_j relu(bn3(t[n,j])) * Wout[j] + bout
// ---------------------------------------------------------------------------
__global__ void __launch_bounds__(256) out_kernel(
    const float* __restrict__ T, const float* __restrict__ Wout,
    const float* __restrict__ bout, float* __restrict__ out, int N,
    const float* __restrict__ g, const float* __restrict__ bt, float invN)
{
    __shared__ float sA[128], sB[128];
    int tid = threadIdx.x;
    if (tid < 128) {
        float mu = g_colsum[3][tid] * invN;
        float var = fmaxf(g_colsq[3][tid] * invN - mu * mu, 0.f);
        float A = g[tid] * rsqrtf(var + 1e-5f);
        sA[tid] = A;
        sB[tid] = bt[tid] - A * mu;
    }
    __syncthreads();
    int wid = tid >> 5, lane = tid & 31;
    int n = blockIdx.x * 8 + wid;
    if (n >= N) return;
    float4 t = ((const float4*)(T + (size_t)n * 128))[lane];
    float4 w = ((const float4*)Wout)[lane];
    int c = lane * 4;
    float s = fmaxf(sA[c]     * t.x + sB[c],     0.f) * w.x
            + fmaxf(sA[c + 1] * t.y + sB[c + 1], 0.f) * w.y
            + fmaxf(sA[c + 2] * t.z + sB[c + 2], 0.f) * w.z
            + fmaxf(sA[c + 3] * t.w + sB[c + 3], 0.f) * w.w;
#pragma unroll
    for (int o = 16; o > 0; o >>= 1)
        s += __shfl_xor_sync(0xffffffffu, s, o);
    if (lane == 0) out[n] = s + bout[0];
}

// ---------------------------------------------------------------------------
extern "C" void kernel_launch(void* const* d_in, const int* in_sizes, int n_in,
                              void* d_out, int out_size)
{
    const float* x    = (const float*)d_in[0];
    const void*  ei   = d_in[1];
    const float* ea   = (const float*)d_in[2];
    const float* eps1 = (const float*)d_in[3];
    const float* We1  = (const float*)d_in[4];
    const float* be1  = (const float*)d_in[5];
    const float* W11  = (const float*)d_in[6];
    const float* b11  = (const float*)d_in[7];
    const float* g11  = (const float*)d_in[8];
    const float* bt11 = (const float*)d_in[9];
    const float* W12  = (const float*)d_in[10];
    const float* b12  = (const float*)d_in[11];
    const float* g1   = (const float*)d_in[12];
    const float* bt1  = (const float*)d_in[13];
    const float* eps2 = (const float*)d_in[14];
    const float* We2  = (const float*)d_in[15];
    const float* be2  = (const float*)d_in[16];
    const float* W21  = (const float*)d_in[17];
    const float* b21  = (const float*)d_in[18];
    const float* g21  = (const float*)d_in[19];
    const float* bt21 = (const float*)d_in[20];
    const float* W22  = (const float*)d_in[21];
    const float* b22  = (const float*)d_in[22];
    const float* g2   = (const float*)d_in[23];
    const float* bt2  = (const float*)d_in[24];
    const float* Wout = (const float*)d_in[25];
    const float* bout = (const float*)d_in[26];

    int N = in_sizes[0] / 64;   // 25000
    int E = in_sizes[2] / 8;    // 400000
    float invN = 1.0f / (float)N;

    float *agg1, *agg2, *bufA, *bufB;
    uint32_t *whi, *wlo;
    cudaGetSymbolAddress((void**)&agg1, g_agg1);
    cudaGetSymbolAddress((void**)&agg2, g_agg2);
    cudaGetSymbolAddress((void**)&bufA, g_bufA);
    cudaGetSymbolAddress((void**)&bufB, g_bufB);
    cudaGetSymbolAddress((void**)&whi, g_Whi);
    cudaGetSymbolAddress((void**)&wlo, g_Wlo);

    static int attr_done = 0;
    if (!attr_done) {
        cudaFuncSetAttribute(gemm_mma<64, 256, 1, 0, 0>,
                             cudaFuncAttributeMaxDynamicSharedMemorySize, GEMM_SMEM_BYTES);
        cudaFuncSetAttribute(gemm_mma<256, 256, 2, 0, 1>,
                             cudaFuncAttributeMaxDynamicSharedMemorySize, GEMM_SMEM_BYTES);
        cudaFuncSetAttribute(gemm_mma<256, 128, 1, 0, 2>,
                             cudaFuncAttributeMaxDynamicSharedMemorySize, GEMM_SMEM_BYTES);
        cudaFuncSetAttribute(gemm_mma<128, 128, 2, 2, 3>,
                             cudaFuncAttributeMaxDynamicSharedMemorySize, GEMM_SMEM_BYTES);
        attr_done = 1;
    }

    int NB = (N + 1023) / 1024;
    int EB = (E + 1023) / 1024;
    int gx = (N + 63) / 64;

    // --- setup + CSR build ---
    setup_kernel<<<(N + 255) / 256, 256>>>((const int*)ei, N);
    hist_kernel<<<EB, 256>>>(ei, E);
    wsplit_kernel<<<256, 256>>>(W11, W12, W21, W22);
    blocksum_kernel<<<NB, 1024>>>(N);
    scan2_kernel<<<NB, 1024>>>(N);
    scatter_kernel<<<EB, 256>>>(ei, E);

    // --- conv1 ---
    agg1_kernel<<<(N + 7) / 8, 256>>>(ea, We1, be1, x, agg1, N);
    gemm_mma<64, 256, 1, 0, 0><<<dim3(gx, 2), 256, GEMM_SMEM_BYTES>>>(
        x, whi, wlo, b11, bufA, agg1, eps1, nullptr, nullptr, N, invN);
    gemm_mma<256, 256, 2, 0, 1><<<dim3(gx, 2), 256, GEMM_SMEM_BYTES>>>(
        bufA, whi + 8192, wlo + 8192, b12, bufB, nullptr, nullptr, g11, bt11, N, invN);
    bnrelu_kernel<<<(N * 64 + 255) / 256, 256>>>(
        (const float4*)bufB, (float4*)bufA, N * 64, g1, bt1, invN);

    // --- conv2 ---
    agg2_kernel<<<(N + 3) / 4, 256>>>(ea, We2, be2, bufA, agg2, N);
    gemm_mma<256, 128, 1, 0, 2><<<dim3(gx, 1), 256, GEMM_SMEM_BYTES>>>(
        bufA, whi + 40960, wlo + 40960, b21, bufB, agg2, eps2, nullptr, nullptr, N, invN);
    gemm_mma<128, 128, 2, 2, 3><<<dim3(gx, 1), 256, GEMM_SMEM_BYTES>>>(
        bufB, whi + 57344, wlo + 57344, b22, bufA, nullptr, nullptr, g21, bt21, N, invN);

    // --- head ---
    out_kernel<<<(N + 7) / 8, 256>>>(bufA, Wout, bout, (float*)d_out, N, g2, bt2, invN);
}

// round 8
// speedup vs baseline: 2.3761x; 1.0263x over previous
#include <cuda_runtime.h>
#include <stdint.h>

// ---------------------------------------------------------------------------
// GINE 2-layer GNN, N=25000, E=400000, 64 -> 256 -> 256 -> 128 -> 128 -> 1
// R8: R6 architecture (3xBF16 mma.sync GEMM) with ldmatrix fragment loads —
// A and B tiles stored k-major [row][20-u32-pad], every fragment one
// conflict-free LDSM.x4. B weight image pre-split+pre-tiled in global.
// ---------------------------------------------------------------------------
#define MAXN 25000
#define MAXE 400000

__device__ float g_bufA[MAXN * 256];
__device__ float g_bufB[MAXN * 256];
__device__ float g_agg1[MAXN * 64];
__device__ float g_agg2[MAXN * 256];
__device__ float g_colsum[4][256];
__device__ float g_colsq[4][256];
__device__ int   g_idx64;
__device__ int   g_deg[MAXN];
__device__ int   g_rowptr[MAXN + 1];
__device__ int   g_fill[MAXN];
__device__ int   g_blocksum[32];
__device__ int2  g_eperm[MAXE];
// k-major bf16x2 weight tiles, [nb][kc] order, each tile 128 rows x 16 u32
// (= 2048 u32). Bases (u32): W11 0, W12 8192, W21 40960, W22 57344.
__device__ uint32_t g_Bhi[65536];
__device__ uint32_t g_Blo[65536];

__device__ __forceinline__ uint32_t packbf(float fhi, float flo) {
    uint32_t r;
    asm("cvt.rn.bf16x2.f32 %0, %1, %2;" : "=r"(r) : "f"(fhi), "f"(flo));
    return r;
}
__device__ __forceinline__ void cp16(uint32_t saddr, const void* g) {
    asm volatile("cp.async.cg.shared.global [%0], [%1], 16;" :: "r"(saddr), "l"(g));
}
__device__ __forceinline__ void cp_commit() {
    asm volatile("cp.async.commit_group;" ::: "memory");
}
__device__ __forceinline__ void cp_wait0() {
    asm volatile("cp.async.wait_group 0;" ::: "memory");
}
__device__ __forceinline__ void ldsm4(uint32_t& r0, uint32_t& r1,
                                      uint32_t& r2, uint32_t& r3, uint32_t a) {
    asm volatile("ldmatrix.sync.aligned.m8n8.x4.shared.b16 {%0,%1,%2,%3}, [%4];"
                 : "=r"(r0), "=r"(r1), "=r"(r2), "=r"(r3) : "r"(a));
}

// ---------------------------------------------------------------------------
// setup: zero degrees + zero BN stats + detect edge_index dtype (block 0)
// ---------------------------------------------------------------------------
__global__ void setup_kernel(const int* __restrict__ ei, int N) {
    int i = blockIdx.x * blockDim.x + threadIdx.x;
    if (i < N) g_deg[i] = 0;
    if (i < 1024) {
        ((float*)g_colsum)[i] = 0.f;
        ((float*)g_colsq)[i]  = 0.f;
    }
    if (blockIdx.x == 0) {
        __shared__ int found;
        if (threadIdx.x == 0) found = 0;
        __syncthreads();
        for (int j = threadIdx.x; j < 1024; j += blockDim.x)
            if (ei[2 * j + 1] != 0) found = 1;
        __syncthreads();
        if (threadIdx.x == 0) g_idx64 = found ? 0 : 1;
    }
}

// ---------------------------------------------------------------------------
// wsplit: W[K][N] fp32 -> bf16 hi/lo bf16x2 (packed along K), k-major tiles:
// tile (nb, kc32) = [128 n-rows][16 u32], tile idx = nb*KTILES + kc.
// ---------------------------------------------------------------------------
__global__ void wsplit_kernel(const float* __restrict__ W11,
                              const float* __restrict__ W12,
                              const float* __restrict__ W21,
                              const float* __restrict__ W22) {
    int i = blockIdx.x * blockDim.x + threadIdx.x;   // < 65536
    const float* W; int Ncols, il, ktiles, base;
    if (i < 8192)        { W = W11; Ncols = 256; il = i;         ktiles = 2; base = 0; }
    else if (i < 40960)  { W = W12; Ncols = 256; il = i - 8192;  ktiles = 8; base = 8192; }
    else if (i < 57344)  { W = W21; Ncols = 128; il = i - 40960; ktiles = 8; base = 40960; }
    else                 { W = W22; Ncols = 128; il = i - 57344; ktiles = 4; base = 57344; }
    int tile = il >> 11, t = il & 2047;
    int nb = tile / ktiles, kc = tile % ktiles;
    int nloc = t >> 4, j = t & 15;
    int n = nb * 128 + nloc;
    int k = kc * 32 + j * 2;
    float f0 = W[(size_t)k * Ncols + n];
    float f1 = W[(size_t)(k + 1) * Ncols + n];
    uint32_t hi = packbf(f1, f0);
    float l0 = f0 - __uint_as_float(hi << 16);
    float l1 = f1 - __uint_as_float(hi & 0xffff0000u);
    g_Bhi[i] = hi;
    g_Blo[i] = packbf(l1, l0);
}

// ---------------------------------------------------------------------------
// CSR build: histogram (4 edges/thread) -> warp-shuffle scan -> scatter
// ---------------------------------------------------------------------------
__global__ void hist_kernel(const void* __restrict__ eiv, int E) {
    int base = (blockIdx.x * blockDim.x + threadIdx.x) * 4;
    if (base >= E) return;
    int f = g_idx64;
    int cnt = min(4, E - base);
    int d[4];
    bool al = ((E & 3) == 0);
    if (f) {
        const long long* p = (const long long*)eiv;
        if (cnt == 4 && al) {
            longlong2 d01 = *(const longlong2*)(p + E + base);
            longlong2 d23 = *(const longlong2*)(p + E + base + 2);
            d[0] = (int)d01.x; d[1] = (int)d01.y; d[2] = (int)d23.x; d[3] = (int)d23.y;
        } else {
            for (int j = 0; j < cnt; j++) d[j] = (int)p[E + base + j];
        }
    } else {
        const int* p = (const int*)eiv;
        if (cnt == 4 && al) {
            int4 dv = *(const int4*)(p + E + base);
            d[0] = dv.x; d[1] = dv.y; d[2] = dv.z; d[3] = dv.w;
        } else {
            for (int j = 0; j < cnt; j++) d[j] = p[E + base + j];
        }
    }
    for (int j = 0; j < cnt; j++) atomicAdd(&g_deg[d[j]], 1);
}

__global__ void blocksum_kernel(int N) {
    __shared__ int ws[32];
    int i = blockIdx.x * 1024 + threadIdx.x;
    int lane = threadIdx.x & 31, wid = threadIdx.x >> 5;
    int v = (i < N) ? g_deg[i] : 0;
#pragma unroll
    for (int o = 16; o > 0; o >>= 1) v += __shfl_xor_sync(0xffffffffu, v, o);
    if (lane == 0) ws[wid] = v;
    __syncthreads();
    if (wid == 0) {
        int t = ws[lane];
#pragma unroll
        for (int o = 16; o > 0; o >>= 1) t += __shfl_xor_sync(0xffffffffu, t, o);
        if (lane == 0) g_blocksum[blockIdx.x] = t;
    }
}

__global__ void scan2_kernel(int N) {
    __shared__ int woff[32];
    __shared__ int boff;
    int tid = threadIdx.x, lane = tid & 31, wid = tid >> 5;
    int b = blockIdx.x;
    int i = b * 1024 + tid;
    int v = (i < N) ? g_deg[i] : 0;
    int incl = v;
#pragma unroll
    for (int o = 1; o < 32; o <<= 1) {
        int t = __shfl_up_sync(0xffffffffu, incl, o);
        if (lane >= o) incl += t;
    }
    if (lane == 31) woff[wid] = incl;
    __syncthreads();
    if (wid == 0) {
        int s = woff[lane];
        int si = s;
#pragma unroll
        for (int o = 1; o < 32; o <<= 1) {
            int t = __shfl_up_sync(0xffffffffu, si, o);
            if (lane >= o) si += t;
        }
        woff[lane] = si - s;
        int bs = (lane < b) ? g_blocksum[lane] : 0;
#pragma unroll
        for (int o = 16; o > 0; o >>= 1) bs += __shfl_xor_sync(0xffffffffu, bs, o);
        if (lane == 0) boff = bs;
    }
    __syncthreads();
    int start = boff + woff[wid] + incl - v;
    if (i < N) {
        g_rowptr[i] = start;
        g_fill[i]   = start;
    }
    if (i == N - 1) g_rowptr[N] = start + v;
}

__global__ void scatter_kernel(const void* __restrict__ eiv, int E) {
    int base = (blockIdx.x * blockDim.x + threadIdx.x) * 4;
    if (base >= E) return;
    int f = g_idx64;
    int cnt = min(4, E - base);
    int s[4], d[4];
    bool al = ((E & 3) == 0);
    if (f) {
        const long long* p = (const long long*)eiv;
        if (cnt == 4 && al) {
            longlong2 s01 = *(const longlong2*)(p + base);
            longlong2 s23 = *(const longlong2*)(p + base + 2);
            longlong2 d01 = *(const longlong2*)(p + E + base);
            longlong2 d23 = *(const longlong2*)(p + E + base + 2);
            s[0] = (int)s01.x; s[1] = (int)s01.y; s[2] = (int)s23.x; s[3] = (int)s23.y;
            d[0] = (int)d01.x; d[1] = (int)d01.y; d[2] = (int)d23.x; d[3] = (int)d23.y;
        } else {
            for (int j = 0; j < cnt; j++) { s[j] = (int)p[base + j]; d[j] = (int)p[E + base + j]; }
        }
    } else {
        const int* p = (const int*)eiv;
        if (cnt == 4 && al) {
            int4 sv = *(const int4*)(p + base);
            int4 dv = *(const int4*)(p + E + base);
            s[0] = sv.x; s[1] = sv.y; s[2] = sv.z; s[3] = sv.w;
            d[0] = dv.x; d[1] = dv.y; d[2] = dv.z; d[3] = dv.w;
        } else {
            for (int j = 0; j < cnt; j++) { s[j] = p[base + j]; d[j] = p[E + base + j]; }
        }
    }
    for (int j = 0; j < cnt; j++) {
        int pos = atomicAdd(&g_fill[d[j]], 1);
        g_eperm[pos] = make_int2(s[j], base + j);
    }
}

// ---------------------------------------------------------------------------
// agg1: warp per node, d=64, 2 cols/lane, W in registers.
// ---------------------------------------------------------------------------
__global__ void __launch_bounds__(256) agg1_kernel(
    const float* __restrict__ ea,
    const float* __restrict__ We, const float* __restrict__ be,
    const float* __restrict__ x, float* __restrict__ agg, int N)
{
    int tid = threadIdx.x, lane = tid & 31, wid = tid >> 5;
    int node = blockIdx.x * 8 + wid;
    if (node >= N) return;
    int c0 = lane * 2;
    float w0[8], w1[8];
#pragma unroll
    for (int k = 0; k < 8; k++) {
        float2 wv = *(const float2*)(We + k * 64 + c0);
        w0[k] = wv.x; w1[k] = wv.y;
    }
    float2 bv = *(const float2*)(be + c0);
    int beg = g_rowptr[node], end = g_rowptr[node + 1];
    float acc0 = 0.f, acc1 = 0.f;

    for (int i = beg; i < end; i += 2) {
        int2 pl = make_int2(0, 0);
        if (lane < 2 && i + lane < end) pl = g_eperm[i + lane];
        int s0 = __shfl_sync(0xffffffffu, pl.x, 0);
        int e0 = __shfl_sync(0xffffffffu, pl.y, 0);
        int s1 = __shfl_sync(0xffffffffu, pl.x, 1);
        int e1 = __shfl_sync(0xffffffffu, pl.y, 1);
        bool has1 = (i + 1 < end);
        int e1s = has1 ? e1 : e0, s1s = has1 ? s1 : s0;

        float4 a0 = __ldg((const float4*)(ea + (size_t)e0 * 8));
        float4 a1 = __ldg((const float4*)(ea + (size_t)e0 * 8) + 1);
        float4 b0 = __ldg((const float4*)(ea + (size_t)e1s * 8));
        float4 b1 = __ldg((const float4*)(ea + (size_t)e1s * 8) + 1);
        float2 xa = *(const float2*)(x + (size_t)s0 * 64 + c0);
        float2 xb = *(const float2*)(x + (size_t)s1s * 64 + c0);

        float aa[8] = {a0.x, a0.y, a0.z, a0.w, a1.x, a1.y, a1.z, a1.w};
        float ab[8] = {b0.x, b0.y, b0.z, b0.w, b1.x, b1.y, b1.z, b1.w};
        float ma0 = bv.x, ma1 = bv.y, mb0 = bv.x, mb1 = bv.y;
#pragma unroll
        for (int k = 0; k < 8; k++) {
            ma0 += aa[k] * w0[k]; ma1 += aa[k] * w1[k];
            mb0 += ab[k] * w0[k]; mb1 += ab[k] * w1[k];
        }
        acc0 += fmaxf(xa.x + ma0, 0.f);
        acc1 += fmaxf(xa.y + ma1, 0.f);
        if (has1) {
            acc0 += fmaxf(xb.x + mb0, 0.f);
            acc1 += fmaxf(xb.y + mb1, 0.f);
        }
    }
    *(float2*)(agg + (size_t)node * 64 + c0) = make_float2(acc0, acc1);
}

// ---------------------------------------------------------------------------
// agg2: 64 threads per node, d=256, 4 cols/lane, W in registers.
// ---------------------------------------------------------------------------
__global__ void __launch_bounds__(256) agg2_kernel(
    const float* __restrict__ ea,
    const float* __restrict__ We, const float* __restrict__ be,
    const float* __restrict__ h1, float* __restrict__ agg, int N)
{
    int tid = threadIdx.x, lane = tid & 31;
    int node = blockIdx.x * 4 + (tid >> 6);
    if (node >= N) return;
    int c0 = (tid & 63) * 4;
    float w0[8], w1[8], w2[8], w3[8];
#pragma unroll
    for (int k = 0; k < 8; k++) {
        float4 wv = *(const float4*)(We + k * 256 + c0);
        w0[k] = wv.x; w1[k] = wv.y; w2[k] = wv.z; w3[k] = wv.w;
    }
    float4 bv = *(const float4*)(be + c0);
    int beg = g_rowptr[node], end = g_rowptr[node + 1];
    float ac0 = 0.f, ac1 = 0.f, ac2 = 0.f, ac3 = 0.f;

    for (int i = beg; i < end; i += 2) {
        int2 pl = make_int2(0, 0);
        if (lane < 2 && i + lane < end) pl = g_eperm[i + lane];
        int s0 = __shfl_sync(0xffffffffu, pl.x, 0);
        int e0 = __shfl_sync(0xffffffffu, pl.y, 0);
        int s1 = __shfl_sync(0xffffffffu, pl.x, 1);
        int e1 = __shfl_sync(0xffffffffu, pl.y, 1);
        bool has1 = (i + 1 < end);
        int e1s = has1 ? e1 : e0, s1s = has1 ? s1 : s0;

        float4 a0 = __ldg((const float4*)(ea + (size_t)e0 * 8));
        float4 a1 = __ldg((const float4*)(ea + (size_t)e0 * 8) + 1);
        float4 b0 = __ldg((const float4*)(ea + (size_t)e1s * 8));
        float4 b1 = __ldg((const float4*)(ea + (size_t)e1s * 8) + 1);
        float4 ha = *(const float4*)(h1 + (size_t)s0 * 256 + c0);
        float4 hb = *(const float4*)(h1 + (size_t)s1s * 256 + c0);

        float aa[8] = {a0.x, a0.y, a0.z, a0.w, a1.x, a1.y, a1.z, a1.w};
        float ab[8] = {b0.x, b0.y, b0.z, b0.w, b1.x, b1.y, b1.z, b1.w};
        float ma0 = bv.x, ma1 = bv.y, ma2 = bv.z, ma3 = bv.w;
        float mb0 = bv.x, mb1 = bv.y, mb2 = bv.z, mb3 = bv.w;
#pragma unroll
        for (int k = 0; k < 8; k++) {
            ma0 += aa[k] * w0[k]; ma1 += aa[k] * w1[k];
            ma2 += aa[k] * w2[k]; ma3 += aa[k] * w3[k];
            mb0 += ab[k] * w0[k]; mb1 += ab[k] * w1[k];
            mb2 += ab[k] * w2[k]; mb3 += ab[k] * w3[k];
        }
        ac0 += fmaxf(ha.x + ma0, 0.f);
        ac1 += fmaxf(ha.y + ma1, 0.f);
        ac2 += fmaxf(ha.z + ma2, 0.f);
        ac3 += fmaxf(ha.w + ma3, 0.f);
        if (has1) {
            ac0 += fmaxf(hb.x + mb0, 0.f);
            ac1 += fmaxf(hb.y + mb1, 0.f);
            ac2 += fmaxf(hb.z + mb2, 0.f);
            ac3 += fmaxf(hb.w + mb3, 0.f);
        }
    }
    *(float4*)(agg + (size_t)node * 256 + c0) = make_float4(ac0, ac1, ac2, ac3);
}

// ---------------------------------------------------------------------------
// 3xBF16 GEMM (m16n8k16) with ldmatrix fragment loads.
// out[N,NCOLS] = PRE(X)[N,K] @ W[K,NCOLS] + bias, fused BN-stat epilogue.
// Block 256 (8 warps: 2M x 4N), BM=64 BN=128 BK=32, warp tile 32x32.
// A smem: [64][20 u32] k-major (hi, lo). B smem: [128][20 u32] k-major.
// PRE: 1 (1+eps)*X + X2; 2 relu(A*X+B) from layer-LIN stats. Stats -> LOUT.
// ---------------------------------------------------------------------------
#define MMA_BF16(d, a, b)                                                     \
    asm volatile(                                                             \
        "mma.sync.aligned.m16n8k16.row.col.f32.bf16.bf16.f32 "                \
        "{%0,%1,%2,%3},{%4,%5,%6,%7},{%8,%9},{%0,%1,%2,%3};"                  \
        : "+f"(d[0]), "+f"(d[1]), "+f"(d[2]), "+f"(d[3])                      \
        : "r"(a[0]), "r"(a[1]), "r"(a[2]), "r"(a[3]), "r"(b[0]), "r"(b[1]))

// dynamic smem u32 offsets
#define GA(s)   ((s) * 2560)            // A hi; lo at +1280
#define GB(s)   (5120 + (s) * 5120)     // B hi; lo at +2560
#define GSUM    15360
#define GSQ     15488
#define GAF     15616
#define GBF     15872
#define GEMM_SMEM_BYTES (16128 * 4)

template <int K, int NCOLS, int PRE, int LIN, int LOUT>
__global__ void __launch_bounds__(256) gemm_mma(
    const float* __restrict__ X,
    const uint32_t* __restrict__ WBhi, const uint32_t* __restrict__ WBlo,
    const float* __restrict__ bias, float* __restrict__ out,
    const float* __restrict__ X2, const float* __restrict__ eps_ptr,
    const float* __restrict__ gin, const float* __restrict__ btin,
    int N, float invN)
{
    constexpr int BM = 64, BN = 128, BK = 32;
    constexpr int KT = K / BK;
    constexpr int KTILES = K / 32;
    extern __shared__ uint32_t dsm[];
    float* ssum = (float*)(dsm + GSUM);
    float* ssq  = (float*)(dsm + GSQ);
    float* sAf  = (float*)(dsm + GAF);
    float* sBf  = (float*)(dsm + GBF);
    uint32_t sbase = (uint32_t)__cvta_generic_to_shared(dsm);

    int tid = threadIdx.x, lane = tid & 31, wid = tid >> 5;
    int wm = wid & 1, wn = wid >> 1;
    int n0  = blockIdx.x * BM;
    int nb0 = blockIdx.y * BN;

    for (int i = tid; i < BN; i += 256) { ssum[i] = 0.f; ssq[i] = 0.f; }
    if constexpr (PRE == 2) {
        for (int j = tid; j < K; j += 256) {
            float mu = g_colsum[LIN][j] * invN;
            float var = fmaxf(g_colsq[LIN][j] * invN - mu * mu, 0.f);
            float A = gin[j] * rsqrtf(var + 1e-5f);
            sAf[j] = A;
            sBf[j] = btin[j] - A * mu;
        }
    }
    __syncthreads();

    float eps = 0.f;
    if constexpr (PRE == 1) eps = 1.0f + *eps_ptr;

    float acc[2][4][4];
#pragma unroll
    for (int mt = 0; mt < 2; mt++)
#pragma unroll
        for (int nt = 0; nt < 4; nt++)
#pragma unroll
            for (int r = 0; r < 4; r++) acc[mt][nt][r] = 0.f;

    int a_row = tid >> 2;            // 0..63
    int a_q   = tid & 3;             // k-eighth: 8 floats at k = a_q*8
    auto loadA = [&](int kt, float4* av) {
        int row = n0 + a_row;
        av[0] = make_float4(0.f, 0.f, 0.f, 0.f);
        av[1] = make_float4(0.f, 0.f, 0.f, 0.f);
        if (row < N) {
            int gk = kt * BK + a_q * 8;
#pragma unroll
            for (int q = 0; q < 2; q++) {
                int gkq = gk + q * 4;
                float4 v = *(const float4*)(X + (size_t)row * K + gkq);
                if constexpr (PRE == 1) {
                    float4 xv = *(const float4*)(X2 + (size_t)row * K + gkq);
                    v.x = eps * v.x + xv.x; v.y = eps * v.y + xv.y;
                    v.z = eps * v.z + xv.z; v.w = eps * v.w + xv.w;
                } else if constexpr (PRE == 2) {
                    v.x = fmaxf(sAf[gkq]     * v.x + sBf[gkq],     0.f);
                    v.y = fmaxf(sAf[gkq + 1] * v.y + sBf[gkq + 1], 0.f);
                    v.z = fmaxf(sAf[gkq + 2] * v.z + sBf[gkq + 2], 0.f);
                    v.w = fmaxf(sAf[gkq + 3] * v.w + sBf[gkq + 3], 0.f);
                }
                av[q] = v;
            }
        }
    };
    auto storeA = [&](int s, const float4* av) {
        uint32_t h[4], l[4];
#pragma unroll
        for (int q = 0; q < 2; q++) {
            uint32_t h0 = packbf(av[q].y, av[q].x);
            uint32_t h1 = packbf(av[q].w, av[q].z);
            h[q * 2]     = h0;
            h[q * 2 + 1] = h1;
            l[q * 2]     = packbf(av[q].y - __uint_as_float(h0 & 0xffff0000u),
                                  av[q].x - __uint_as_float(h0 << 16));
            l[q * 2 + 1] = packbf(av[q].w - __uint_as_float(h1 & 0xffff0000u),
                                  av[q].z - __uint_as_float(h1 << 16));
        }
        int idx = GA(s) + a_row * 20 + a_q * 4;
        *(uint4*)&dsm[idx]        = make_uint4(h[0], h[1], h[2], h[3]);
        *(uint4*)&dsm[idx + 1280] = make_uint4(l[0], l[1], l[2], l[3]);
    };
    auto loadB = [&](int kt, int s) {
        int tile = blockIdx.y * KTILES + kt;
        const uint32_t* srcH = WBhi + ((size_t)tile << 11);
        const uint32_t* srcL = WBlo + ((size_t)tile << 11);
        uint32_t dH = sbase + GB(s) * 4;
        uint32_t dL = dH + 2560 * 4;
#pragma unroll
        for (int r = 0; r < 2; r++) {
            int c = tid + r * 256;                 // 16B chunk index, < 512
            uint32_t off = (uint32_t)((c >> 2) * 20 + (c & 3) * 4) * 4;
            cp16(dH + off, srcH + c * 4);
            cp16(dL + off, srcL + c * 4);
        }
        cp_commit();
    };

    {
        float4 av[2];
        loadB(0, 0);
        loadA(0, av);
        storeA(0, av);
        cp_wait0();
        __syncthreads();
    }

    // ldmatrix per-lane row offsets (u32 units, within a term buffer)
    uint32_t aoff = (uint32_t)((wm * 32 + (lane & 7) + ((lane & 8) ? 8 : 0)) * 20
                               + ((lane & 16) ? 4 : 0));
    uint32_t boff = (uint32_t)((wn * 32 + (lane & 7) + ((lane & 16) ? 8 : 0)) * 20
                               + ((lane & 8) ? 4 : 0));

    for (int kt = 0; kt < KT; kt++) {
        int s = kt & 1;
        float4 nav[2];
        if (kt + 1 < KT) { loadB(kt + 1, s ^ 1); loadA(kt + 1, nav); }

#pragma unroll
        for (int ks = 0; ks < 2; ks++) {
            uint32_t ka = ks * 8;
            uint32_t aB = sbase + (GA(s) + ka) * 4;
            uint32_t bB = sbase + (GB(s) + ka) * 4;
            uint32_t ahi[2][4], alo[2][4];
#pragma unroll
            for (int mt = 0; mt < 2; mt++) {
                uint32_t ad = aB + (aoff + mt * 320) * 4;
                ldsm4(ahi[mt][0], ahi[mt][1], ahi[mt][2], ahi[mt][3], ad);
                ldsm4(alo[mt][0], alo[mt][1], alo[mt][2], alo[mt][3], ad + 1280 * 4);
            }
            uint32_t bhi[4][2], blo[4][2];
#pragma unroll
            for (int p = 0; p < 2; p++) {
                uint32_t bd = bB + (boff + p * 320) * 4;
                uint32_t r0, r1, r2, r3;
                ldsm4(r0, r1, r2, r3, bd);
                bhi[p * 2][0] = r0;     bhi[p * 2][1] = r1;
                bhi[p * 2 + 1][0] = r2; bhi[p * 2 + 1][1] = r3;
                ldsm4(r0, r1, r2, r3, bd + 2560 * 4);
                blo[p * 2][0] = r0;     blo[p * 2][1] = r1;
                blo[p * 2 + 1][0] = r2; blo[p * 2 + 1][1] = r3;
            }
#pragma unroll
            for (int mt = 0; mt < 2; mt++)
#pragma unroll
                for (int nt = 0; nt < 4; nt++) {
                    MMA_BF16(acc[mt][nt], ahi[mt], bhi[nt]);
                    MMA_BF16(acc[mt][nt], alo[mt], bhi[nt]);
                    MMA_BF16(acc[mt][nt], ahi[mt], blo[nt]);
                }
        }
        if (kt + 1 < KT) {
            cp_wait0();
            __syncthreads();
            storeA(s ^ 1, nav);
            __syncthreads();
        }
    }

    // epilogue: bias, store, BN stats
#pragma unroll
    for (int nt = 0; nt < 4; nt++) {
        int cb = wn * 32 + nt * 8 + 2 * (lane & 3);
        float b0 = bias[nb0 + cb], b1 = bias[nb0 + cb + 1];
        float s0 = 0.f, s1 = 0.f, q0 = 0.f, q1 = 0.f;
#pragma unroll
        for (int mt = 0; mt < 2; mt++) {
            int row0 = n0 + wm * 32 + mt * 16 + (lane >> 2);
            float v0 = acc[mt][nt][0] + b0, v1 = acc[mt][nt][1] + b1;
            float v2 = acc[mt][nt][2] + b0, v3 = acc[mt][nt][3] + b1;
            if (row0 < N) {
                *(float2*)(out + (size_t)row0 * NCOLS + nb0 + cb) = make_float2(v0, v1);
                s0 += v0; s1 += v1; q0 += v0 * v0; q1 += v1 * v1;
            }
            if (row0 + 8 < N) {
                *(float2*)(out + (size_t)(row0 + 8) * NCOLS + nb0 + cb) = make_float2(v2, v3);
                s0 += v2; s1 += v3; q0 += v2 * v2; q1 += v3 * v3;
            }
        }
#pragma unroll
        for (int off = 4; off < 32; off <<= 1) {
            s0 += __shfl_xor_sync(0xffffffffu, s0, off);
            s1 += __shfl_xor_sync(0xffffffffu, s1, off);
            q0 += __shfl_xor_sync(0xffffffffu, q0, off);
            q1 += __shfl_xor_sync(0xffffffffu, q1, off);
        }
        if (lane < 4) {
            atomicAdd(&ssum[cb], s0); atomicAdd(&ssum[cb + 1], s1);
            atomicAdd(&ssq[cb],  q0); atomicAdd(&ssq[cb + 1],  q1);
        }
    }
    __syncthreads();
    for (int i = tid; i < BN; i += 256) {
        atomicAdd(&g_colsum[LOUT][nb0 + i], ssum[i]);
        atomicAdd(&g_colsq[LOUT][nb0 + i],  ssq[i]);
    }
}

// ---------------------------------------------------------------------------
// h = relu(bn(in)) with inline affine from layer-1 stats (256 cols)
// ---------------------------------------------------------------------------
__global__ void bnrelu_kernel(const float4* __restrict__ in,
                              float4* __restrict__ outp, int n4,
                              const float* __restrict__ g,
                              const float* __restrict__ bt, float invN)
{
    __shared__ float sA[256], sB[256];
    int tid = threadIdx.x;
    {
        float mu = g_colsum[1][tid] * invN;
        float var = fmaxf(g_colsq[1][tid] * invN - mu * mu, 0.f);
        float A = g[tid] * rsqrtf(var + 1e-5f);
        sA[tid] = A;
        sB[tid] = bt[tid] - A * mu;
    }
    __syncthreads();
    int i = blockIdx.x * 256 + tid;
    if (i >= n4) return;
    int c0 = (i & 63) * 4;
    float4 v = in[i];
    v.x = fmaxf(sA[c0]     * v.x + sB[c0],     0.f);
    v.y = fmaxf(sA[c0 + 1] * v.y + sB[c0 + 1], 0.f);
    v.z = fmaxf(sA[c0 + 2] * v.z + sB[c0 + 2], 0.f);
    v.w = fmaxf(sA[c0 + 3] * v.w + sB[c0 + 3], 0.f);
    outp[i] = v;
}

// ---------------------------------------------------------------------------
// Output head: out[n] = sum_j relu(bn3(t[n,j])) * Wout[j] + bout
// ---------------------------------------------------------------------------
__global__ void __launch_bounds__(256) out_kernel(
    const float* __restrict__ T, const float* __restrict__ Wout,
    const float* __restrict__ bout, float* __restrict__ out, int N,
    const float* __restrict__ g, const float* __restrict__ bt, float invN)
{
    __shared__ float sA[128], sB[128];
    int tid = threadIdx.x;
    if (tid < 128) {
        float mu = g_colsum[3][tid] * invN;
        float var = fmaxf(g_colsq[3][tid] * invN - mu * mu, 0.f);
        float A = g[tid] * rsqrtf(var + 1e-5f);
        sA[tid] = A;
        sB[tid] = bt[tid] - A * mu;
    }
    __syncthreads();
    int wid = tid >> 5, lane = tid & 31;
    int n = blockIdx.x * 8 + wid;
    if (n >= N) return;
    float4 t = ((const float4*)(T + (size_t)n * 128))[lane];
    float4 w = ((const float4*)Wout)[lane];
    int c = lane * 4;
    float s = fmaxf(sA[c]     * t.x + sB[c],     0.f) * w.x
            + fmaxf(sA[c + 1] * t.y + sB[c + 1], 0.f) * w.y
            + fmaxf(sA[c + 2] * t.z + sB[c + 2], 0.f) * w.z
            + fmaxf(sA[c + 3] * t.w + sB[c + 3], 0.f) * w.w;
#pragma unroll
    for (int o = 16; o > 0; o >>= 1)
        s += __shfl_xor_sync(0xffffffffu, s, o);
    if (lane == 0) out[n] = s + bout[0];
}

// ---------------------------------------------------------------------------
extern "C" void kernel_launch(void* const* d_in, const int* in_sizes, int n_in,
                              void* d_out, int out_size)
{
    const float* x    = (const float*)d_in[0];
    const void*  ei   = d_in[1];
    const float* ea   = (const float*)d_in[2];
    const float* eps1 = (const float*)d_in[3];
    const float* We1  = (const float*)d_in[4];
    const float* be1  = (const float*)d_in[5];
    const float* W11  = (const float*)d_in[6];
    const float* b11  = (const float*)d_in[7];
    const float* g11  = (const float*)d_in[8];
    const float* bt11 = (const float*)d_in[9];
    const float* W12  = (const float*)d_in[10];
    const float* b12  = (const float*)d_in[11];
    const float* g1   = (const float*)d_in[12];
    const float* bt1  = (const float*)d_in[13];
    const float* eps2 = (const float*)d_in[14];
    const float* We2  = (const float*)d_in[15];
    const float* be2  = (const float*)d_in[16];
    const float* W21  = (const float*)d_in[17];
    const float* b21  = (const float*)d_in[18];
    const float* g21  = (const float*)d_in[19];
    const float* bt21 = (const float*)d_in[20];
    const float* W22  = (const float*)d_in[21];
    const float* b22  = (const float*)d_in[22];
    const float* g2   = (const float*)d_in[23];
    const float* bt2  = (const float*)d_in[24];
    const float* Wout = (const float*)d_in[25];
    const float* bout = (const float*)d_in[26];

    int N = in_sizes[0] / 64;   // 25000
    int E = in_sizes[2] / 8;    // 400000
    float invN = 1.0f / (float)N;

    float *agg1, *agg2, *bufA, *bufB;
    uint32_t *bhi, *blo;
    cudaGetSymbolAddress((void**)&agg1, g_agg1);
    cudaGetSymbolAddress((void**)&agg2, g_agg2);
    cudaGetSymbolAddress((void**)&bufA, g_bufA);
    cudaGetSymbolAddress((void**)&bufB, g_bufB);
    cudaGetSymbolAddress((void**)&bhi, g_Bhi);
    cudaGetSymbolAddress((void**)&blo, g_Blo);

    static int attr_done = 0;
    if (!attr_done) {
        cudaFuncSetAttribute(gemm_mma<64, 256, 1, 0, 0>,
                             cudaFuncAttributeMaxDynamicSharedMemorySize, GEMM_SMEM_BYTES);
        cudaFuncSetAttribute(gemm_mma<256, 256, 2, 0, 1>,
                             cudaFuncAttributeMaxDynamicSharedMemorySize, GEMM_SMEM_BYTES);
        cudaFuncSetAttribute(gemm_mma<256, 128, 1, 0, 2>,
                             cudaFuncAttributeMaxDynamicSharedMemorySize, GEMM_SMEM_BYTES);
        cudaFuncSetAttribute(gemm_mma<128, 128, 2, 2, 3>,
                             cudaFuncAttributeMaxDynamicSharedMemorySize, GEMM_SMEM_BYTES);
        attr_done = 1;
    }

    int NB = (N + 1023) / 1024;
    int EB = (E + 1023) / 1024;
    int gx = (N + 63) / 64;

    // --- setup + CSR build ---
    setup_kernel<<<(N + 255) / 256, 256>>>((const int*)ei, N);
    hist_kernel<<<EB, 256>>>(ei, E);
    wsplit_kernel<<<256, 256>>>(W11, W12, W21, W22);
    blocksum_kernel<<<NB, 1024>>>(N);
    scan2_kernel<<<NB, 1024>>>(N);
    scatter_kernel<<<EB, 256>>>(ei, E);

    // --- conv1 ---
    agg1_kernel<<<(N + 7) / 8, 256>>>(ea, We1, be1, x, agg1, N);
    gemm_mma<64, 256, 1, 0, 0><<<dim3(gx, 2), 256, GEMM_SMEM_BYTES>>>(
        x, bhi, blo, b11, bufA, agg1, eps1, nullptr, nullptr, N, invN);
    gemm_mma<256, 256, 2, 0, 1><<<dim3(gx, 2), 256, GEMM_SMEM_BYTES>>>(
        bufA, bhi + 8192, blo + 8192, b12, bufB, nullptr, nullptr, g11, bt11, N, invN);
    bnrelu_kernel<<<(N * 64 + 255) / 256, 256>>>(
        (const float4*)bufB, (float4*)bufA, N * 64, g1, bt1, invN);

    // --- conv2 ---
    agg2_kernel<<<(N + 3) / 4, 256>>>(ea, We2, be2, bufA, agg2, N);
    gemm_mma<256, 128, 1, 0, 2><<<dim3(gx, 1), 256, GEMM_SMEM_BYTES>>>(
        bufA, bhi + 40960, blo + 40960, b21, bufB, agg2, eps2, nullptr, nullptr, N, invN);
    gemm_mma<128, 128, 2, 2, 3><<<dim3(gx, 1), 256, GEMM_SMEM_BYTES>>>(
        bufB, bhi + 57344, blo + 57344, b22, bufA, nullptr, nullptr, g21, bt21, N, invN);

    // --- head ---
    out_kernel<<<(N + 7) / 8, 256>>>(bufA, Wout, bout, (float*)d_out, N, g2, bt2, invN);
}